// round 10
// baseline (speedup 1.0000x reference)
#include <cuda_runtime.h>
#include <cuda_fp16.h>
#include <math.h>
#include <stdint.h>

// ---------------- problem constants ----------------
#define BB 32
#define TT 512
#define DD 512
#define LL 6
#define HH 8
#define HD 64
#define FF 2048      // 4*D
#define EH 4
#define EHD 128
#define MM 100000u
#define OVL 64
#define NTOK (BB*TT)   // 16384

// ---------------- scratch ----------------
__device__ float g_x[NTOK*DD];
__device__ float g_qkv[(size_t)NTOK*3*DD];
__device__ float g_ffg[(size_t)NTOK*FF];
__device__ float g_ctx[BB*DD];
__device__ float g_logits[NTOK*EH];
__device__ float g_wv[BB*DD];
__device__ float g_u[BB*EH];
// fp16 activations (single plane)
__device__ __half g_nx[NTOK*DD];
__device__ __half g_at[NTOK*DD];
__device__ __half g_ff[(size_t)NTOK*FF];
// transposed fp16 weights: [N][K]
__device__ __half g_wqkvo[(size_t)LL*4*DD*DD];
__device__ __half g_w1[(size_t)LL*2*FF*DD];
__device__ __half g_w2[(size_t)LL*DD*FF];

// ---------------- PTX helpers ----------------
__device__ __forceinline__ uint32_t smem_to_u32(const void* p) {
    uint32_t a;
    asm("{ .reg .u64 t; cvta.to.shared.u64 t, %1; cvt.u32.u64 %0, t; }" : "=r"(a) : "l"(p));
    return a;
}
__device__ __forceinline__ void cp16(uint32_t dst, const void* src) {
    asm volatile("cp.async.cg.shared.global [%0], [%1], 16;" :: "r"(dst), "l"(src));
}
#define CP_COMMIT() asm volatile("cp.async.commit_group;" ::: "memory")
#define CP_WAIT4()  asm volatile("cp.async.wait_group 4;" ::: "memory")

#define LDSM4(r, addr) \
    asm volatile("ldmatrix.sync.aligned.m8n8.x4.shared.b16 {%0,%1,%2,%3}, [%4];" \
        : "=r"((r)[0]), "=r"((r)[1]), "=r"((r)[2]), "=r"((r)[3]) : "r"(addr))

#define HMMA(c, a, b0, b1) \
    asm volatile("mma.sync.aligned.m16n8k16.row.col.f32.f16.f16.f32 " \
        "{%0,%1,%2,%3}, {%4,%5,%6,%7}, {%8,%9}, {%0,%1,%2,%3};" \
        : "+f"((c)[0]), "+f"((c)[1]), "+f"((c)[2]), "+f"((c)[3]) \
        : "r"((a)[0]), "r"((a)[1]), "r"((a)[2]), "r"((a)[3]), "r"(b0), "r"(b1))

__device__ __forceinline__ uint32_t f22u(float a, float b) {
    __half2 h = __floats2half2_rn(a, b);
    return *(uint32_t*)&h;
}

// ---------------- reduction helpers ----------------
__device__ __forceinline__ float warpReduceSum(float v) {
    #pragma unroll
    for (int o = 16; o; o >>= 1) v += __shfl_xor_sync(0xffffffffu, v, o);
    return v;
}
__device__ __forceinline__ float warpReduceMax(float v) {
    #pragma unroll
    for (int o = 16; o; o >>= 1) v = fmaxf(v, __shfl_xor_sync(0xffffffffu, v, o));
    return v;
}
__device__ __forceinline__ float blockReduceSum128(float v) {
    __shared__ float sm[4];
    __syncthreads();
    v = warpReduceSum(v);
    if ((threadIdx.x & 31) == 0) sm[threadIdx.x >> 5] = v;
    __syncthreads();
    return sm[0] + sm[1] + sm[2] + sm[3];
}
__device__ __forceinline__ float blockReduceMax128(float v) {
    __shared__ float sm[4];
    __syncthreads();
    v = warpReduceMax(v);
    if ((threadIdx.x & 31) == 0) sm[threadIdx.x >> 5] = v;
    __syncthreads();
    return fmaxf(fmaxf(sm[0], sm[1]), fmaxf(sm[2], sm[3]));
}

// ---------------- 4-source transpose to fp16 (Wq/Wk/Wv/Wo stacked) ----------------
__global__ void tsplit4_kernel(const float* __restrict__ s0, const float* __restrict__ s1,
                               const float* __restrict__ s2, const float* __restrict__ s3,
                               __half* __restrict__ dst) {
    __shared__ float t[32][33];
    int z = blockIdx.z;
    int l = z >> 2, sel = z & 3;
    const float* S = (sel == 0 ? s0 : sel == 1 ? s1 : sel == 2 ? s2 : s3) + (size_t)l*DD*DD;
    __half* Hd = dst + (size_t)z*DD*DD;
    int n0 = blockIdx.x*32, k0 = blockIdx.y*32;
    int x = threadIdx.x, y = threadIdx.y;
    #pragma unroll
    for (int i = 0; i < 32; i += 8) t[y+i][x] = S[(size_t)(k0+y+i)*DD + n0+x];
    __syncthreads();
    #pragma unroll
    for (int i = 0; i < 32; i += 8)
        Hd[(size_t)(n0+y+i)*DD + k0+x] = __float2half_rn(t[x][y+i]);
}

// ---------------- generic transpose to fp16 ----------------
__global__ void tsplit_kernel(const float* __restrict__ src, int ldsrc, size_t srcStride,
                              __half* __restrict__ dst, size_t dstStride, int K) {
    __shared__ float t[32][33];
    int l = blockIdx.z;
    const float* S = src + (size_t)l*srcStride;
    __half* Hd = dst + (size_t)l*dstStride;
    int n0 = blockIdx.x*32, k0 = blockIdx.y*32;
    int x = threadIdx.x, y = threadIdx.y;
    #pragma unroll
    for (int i = 0; i < 32; i += 8) t[y+i][x] = S[(size_t)(k0+y+i)*ldsrc + n0+x];
    __syncthreads();
    #pragma unroll
    for (int i = 0; i < 32; i += 8)
        Hd[(size_t)(n0+y+i)*K + k0+x] = __float2half_rn(t[x][y+i]);
}

// ---------------- W1 transpose to fp16 ----------------
__global__ void tsplitW1_kernel(const float* __restrict__ W1, __half* __restrict__ dst) {
    __shared__ float t[32][33];
    int z = blockIdx.z;
    int l = z >> 1, half = z & 1;
    const float* S = W1 + (size_t)l*DD*2*FF + (size_t)half*FF;
    __half* Hd = dst + (size_t)l*2*FF*DD + (size_t)half*FF*DD;
    int n0 = blockIdx.x*32, k0 = blockIdx.y*32;
    int x = threadIdx.x, y = threadIdx.y;
    #pragma unroll
    for (int i = 0; i < 32; i += 8) t[y+i][x] = S[(size_t)(k0+y+i)*(2*FF) + n0+x];
    __syncthreads();
    #pragma unroll
    for (int i = 0; i < 32; i += 8)
        Hd[(size_t)(n0+y+i)*DD + k0+x] = __float2half_rn(t[x][y+i]);
}

// ---------------- fp16 HMMA GEMM (single pass, 6-stage cp.async, 1 CTA/SM deep pipeline) ----------------
#define TILE_B 10240
#define STAGE_B 20480
#define NSTAGE 6
#define HSMEM (NSTAGE*STAGE_B)   // 122880

__device__ __forceinline__ void load_stage(uint32_t sb,
        const __half* A, const __half* B, int K, int kof, int tid) {
    #pragma unroll
    for (int i = 0; i < 2; i++) {
        int e = tid + i*256;
        int row = e >> 2, seg = e & 3;
        uint32_t off = (uint32_t)(row*80 + seg*16);
        size_t g = (size_t)row*K + kof + seg*8;
        cp16(sb + off,          A + g);
        cp16(sb + TILE_B + off, B + g);
    }
}

template<int MODE>
__global__ void __launch_bounds__(256)
hgemm(const __half* __restrict__ A, const __half* __restrict__ B,
      const float* __restrict__ bias, const float* __restrict__ bias2,
      const float* __restrict__ bias3,
      const float* __restrict__ Res, const float* __restrict__ Gg,
      float* __restrict__ C, __half* __restrict__ Out,
      int M, int N, int K) {
    extern __shared__ char dsm[];
    uint32_t sb = smem_to_u32(dsm);
    int tid = threadIdx.x, lane = tid & 31, wid = tid >> 5;
    int m0 = blockIdx.x * 128, n0 = blockIdx.y * 128;
    int wm = (wid & 1) * 64, wn = (wid >> 1) * 32;
    const __half* Ab = A + (size_t)m0*K;
    const __half* Bb = B + (size_t)n0*K;
    int NC = K >> 5;

    #pragma unroll
    for (int j = 0; j < 5; j++) {
        load_stage(sb + (uint32_t)j*STAGE_B, Ab, Bb, K, j*32, tid);
        CP_COMMIT();
    }

    float acc[4][4][4];
    #pragma unroll
    for (int a = 0; a < 4; a++)
        #pragma unroll
        for (int b = 0; b < 4; b++)
            #pragma unroll
            for (int c = 0; c < 4; c++) acc[a][b][c] = 0.f;

    const int a_row = lane & 15;
    const int a_k   = (lane >> 4) * 8;
    const int b_row = (lane & 7) + ((lane >> 4) << 3);
    const int b_k   = ((lane >> 3) & 1) * 8;

    uint32_t slot = 0, wslot = 5;
    for (int i = 0; i < NC; i++) {
        CP_WAIT4();
        __syncthreads();
        if (i + 5 < NC)
            load_stage(sb + wslot*STAGE_B, Ab, Bb, K, (i+5)*32, tid);
        CP_COMMIT();
        if (++wslot == NSTAGE) wslot = 0;
        uint32_t st = sb + slot*STAGE_B;
        if (++slot == NSTAGE) slot = 0;
        // full-chunk fragment prefetch: 12 LDSM4, then 32 independent HMMAs
        uint32_t a0[4][4], a1[4][4], b0[2][4], b1[2][4];
        #pragma unroll
        for (int mt = 0; mt < 4; mt++) {
            uint32_t ad = st + (uint32_t)((wm + mt*16 + a_row)*80 + a_k*2);
            LDSM4(a0[mt], ad);
            LDSM4(a1[mt], ad + 32);
        }
        #pragma unroll
        for (int np = 0; np < 2; np++) {
            uint32_t bd = st + TILE_B + (uint32_t)((wn + np*16 + b_row)*80 + b_k*2);
            LDSM4(b0[np], bd);
            LDSM4(b1[np], bd + 32);
        }
        #pragma unroll
        for (int mt = 0; mt < 4; mt++)
            #pragma unroll
            for (int nt = 0; nt < 4; nt++)
                HMMA(acc[mt][nt], a0[mt], b0[nt>>1][(nt&1)*2], b0[nt>>1][(nt&1)*2+1]);
        #pragma unroll
        for (int mt = 0; mt < 4; mt++)
            #pragma unroll
            for (int nt = 0; nt < 4; nt++)
                HMMA(acc[mt][nt], a1[mt], b1[nt>>1][(nt&1)*2], b1[nt>>1][(nt&1)*2+1]);
    }

    int gid = lane >> 2, ctg = lane & 3;
    #pragma unroll
    for (int mt = 0; mt < 4; mt++)
        #pragma unroll
        for (int nt = 0; nt < 4; nt++) {
            int r0 = m0 + wm + mt*16 + gid;
            int cc = n0 + wn + nt*8 + ctg*2;
            float2 v0 = make_float2(acc[mt][nt][0], acc[mt][nt][1]);
            float2 v1 = make_float2(acc[mt][nt][2], acc[mt][nt][3]);
            if (MODE == 0) {
                const float* bp = (cc < 512) ? (bias + cc)
                                : (cc < 1024) ? (bias2 + cc - 512) : (bias3 + cc - 1024);
                float2 bb = *(const float2*)bp;
                v0.x += bb.x; v0.y += bb.y; v1.x += bb.x; v1.y += bb.y;
            }
            if (MODE == 1) {
                float2 bb = *(const float2*)(bias + cc);
                v0.x += bb.x; v0.y += bb.y; v1.x += bb.x; v1.y += bb.y;
            }
            if (MODE == 1 || MODE == 4) {
                float2 ra = *(const float2*)(Res + (size_t)r0*N + cc);
                float2 rb = *(const float2*)(Res + (size_t)(r0+8)*N + cc);
                v0.x += ra.x; v0.y += ra.y; v1.x += rb.x; v1.y += rb.y;
            }
            if (MODE == 3) {
                float2 ga = *(const float2*)(Gg + (size_t)r0*N + cc);
                float2 gb = *(const float2*)(Gg + (size_t)(r0+8)*N + cc);
                float s0 = ga.x/(1.f+__expf(-ga.x))*v0.x;
                float s1 = ga.y/(1.f+__expf(-ga.y))*v0.y;
                float s2 = gb.x/(1.f+__expf(-gb.x))*v1.x;
                float s3 = gb.y/(1.f+__expf(-gb.y))*v1.y;
                *(__half2*)(Out + (size_t)r0*N + cc)     = __floats2half2_rn(s0, s1);
                *(__half2*)(Out + (size_t)(r0+8)*N + cc) = __floats2half2_rn(s2, s3);
            } else {
                *(float2*)(C + (size_t)r0*N + cc) = v0;
                *(float2*)(C + (size_t)(r0+8)*N + cc) = v1;
            }
        }
}

// ---------------- context projection ----------------
__global__ void ctx_kernel(const float* __restrict__ fast, const float* __restrict__ slow,
                           const float* __restrict__ W, const float* __restrict__ bias,
                           float* __restrict__ out) {
    int b = blockIdx.x, d = threadIdx.x;
    float acc = bias[d];
    const float* fb = fast + b*DD;
    const float* sb = slow + b*DD;
    for (int k = 0; k < DD; k++) acc += fb[k] * W[(size_t)k*DD + d];
    for (int k = 0; k < DD; k++) acc += sb[k] * W[(size_t)(k+DD)*DD + d];
    out[b*DD + d] = acc;
}

// ---------------- embedding + context + engram + fused layer-0 rmsnorm ----------------
__global__ void embed_fused_kernel(const int* __restrict__ tokens, const int* __restrict__ prev,
                                   const float* __restrict__ embed, const float* __restrict__ ctxadd,
                                   const float* __restrict__ etab, const float* __restrict__ egate,
                                   const float* __restrict__ ln1,
                                   float* __restrict__ X, __half* __restrict__ H) {
    int row = blockIdx.x;
    int b = row >> 9, t = row & 511;
    __shared__ unsigned int sidx[EH];
    int tid = threadIdx.x;
    if (tid < EH) {
        unsigned int xseed = 131u + (unsigned)tid * 1009u;
        unsigned int hs = 0u;
        #pragma unroll
        for (int i = 0; i < 4; i++) {
            unsigned int p = xseed; xseed = xseed * 31u + 1u;
            int pos = t - i;
            unsigned int tok = (pos >= 0) ? (unsigned)tokens[b*TT + pos]
                                          : (unsigned)prev[b*OVL + OVL + pos];
            hs += tok * p;
        }
        sidx[tid] = hs % MM;
    }
    __syncthreads();
    int d0 = tid * 4;
    int eh = tid >> 5;
    int jj = d0 & 127;
    int tok = tokens[b*TT + t];
    float4 ev = *(const float4*)(embed + (size_t)tok*DD + d0);
    float4 cv = *(const float4*)(ctxadd + b*DD + d0);
    float4 rv = *(const float4*)(etab + ((size_t)sidx[eh]*EH + eh)*EHD + jj);
    float4 gv = *(const float4*)(egate + eh*EHD + jj);
    float4 o;
    o.x = ev.x + cv.x + rv.x * (1.f/(1.f+__expf(-gv.x)));
    o.y = ev.y + cv.y + rv.y * (1.f/(1.f+__expf(-gv.y)));
    o.z = ev.z + cv.z + rv.z * (1.f/(1.f+__expf(-gv.z)));
    o.w = ev.w + cv.w + rv.w * (1.f/(1.f+__expf(-gv.w)));
    *(float4*)(X + (size_t)row*DD + d0) = o;
    float ss = blockReduceSum128(o.x*o.x + o.y*o.y + o.z*o.z + o.w*o.w);
    float inv = rsqrtf(ss * (1.f/DD) + 1e-6f);
    float4 sc = ((const float4*)ln1)[tid];
    size_t off = (size_t)row*DD + d0;
    *(__half2*)(H + off)     = __floats2half2_rn(o.x*inv*sc.x, o.y*inv*sc.y);
    *(__half2*)(H + off + 2) = __floats2half2_rn(o.z*inv*sc.z, o.w*inv*sc.w);
}

// ---------------- RMSNorm -> fp16 plane ----------------
__global__ void rmsnorm_half_kernel(const float* __restrict__ X, const float* __restrict__ scale,
                                    __half* __restrict__ H) {
    int row = blockIdx.x;
    float4 v = ((const float4*)(X + (size_t)row*DD))[threadIdx.x];
    float ss = v.x*v.x + v.y*v.y + v.z*v.z + v.w*v.w;
    ss = blockReduceSum128(ss);
    float inv = rsqrtf(ss * (1.f/DD) + 1e-6f);
    float4 sc = ((const float4*)scale)[threadIdx.x];
    size_t off = (size_t)row*DD + threadIdx.x*4;
    *(__half2*)(H + off)     = __floats2half2_rn(v.x*inv*sc.x, v.y*inv*sc.y);
    *(__half2*)(H + off + 2) = __floats2half2_rn(v.z*inv*sc.z, v.w*inv*sc.w);
}

// ---------------- final RMSNorm (fp32 out) ----------------
__global__ void rmsnorm_kernel(const float* __restrict__ X, const float* __restrict__ scale,
                               float* __restrict__ Out) {
    int row = blockIdx.x;
    float4 v = ((const float4*)(X + (size_t)row*DD))[threadIdx.x];
    float ss = v.x*v.x + v.y*v.y + v.z*v.z + v.w*v.w;
    ss = blockReduceSum128(ss);
    float inv = rsqrtf(ss * (1.f/DD) + 1e-6f);
    float4 sc = ((const float4*)scale)[threadIdx.x];
    float4 o;
    o.x = v.x*inv*sc.x; o.y = v.y*inv*sc.y; o.z = v.z*inv*sc.z; o.w = v.w*inv*sc.w;
    ((float4*)(Out + (size_t)row*DD))[threadIdx.x] = o;
}

// ---------------- rope helper ----------------
__device__ __forceinline__ float4 rope4(float4 v, int t, int dv) {
    const float c = 9.210340371976184f / 64.f;
    float inv0 = __expf(-(float)dv * c);
    float inv1 = __expf(-(float)(dv+2) * c);
    float s0, c0, s1, c1;
    __sincosf((float)t * inv0, &s0, &c0);
    __sincosf((float)t * inv1, &s1, &c1);
    float4 r;
    r.x = v.x*c0 - v.y*s0;  r.y = v.x*s0 + v.y*c0;
    r.z = v.z*c1 - v.w*s1;  r.w = v.z*s1 + v.w*c1;
    return r;
}

// ---------------- HMMA causal flash attention: BQ=64, BK=64, HD=64, 256 threads ----------------
#define FPAD 72
#define FSMEM (3*64*FPAD*2 + 2*128*4 + 64*64*4)   // 45056

__global__ void __launch_bounds__(256) flash_kernel(const float* __restrict__ QKV,
        __half* __restrict__ Oh) {
    extern __shared__ char fsm[];
    __half* Qh = (__half*)fsm;
    __half* Kh = Qh + 64*FPAD;
    __half* Vt = Kh + 64*FPAD;
    float* smax = (float*)(Vt + 64*FPAD);
    float* ssum = smax + 128;
    float* obuf = ssum + 128;
    uint32_t uq = smem_to_u32(Qh);
    uint32_t uk = smem_to_u32(Kh);
    uint32_t uv = smem_to_u32(Vt);

    int bh = blockIdx.y;
    int b = bh >> 3, h = bh & 7;
    int q0 = blockIdx.x * 64;
    int tid = threadIdx.x, lane = tid & 31, wid = tid >> 5;
    int wm = wid & 3, wk2 = wid >> 2;
    int gid = lane >> 2, ctg = lane & 3;
    const int a_row = lane & 15;
    const int a_k   = (lane >> 4) * 8;
    const int b_row = (lane & 7) + ((lane >> 4) << 3);
    const int b_k   = ((lane >> 3) & 1) * 8;
    size_t base = ((size_t)b*TT)*1536 + h*HD;
    const float scl = 0.125f;

    for (int i = tid; i < 64*16; i += 256) {
        int r = i >> 4, dv = (i & 15) * 4;
        float4 v = rope4(*(const float4*)(QKV + base + (size_t)(q0 + r)*1536 + dv), q0 + r, dv);
        __half2* dst = (__half2*)(Qh + r*FPAD + dv);
        dst[0] = __floats2half2_rn(v.x, v.y);
        dst[1] = __floats2half2_rn(v.z, v.w);
    }

    float m0 = -1e30f, m1 = -1e30f, l0 = 0.f, l1 = 0.f;
    float oacc[8][4];
    #pragma unroll
    for (int i = 0; i < 8; i++)
        #pragma unroll
        for (int j = 0; j < 4; j++) oacc[i][j] = 0.f;

    int row0 = q0 + wm*16 + gid;
    int nkt = (q0 >> 6) + 1;
    for (int kt = 0; kt < nkt; kt++) {
        int k0 = kt * 64;
        __syncthreads();
        for (int i = tid; i < 64*16; i += 256) {
            int r = i >> 4, dv = (i & 15)*4;
            size_t g = base + (size_t)(k0 + r)*1536 + dv;
            float4 kv = rope4(*(const float4*)(QKV + g + 512), k0 + r, dv);
            __half2* kd = (__half2*)(Kh + r*FPAD + dv);
            kd[0] = __floats2half2_rn(kv.x, kv.y);
            kd[1] = __floats2half2_rn(kv.z, kv.w);
            float4 vv = *(const float4*)(QKV + g + 1024);
            Vt[(dv+0)*FPAD + r] = __float2half_rn(vv.x);
            Vt[(dv+1)*FPAD + r] = __float2half_rn(vv.y);
            Vt[(dv+2)*FPAD + r] = __float2half_rn(vv.z);
            Vt[(dv+3)*FPAD + r] = __float2half_rn(vv.w);
        }
        __syncthreads();
        float sacc[4][4];
        #pragma unroll
        for (int nt = 0; nt < 4; nt++)
            #pragma unroll
            for (int j = 0; j < 4; j++) sacc[nt][j] = 0.f;
        #pragma unroll
        for (int kk = 0; kk < 64; kk += 16) {
            uint32_t af[4], bf[2][4];
            LDSM4(af, uq + (uint32_t)((wm*16 + a_row)*FPAD + kk + a_k)*2);
            #pragma unroll
            for (int np = 0; np < 2; np++)
                LDSM4(bf[np], uk + (uint32_t)((wk2*32 + np*16 + b_row)*FPAD + kk + b_k)*2);
            #pragma unroll
            for (int nt = 0; nt < 4; nt++)
                HMMA(sacc[nt], af, bf[nt>>1][(nt&1)*2], bf[nt>>1][(nt&1)*2+1]);
        }
        bool diag = (kt == nkt - 1);
        #pragma unroll
        for (int nt = 0; nt < 4; nt++) {
            int col = k0 + wk2*32 + nt*8 + ctg*2;
            #pragma unroll
            for (int j = 0; j < 4; j++) {
                int cc = col + (j & 1);
                int rr = row0 + ((j >> 1) << 3);
                sacc[nt][j] = (!diag || cc <= rr) ? sacc[nt][j]*scl : -1e9f;
            }
        }
        float rm0 = fmaxf(fmaxf(sacc[0][0], sacc[0][1]), fmaxf(sacc[1][0], sacc[1][1]));
        rm0 = fmaxf(rm0, fmaxf(fmaxf(sacc[2][0], sacc[2][1]), fmaxf(sacc[3][0], sacc[3][1])));
        float rm1 = fmaxf(fmaxf(sacc[0][2], sacc[0][3]), fmaxf(sacc[1][2], sacc[1][3]));
        rm1 = fmaxf(rm1, fmaxf(fmaxf(sacc[2][2], sacc[2][3]), fmaxf(sacc[3][2], sacc[3][3])));
        rm0 = fmaxf(rm0, __shfl_xor_sync(0xffffffffu, rm0, 1));
        rm0 = fmaxf(rm0, __shfl_xor_sync(0xffffffffu, rm0, 2));
        rm1 = fmaxf(rm1, __shfl_xor_sync(0xffffffffu, rm1, 1));
        rm1 = fmaxf(rm1, __shfl_xor_sync(0xffffffffu, rm1, 2));
        if (ctg == 0) {
            smax[wk2*64 + wm*16 + gid]     = rm0;
            smax[wk2*64 + wm*16 + gid + 8] = rm1;
        }
        __syncthreads();
        float mx0 = fmaxf(smax[wm*16 + gid],     smax[64 + wm*16 + gid]);
        float mx1 = fmaxf(smax[wm*16 + gid + 8], smax[64 + wm*16 + gid + 8]);
        float mn0 = fmaxf(m0, mx0), mn1 = fmaxf(m1, mx1);
        float c0 = __expf(m0 - mn0), c1 = __expf(m1 - mn1);
        m0 = mn0; m1 = mn1;
        float rs0 = 0.f, rs1 = 0.f;
        #pragma unroll
        for (int nt = 0; nt < 4; nt++) {
            sacc[nt][0] = __expf(sacc[nt][0] - mn0); rs0 += sacc[nt][0];
            sacc[nt][1] = __expf(sacc[nt][1] - mn0); rs0 += sacc[nt][1];
            sacc[nt][2] = __expf(sacc[nt][2] - mn1); rs1 += sacc[nt][2];
            sacc[nt][3] = __expf(sacc[nt][3] - mn1); rs1 += sacc[nt][3];
        }
        rs0 += __shfl_xor_sync(0xffffffffu, rs0, 1);
        rs0 += __shfl_xor_sync(0xffffffffu, rs0, 2);
        rs1 += __shfl_xor_sync(0xffffffffu, rs1, 1);
        rs1 += __shfl_xor_sync(0xffffffffu, rs1, 2);
        if (ctg == 0) {
            ssum[wk2*64 + wm*16 + gid]     = rs0;
            ssum[wk2*64 + wm*16 + gid + 8] = rs1;
        }
        #pragma unroll
        for (int nh = 0; nh < 8; nh++) {
            oacc[nh][0] *= c0; oacc[nh][1] *= c0;
            oacc[nh][2] *= c1; oacc[nh][3] *= c1;
        }
        __syncthreads();
        l0 = l0*c0 + ssum[wm*16 + gid]     + ssum[64 + wm*16 + gid];
        l1 = l1*c1 + ssum[wm*16 + gid + 8] + ssum[64 + wm*16 + gid + 8];
        #pragma unroll
        for (int g = 0; g < 2; g++) {
            uint32_t pf[4];
            pf[0] = f22u(sacc[2*g][0],   sacc[2*g][1]);
            pf[1] = f22u(sacc[2*g][2],   sacc[2*g][3]);
            pf[2] = f22u(sacc[2*g+1][0], sacc[2*g+1][1]);
            pf[3] = f22u(sacc[2*g+1][2], sacc[2*g+1][3]);
            int kof = wk2*32 + g*16;
            #pragma unroll
            for (int nh = 0; nh < 4; nh++) {
                uint32_t bf2[4];
                LDSM4(bf2, uv + (uint32_t)((nh*16 + b_row)*FPAD + kof + b_k)*2);
                HMMA(oacc[2*nh],   pf, bf2[0], bf2[1]);
                HMMA(oacc[2*nh+1], pf, bf2[2], bf2[3]);
            }
        }
    }
    __syncthreads();
    if (wk2 == 1) {
        #pragma unroll
        for (int nh = 0; nh < 8; nh++) {
            int c = nh*8 + ctg*2;
            float* o0 = obuf + (wm*16 + gid)*64 + c;
            float* o1 = obuf + (wm*16 + gid + 8)*64 + c;
            o0[0] = oacc[nh][0]; o0[1] = oacc[nh][1];
            o1[0] = oacc[nh][2]; o1[1] = oacc[nh][3];
        }
    }
    __syncthreads();
    if (wk2 == 0) {
        float inv0 = 1.f / l0, inv1 = 1.f / l1;
        #pragma unroll
        for (int nh = 0; nh < 8; nh++) {
            int c = nh*8 + ctg*2;
            const float* o0 = obuf + (wm*16 + gid)*64 + c;
            const float* o1 = obuf + (wm*16 + gid + 8)*64 + c;
            float x0 = (oacc[nh][0] + o0[0]) * inv0;
            float x1 = (oacc[nh][1] + o0[1]) * inv0;
            float y0 = (oacc[nh][2] + o1[0]) * inv1;
            float y1 = (oacc[nh][3] + o1[1]) * inv1;
            size_t r0 = (size_t)(b*TT + q0 + wm*16 + gid)*DD + h*HD + c;
            size_t r1 = (size_t)(b*TT + q0 + wm*16 + gid + 8)*DD + h*HD + c;
            *(__half2*)(Oh + r0) = __floats2half2_rn(x0, x1);
            *(__half2*)(Oh + r1) = __floats2half2_rn(y0, y1);
        }
    }
}

// ---------------- salience logits ----------------
__global__ void logits_kernel(const float* __restrict__ X, const float* __restrict__ sal_W,
                              const float* __restrict__ sal_b, const float* __restrict__ temp,
                              float* __restrict__ out) {
    int row = blockIdx.x;
    int e = threadIdx.x >> 5, lane = threadIdx.x & 31;
    const float* xr = X + (size_t)row*DD;
    float acc = 0.f;
    for (int d = lane; d < DD; d += 32)
        acc += xr[d] * sal_W[d*EH + e];
    acc = warpReduceSum(acc);
    if (lane == 0) {
        float tp = log1pf(expf(temp[e])) + 0.3f;
        out[(size_t)row*EH + e] = (acc + sal_b[e]) / tp;
    }
}

// ---------------- masked softmax pool ----------------
__global__ void pool_kernel(const int* __restrict__ tokens, const float* __restrict__ logits,
                            const float* __restrict__ X, const float* __restrict__ gate_W,
                            const float* __restrict__ gate_b,
                            float* __restrict__ wv_out, float* __restrict__ u_out) {
    int b = blockIdx.x >> 2, e = blockIdx.x & 3;
    int tid = threadIdx.x;
    __shared__ float ws[TT];
    float lg4[4]; int mv4[4];
    float lmax = -1e30f; float lvalid = 0.f;
    #pragma unroll
    for (int p = 0; p < 4; p++) {
        int t = tid + p*128;
        int mv = (tokens[b*TT + t] != 0);
        float lgv = logits[((size_t)b*TT + t)*EH + e];
        float sf = mv ? lgv : -1e9f;
        lg4[p] = sf; mv4[p] = mv;
        lmax = fmaxf(lmax, sf);
        lvalid += (float)mv;
    }
    float mx = blockReduceMax128(lmax);
    float lsum = 0.f;
    #pragma unroll
    for (int p = 0; p < 4; p++) {
        int t = tid + p*128;
        float ev = mv4[p] ? expf(lg4[p] - mx) : 0.f;
        ws[t] = ev;
        lsum += ev;
    }
    float ssum = blockReduceSum128(lsum);
    float nvalid = blockReduceSum128(lvalid);
    float wsc = 1.f / (ssum + 1e-6f);
    __syncthreads();
    float acc = 0.f;
    const float* xb = X + ((size_t)b*TT)*DD + e*EHD + tid;
    for (int t = 0; t < TT; t++)
        acc += ws[t] * xb[(size_t)t*DD];
    acc *= wsc;
    wv_out[b*DD + e*EHD + tid] = acc;
    float gsum = blockReduceSum128(acc * gate_W[tid]);
    if (tid == 0) {
        float gl = gsum + gate_b[0];
        float u = (nvalid > 0.f) ? 1.f/(1.f+expf(-gl)) : 0.f;
        u_out[b*EH + e] = u;
    }
}

// ---------------- fast/slow state update ----------------
__global__ void update_kernel(const float* __restrict__ wv, const float* __restrict__ u,
                              const float* __restrict__ sal_rms,
                              const float* __restrict__ fast, const float* __restrict__ slow,
                              float* __restrict__ out_fast, float* __restrict__ out_slow) {
    int b = blockIdx.x, tid = threadIdx.x;
    float4 v = ((const float4*)(wv + b*DD))[tid];
    float ss = blockReduceSum128(v.x*v.x + v.y*v.y + v.z*v.z + v.w*v.w);
    float inv = rsqrtf(ss * (1.f/DD) + 1e-6f);
    float4 sr = ((const float4*)sal_rms)[tid];
    int e = tid >> 5;
    float uu = u[b*EH + e];
    float4 f = ((const float4*)(fast + b*DD))[tid];
    float4 s = ((const float4*)(slow + b*DD))[tid];
    float4 wn;
    wn.x = v.x*inv*sr.x; wn.y = v.y*inv*sr.y; wn.z = v.z*inv*sr.z; wn.w = v.w*inv*sr.w;
    float4 nf, ns;
    nf.x = (1.f-uu)*f.x + uu*wn.x;  nf.y = (1.f-uu)*f.y + uu*wn.y;
    nf.z = (1.f-uu)*f.z + uu*wn.z;  nf.w = (1.f-uu)*f.w + uu*wn.w;
    float ud = 0.1f*uu;
    ns.x = (1.f-ud)*s.x + ud*wn.x;  ns.y = (1.f-ud)*s.y + ud*wn.y;
    ns.z = (1.f-ud)*s.z + ud*wn.z;  ns.w = (1.f-ud)*s.w + ud*wn.w;
    ((float4*)(out_fast + b*DD))[tid] = nf;
    ((float4*)(out_slow + b*DD))[tid] = ns;
}

// ---------------- launch ----------------
extern "C" void kernel_launch(void* const* d_in, const int* in_sizes, int n_in,
                              void* d_out, int out_size) {
    const int*   tokens = (const int*)  d_in[0];
    const int*   prev   = (const int*)  d_in[1];
    const float* fast   = (const float*)d_in[2];
    const float* slow   = (const float*)d_in[3];
    const float* embed  = (const float*)d_in[4];
    const float* ctx_W  = (const float*)d_in[5];
    const float* ctx_b  = (const float*)d_in[6];
    const float* etab   = (const float*)d_in[7];
    const float* egate  = (const float*)d_in[8];
    const float* ln1    = (const float*)d_in[9];
    const float* Wq     = (const float*)d_in[10];
    const float* bq     = (const float*)d_in[11];
    const float* Wk     = (const float*)d_in[12];
    const float* bk     = (const float*)d_in[13];
    const float* Wv     = (const float*)d_in[14];
    const float* bv     = (const float*)d_in[15];
    const float* Wo     = (const float*)d_in[16];
    const float* bo     = (const float*)d_in[17];
    const float* ln2    = (const float*)d_in[18];
    const float* W1     = (const float*)d_in[19];
    const float* W2     = (const float*)d_in[20];
    const float* ln_f   = (const float*)d_in[21];
    const float* sal_W  = (const float*)d_in[22];
    const float* sal_b  = (const float*)d_in[23];
    const float* temp   = (const float*)d_in[24];
    const float* gate_W = (const float*)d_in[25];
    const float* gate_b = (const float*)d_in[26];
    const float* sal_rms= (const float*)d_in[27];
    float* out = (float*)d_out;

    float *gx, *gqkv, *gffg, *gctx, *glog, *gwv, *gu;
    __half *nx, *at, *ff;
    __half *wA, *w1, *w2;
    cudaGetSymbolAddress((void**)&gx,   g_x);
    cudaGetSymbolAddress((void**)&gqkv, g_qkv);
    cudaGetSymbolAddress((void**)&gffg, g_ffg);
    cudaGetSymbolAddress((void**)&gctx, g_ctx);
    cudaGetSymbolAddress((void**)&glog, g_logits);
    cudaGetSymbolAddress((void**)&gwv,  g_wv);
    cudaGetSymbolAddress((void**)&gu,   g_u);
    cudaGetSymbolAddress((void**)&nx,   g_nx);
    cudaGetSymbolAddress((void**)&at,   g_at);
    cudaGetSymbolAddress((void**)&ff,   g_ff);
    cudaGetSymbolAddress((void**)&wA,   g_wqkvo);
    cudaGetSymbolAddress((void**)&w1,   g_w1);
    cudaGetSymbolAddress((void**)&w2,   g_w2);

    cudaFuncSetAttribute(hgemm<0>, cudaFuncAttributeMaxDynamicSharedMemorySize, HSMEM);
    cudaFuncSetAttribute(hgemm<1>, cudaFuncAttributeMaxDynamicSharedMemorySize, HSMEM);
    cudaFuncSetAttribute(hgemm<2>, cudaFuncAttributeMaxDynamicSharedMemorySize, HSMEM);
    cudaFuncSetAttribute(hgemm<3>, cudaFuncAttributeMaxDynamicSharedMemorySize, HSMEM);
    cudaFuncSetAttribute(hgemm<4>, cudaFuncAttributeMaxDynamicSharedMemorySize, HSMEM);
    cudaFuncSetAttribute(flash_kernel, cudaFuncAttributeMaxDynamicSharedMemorySize, FSMEM);

    dim3 tb(32, 8);
    dim3 gD(NTOK/128, DD/128);
    dim3 gQKV(NTOK/128, (3*DD)/128);
    dim3 gF(NTOK/128, FF/128);

    // ncu captures launch #4 -> fused-QKV hgemm.
    tsplit4_kernel<<<dim3(DD/32, DD/32, 4*LL), tb>>>(Wq, Wk, Wv, Wo, wA);                // 1
    ctx_kernel<<<BB, 512>>>(fast, slow, ctx_W, ctx_b, gctx);                             // 2
    embed_fused_kernel<<<NTOK, 128>>>(tokens, prev, embed, gctx, etab, egate, ln1,
                                      gx, nx);                                           // 3

    for (int l = 0; l < LL; l++) {
        size_t wo  = (size_t)l*4*DD*DD;
        size_t w1o = (size_t)l*2*FF*DD;
        size_t w2o = (size_t)l*DD*FF;
        if (l > 0)
            rmsnorm_half_kernel<<<NTOK, 128>>>(gx, ln1 + l*DD, nx);
        hgemm<0><<<gQKV, 256, HSMEM>>>(nx, wA + wo,
                                       bq + l*DD, bk + l*DD, bv + l*DD,
                                       nullptr, nullptr, gqkv, nullptr,
                                       NTOK, 3*DD, DD);
        if (l == 0) {
            tsplitW1_kernel<<<dim3(FF/32, DD/32, 2*LL), tb>>>(W1, w1);
            tsplit_kernel<<<dim3(DD/32, FF/32, LL), tb>>>(W2, DD, (size_t)FF*DD, w2, (size_t)DD*FF, FF);
        }
        flash_kernel<<<dim3(TT/64, BB*HH), 256, FSMEM>>>(gqkv, at);
        hgemm<1><<<gD, 256, HSMEM>>>(at, wA + wo + (size_t)1536*DD,
                                     bo + l*DD, nullptr, nullptr, gx, nullptr,
                                     gx, nullptr, NTOK, DD, DD);
        rmsnorm_half_kernel<<<NTOK, 128>>>(gx, ln2 + l*DD, nx);
        hgemm<2><<<gF, 256, HSMEM>>>(nx, w1 + w1o,
                                     nullptr, nullptr, nullptr, nullptr, nullptr,
                                     gffg, nullptr, NTOK, FF, DD);
        hgemm<3><<<gF, 256, HSMEM>>>(nx, w1 + w1o + (size_t)FF*DD,
                                     nullptr, nullptr, nullptr, nullptr, gffg,
                                     nullptr, ff, NTOK, FF, DD);
        hgemm<4><<<gD, 256, HSMEM>>>(ff, w2 + w2o,
                                     nullptr, nullptr, nullptr, gx, nullptr,
                                     gx, nullptr, NTOK, DD, FF);
    }
    rmsnorm_kernel<<<NTOK, 128>>>(gx, ln_f, out);
    logits_kernel<<<NTOK, 128>>>(out, sal_W, sal_b, temp, glog);
    pool_kernel<<<BB*EH, 128>>>(tokens, glog, out, gate_W, gate_b, gwv, gu);
    update_kernel<<<BB, 128>>>(gwv, gu, sal_rms, fast, slow,
                               out + (size_t)NTOK*DD,
                               out + (size_t)NTOK*DD + BB*DD);
}

// round 11
// speedup vs baseline: 1.2911x; 1.2911x over previous
#include <cuda_runtime.h>
#include <cuda_fp16.h>
#include <math.h>
#include <stdint.h>

// ---------------- problem constants ----------------
#define BB 32
#define TT 512
#define DD 512
#define LL 6
#define HH 8
#define HD 64
#define FF 2048      // 4*D
#define EH 4
#define EHD 128
#define MM 100000u
#define OVL 64
#define NTOK (BB*TT)   // 16384

// ---------------- scratch ----------------
__device__ float g_x[NTOK*DD];
__device__ float g_qkv[(size_t)NTOK*3*DD];
__device__ float g_ctx[BB*DD];
__device__ float g_logits[NTOK*EH];
__device__ float g_wv[BB*DD];
__device__ float g_u[BB*EH];
// fp16 activations (single plane)
__device__ __half g_nx[NTOK*DD];
__device__ __half g_at[NTOK*DD];
__device__ __half g_ff[(size_t)NTOK*FF];
// transposed fp16 weights: [N][K]
__device__ __half g_wqkvo[(size_t)LL*4*DD*DD];
__device__ __half g_w1[(size_t)LL*2*FF*DD];
__device__ __half g_w2[(size_t)LL*DD*FF];

// ---------------- PTX helpers ----------------
__device__ __forceinline__ uint32_t smem_to_u32(const void* p) {
    uint32_t a;
    asm("{ .reg .u64 t; cvta.to.shared.u64 t, %1; cvt.u32.u64 %0, t; }" : "=r"(a) : "l"(p));
    return a;
}
__device__ __forceinline__ void cp16(uint32_t dst, const void* src) {
    asm volatile("cp.async.cg.shared.global [%0], [%1], 16;" :: "r"(dst), "l"(src));
}
#define CP_COMMIT() asm volatile("cp.async.commit_group;" ::: "memory")
#define CP_WAIT2()  asm volatile("cp.async.wait_group 2;" ::: "memory")

#define LDSM4(r, addr) \
    asm volatile("ldmatrix.sync.aligned.m8n8.x4.shared.b16 {%0,%1,%2,%3}, [%4];" \
        : "=r"((r)[0]), "=r"((r)[1]), "=r"((r)[2]), "=r"((r)[3]) : "r"(addr))

#define HMMA(c, a, b0, b1) \
    asm volatile("mma.sync.aligned.m16n8k16.row.col.f32.f16.f16.f32 " \
        "{%0,%1,%2,%3}, {%4,%5,%6,%7}, {%8,%9}, {%0,%1,%2,%3};" \
        : "+f"((c)[0]), "+f"((c)[1]), "+f"((c)[2]), "+f"((c)[3]) \
        : "r"((a)[0]), "r"((a)[1]), "r"((a)[2]), "r"((a)[3]), "r"(b0), "r"(b1))

__device__ __forceinline__ uint32_t f22u(float a, float b) {
    __half2 h = __floats2half2_rn(a, b);
    return *(uint32_t*)&h;
}

// ---------------- reduction helpers ----------------
__device__ __forceinline__ float warpReduceSum(float v) {
    #pragma unroll
    for (int o = 16; o; o >>= 1) v += __shfl_xor_sync(0xffffffffu, v, o);
    return v;
}
__device__ __forceinline__ float warpReduceMax(float v) {
    #pragma unroll
    for (int o = 16; o; o >>= 1) v = fmaxf(v, __shfl_xor_sync(0xffffffffu, v, o));
    return v;
}
__device__ __forceinline__ float blockReduceSum128(float v) {
    __shared__ float sm[4];
    __syncthreads();
    v = warpReduceSum(v);
    if ((threadIdx.x & 31) == 0) sm[threadIdx.x >> 5] = v;
    __syncthreads();
    return sm[0] + sm[1] + sm[2] + sm[3];
}
__device__ __forceinline__ float blockReduceMax128(float v) {
    __shared__ float sm[4];
    __syncthreads();
    v = warpReduceMax(v);
    if ((threadIdx.x & 31) == 0) sm[threadIdx.x >> 5] = v;
    __syncthreads();
    return fmaxf(fmaxf(sm[0], sm[1]), fmaxf(sm[2], sm[3]));
}

// ---------------- 4-source transpose to fp16 (Wq/Wk/Wv/Wo stacked) ----------------
__global__ void tsplit4_kernel(const float* __restrict__ s0, const float* __restrict__ s1,
                               const float* __restrict__ s2, const float* __restrict__ s3,
                               __half* __restrict__ dst) {
    __shared__ float t[32][33];
    int z = blockIdx.z;
    int l = z >> 2, sel = z & 3;
    const float* S = (sel == 0 ? s0 : sel == 1 ? s1 : sel == 2 ? s2 : s3) + (size_t)l*DD*DD;
    __half* Hd = dst + (size_t)z*DD*DD;
    int n0 = blockIdx.x*32, k0 = blockIdx.y*32;
    int x = threadIdx.x, y = threadIdx.y;
    #pragma unroll
    for (int i = 0; i < 32; i += 8) t[y+i][x] = S[(size_t)(k0+y+i)*DD + n0+x];
    __syncthreads();
    #pragma unroll
    for (int i = 0; i < 32; i += 8)
        Hd[(size_t)(n0+y+i)*DD + k0+x] = __float2half_rn(t[x][y+i]);
}

// ---------------- generic transpose to fp16 ----------------
__global__ void tsplit_kernel(const float* __restrict__ src, int ldsrc, size_t srcStride,
                              __half* __restrict__ dst, size_t dstStride, int K) {
    __shared__ float t[32][33];
    int l = blockIdx.z;
    const float* S = src + (size_t)l*srcStride;
    __half* Hd = dst + (size_t)l*dstStride;
    int n0 = blockIdx.x*32, k0 = blockIdx.y*32;
    int x = threadIdx.x, y = threadIdx.y;
    #pragma unroll
    for (int i = 0; i < 32; i += 8) t[y+i][x] = S[(size_t)(k0+y+i)*ldsrc + n0+x];
    __syncthreads();
    #pragma unroll
    for (int i = 0; i < 32; i += 8)
        Hd[(size_t)(n0+y+i)*K + k0+x] = __float2half_rn(t[x][y+i]);
}

// ---------------- W1 transpose to fp16 ----------------
__global__ void tsplitW1_kernel(const float* __restrict__ W1, __half* __restrict__ dst) {
    __shared__ float t[32][33];
    int z = blockIdx.z;
    int l = z >> 1, half = z & 1;
    const float* S = W1 + (size_t)l*DD*2*FF + (size_t)half*FF;
    __half* Hd = dst + (size_t)l*2*FF*DD + (size_t)half*FF*DD;
    int n0 = blockIdx.x*32, k0 = blockIdx.y*32;
    int x = threadIdx.x, y = threadIdx.y;
    #pragma unroll
    for (int i = 0; i < 32; i += 8) t[y+i][x] = S[(size_t)(k0+y+i)*(2*FF) + n0+x];
    __syncthreads();
    #pragma unroll
    for (int i = 0; i < 32; i += 8)
        Hd[(size_t)(n0+y+i)*DD + k0+x] = __float2half_rn(t[x][y+i]);
}

// ---------------- fp16 HMMA GEMM (single pass, 4-stage cp.async) ----------------
// MODE 0: +bias3 (QKV select) ; 1: +bias +res ; 4: +res
#define TILE_B 10240
#define STAGE_B 20480
#define HSMEM (4*STAGE_B)

__device__ __forceinline__ void load_stage(uint32_t sb,
        const __half* A, const __half* B, int K, int kof, int tid) {
    #pragma unroll
    for (int i = 0; i < 2; i++) {
        int e = tid + i*256;
        int row = e >> 2, seg = e & 3;
        uint32_t off = (uint32_t)(row*80 + seg*16);
        size_t g = (size_t)row*K + kof + seg*8;
        cp16(sb + off,          A + g);
        cp16(sb + TILE_B + off, B + g);
    }
}

template<int MODE>
__global__ void __launch_bounds__(256, 2)
hgemm(const __half* __restrict__ A, const __half* __restrict__ B,
      const float* __restrict__ bias, const float* __restrict__ bias2,
      const float* __restrict__ bias3,
      const float* __restrict__ Res,
      float* __restrict__ C,
      int M, int N, int K) {
    extern __shared__ char dsm[];
    uint32_t sb = smem_to_u32(dsm);
    int tid = threadIdx.x, lane = tid & 31, wid = tid >> 5;
    int m0 = blockIdx.x * 128, n0 = blockIdx.y * 128;
    int wm = (wid & 1) * 64, wn = (wid >> 1) * 32;
    const __half* Ab = A + (size_t)m0*K;
    const __half* Bb = B + (size_t)n0*K;
    int NC = K >> 5;

    load_stage(sb,             Ab, Bb, K, 0,  tid); CP_COMMIT();
    load_stage(sb + STAGE_B,   Ab, Bb, K, 32, tid); CP_COMMIT();
    load_stage(sb + 2*STAGE_B, Ab, Bb, K, 64, tid); CP_COMMIT();

    float acc[4][4][4];
    #pragma unroll
    for (int a = 0; a < 4; a++)
        #pragma unroll
        for (int b = 0; b < 4; b++)
            #pragma unroll
            for (int c = 0; c < 4; c++) acc[a][b][c] = 0.f;

    const int a_row = lane & 15;
    const int a_k   = (lane >> 4) * 8;
    const int b_row = (lane & 7) + ((lane >> 4) << 3);
    const int b_k   = ((lane >> 3) & 1) * 8;

    for (int i = 0; i < NC; i++) {
        CP_WAIT2();
        __syncthreads();
        if (i + 3 < NC)
            load_stage(sb + (uint32_t)((i+3) & 3)*STAGE_B, Ab, Bb, K, (i+3)*32, tid);
        CP_COMMIT();
        uint32_t st = sb + (uint32_t)(i & 3)*STAGE_B;
        #pragma unroll
        for (int kk = 0; kk < 32; kk += 16) {
            uint32_t a4[4][4], b2[2][4];
            #pragma unroll
            for (int mt = 0; mt < 4; mt++) {
                uint32_t ad = st + (uint32_t)((wm + mt*16 + a_row)*80 + (kk + a_k)*2);
                LDSM4(a4[mt], ad);
            }
            #pragma unroll
            for (int np = 0; np < 2; np++) {
                uint32_t bd = st + TILE_B + (uint32_t)((wn + np*16 + b_row)*80 + (kk + b_k)*2);
                LDSM4(b2[np], bd);
            }
            #pragma unroll
            for (int mt = 0; mt < 4; mt++)
                #pragma unroll
                for (int nt = 0; nt < 4; nt++)
                    HMMA(acc[mt][nt], a4[mt], b2[nt>>1][(nt&1)*2], b2[nt>>1][(nt&1)*2+1]);
        }
    }

    int gid = lane >> 2, ctg = lane & 3;
    #pragma unroll
    for (int mt = 0; mt < 4; mt++)
        #pragma unroll
        for (int nt = 0; nt < 4; nt++) {
            int r0 = m0 + wm + mt*16 + gid;
            int cc = n0 + wn + nt*8 + ctg*2;
            float2 v0 = make_float2(acc[mt][nt][0], acc[mt][nt][1]);
            float2 v1 = make_float2(acc[mt][nt][2], acc[mt][nt][3]);
            if (MODE == 0) {
                const float* bp = (cc < 512) ? (bias + cc)
                                : (cc < 1024) ? (bias2 + cc - 512) : (bias3 + cc - 1024);
                float2 bb = *(const float2*)bp;
                v0.x += bb.x; v0.y += bb.y; v1.x += bb.x; v1.y += bb.y;
            }
            if (MODE == 1) {
                float2 bb = *(const float2*)(bias + cc);
                v0.x += bb.x; v0.y += bb.y; v1.x += bb.x; v1.y += bb.y;
            }
            if (MODE == 1 || MODE == 4) {
                float2 ra = *(const float2*)(Res + (size_t)r0*N + cc);
                float2 rb = *(const float2*)(Res + (size_t)(r0+8)*N + cc);
                v0.x += ra.x; v0.y += ra.y; v1.x += rb.x; v1.y += rb.y;
            }
            *(float2*)(C + (size_t)r0*N + cc) = v0;
            *(float2*)(C + (size_t)(r0+8)*N + cc) = v1;
        }
}

// ---------------- fused gate+value FFN GEMM: ff = half(silu(A@Wg^T) * (A@Wv^T)) ----------------
// block: M=128 x N=64 (of FF), computes BOTH gate and value tiles; A-frags shared.
// stage: A 10240 + Bg 5120 + Bv 5120 = 20480
#define FT_BG 10240
#define FT_BV 15360

__device__ __forceinline__ void load_stage_ffn(uint32_t sb,
        const __half* A, const __half* Bg, const __half* Bv, int K, int kof, int tid) {
    #pragma unroll
    for (int i = 0; i < 2; i++) {    // A: 128 rows
        int e = tid + i*256;
        int row = e >> 2, seg = e & 3;
        uint32_t off = (uint32_t)(row*80 + seg*16);
        cp16(sb + off, A + (size_t)row*K + kof + seg*8);
    }
    {   // Bg + Bv: 64 rows each; e 0..255 -> row 0..63, seg 0..3
        int row = tid >> 2, seg = tid & 3;
        uint32_t off = (uint32_t)(row*80 + seg*16);
        size_t g = (size_t)row*K + kof + seg*8;
        cp16(sb + FT_BG + off, Bg + g);
        cp16(sb + FT_BV + off, Bv + g);
    }
}

__global__ void __launch_bounds__(256, 2)
hgemm_ffn(const __half* __restrict__ A, const __half* __restrict__ Bg,
          const __half* __restrict__ Bv, __half* __restrict__ Out,
          int M, int N, int K) {
    extern __shared__ char dsm[];
    uint32_t sb = smem_to_u32(dsm);
    int tid = threadIdx.x, lane = tid & 31, wid = tid >> 5;
    int m0 = blockIdx.x * 128, n0 = blockIdx.y * 64;
    int wm = (wid & 1) * 64, wn = (wid >> 1) * 16;
    const __half* Ab  = A  + (size_t)m0*K;
    const __half* Bgb = Bg + (size_t)n0*K;
    const __half* Bvb = Bv + (size_t)n0*K;
    int NC = K >> 5;

    load_stage_ffn(sb,             Ab, Bgb, Bvb, K, 0,  tid); CP_COMMIT();
    load_stage_ffn(sb + STAGE_B,   Ab, Bgb, Bvb, K, 32, tid); CP_COMMIT();
    load_stage_ffn(sb + 2*STAGE_B, Ab, Bgb, Bvb, K, 64, tid); CP_COMMIT();

    float ag[4][2][4], av[4][2][4];
    #pragma unroll
    for (int a = 0; a < 4; a++)
        #pragma unroll
        for (int b = 0; b < 2; b++)
            #pragma unroll
            for (int c = 0; c < 4; c++) { ag[a][b][c] = 0.f; av[a][b][c] = 0.f; }

    const int a_row = lane & 15;
    const int a_k   = (lane >> 4) * 8;
    const int b_row = (lane & 7) + ((lane >> 4) << 3);
    const int b_k   = ((lane >> 3) & 1) * 8;

    for (int i = 0; i < NC; i++) {
        CP_WAIT2();
        __syncthreads();
        if (i + 3 < NC)
            load_stage_ffn(sb + (uint32_t)((i+3) & 3)*STAGE_B, Ab, Bgb, Bvb, K, (i+3)*32, tid);
        CP_COMMIT();
        uint32_t st = sb + (uint32_t)(i & 3)*STAGE_B;
        #pragma unroll
        for (int kk = 0; kk < 32; kk += 16) {
            uint32_t a4[4][4], bg[4], bv2[4];
            #pragma unroll
            for (int mt = 0; mt < 4; mt++) {
                uint32_t ad = st + (uint32_t)((wm + mt*16 + a_row)*80 + (kk + a_k)*2);
                LDSM4(a4[mt], ad);
            }
            uint32_t brow = (uint32_t)((wn + b_row)*80 + (kk + b_k)*2);
            LDSM4(bg,  st + FT_BG + brow);
            LDSM4(bv2, st + FT_BV + brow);
            #pragma unroll
            for (int mt = 0; mt < 4; mt++) {
                HMMA(ag[mt][0], a4[mt], bg[0],  bg[1]);
                HMMA(ag[mt][1], a4[mt], bg[2],  bg[3]);
                HMMA(av[mt][0], a4[mt], bv2[0], bv2[1]);
                HMMA(av[mt][1], a4[mt], bv2[2], bv2[3]);
            }
        }
    }

    int gid = lane >> 2, ctg = lane & 3;
    #pragma unroll
    for (int mt = 0; mt < 4; mt++)
        #pragma unroll
        for (int nt = 0; nt < 2; nt++) {
            int r0 = m0 + wm + mt*16 + gid;
            int cc = n0 + wn + nt*8 + ctg*2;
            float g0 = ag[mt][nt][0], g1 = ag[mt][nt][1];
            float g2 = ag[mt][nt][2], g3 = ag[mt][nt][3];
            float s0 = g0/(1.f+__expf(-g0))*av[mt][nt][0];
            float s1 = g1/(1.f+__expf(-g1))*av[mt][nt][1];
            float s2 = g2/(1.f+__expf(-g2))*av[mt][nt][2];
            float s3 = g3/(1.f+__expf(-g3))*av[mt][nt][3];
            *(__half2*)(Out + (size_t)r0*N + cc)     = __floats2half2_rn(s0, s1);
            *(__half2*)(Out + (size_t)(r0+8)*N + cc) = __floats2half2_rn(s2, s3);
        }
}

// ---------------- context projection ----------------
__global__ void ctx_kernel(const float* __restrict__ fast, const float* __restrict__ slow,
                           const float* __restrict__ W, const float* __restrict__ bias,
                           float* __restrict__ out) {
    int b = blockIdx.x, d = threadIdx.x;
    float acc = bias[d];
    const float* fb = fast + b*DD;
    const float* sb = slow + b*DD;
    for (int k = 0; k < DD; k++) acc += fb[k] * W[(size_t)k*DD + d];
    for (int k = 0; k < DD; k++) acc += sb[k] * W[(size_t)(k+DD)*DD + d];
    out[b*DD + d] = acc;
}

// ---------------- embedding + context + engram + fused layer-0 rmsnorm ----------------
__global__ void embed_fused_kernel(const int* __restrict__ tokens, const int* __restrict__ prev,
                                   const float* __restrict__ embed, const float* __restrict__ ctxadd,
                                   const float* __restrict__ etab, const float* __restrict__ egate,
                                   const float* __restrict__ ln1,
                                   float* __restrict__ X, __half* __restrict__ H) {
    int row = blockIdx.x;
    int b = row >> 9, t = row & 511;
    __shared__ unsigned int sidx[EH];
    int tid = threadIdx.x;
    if (tid < EH) {
        unsigned int xseed = 131u + (unsigned)tid * 1009u;
        unsigned int hs = 0u;
        #pragma unroll
        for (int i = 0; i < 4; i++) {
            unsigned int p = xseed; xseed = xseed * 31u + 1u;
            int pos = t - i;
            unsigned int tok = (pos >= 0) ? (unsigned)tokens[b*TT + pos]
                                          : (unsigned)prev[b*OVL + OVL + pos];
            hs += tok * p;
        }
        sidx[tid] = hs % MM;
    }
    __syncthreads();
    int d0 = tid * 4;
    int eh = tid >> 5;
    int jj = d0 & 127;
    int tok = tokens[b*TT + t];
    float4 ev = *(const float4*)(embed + (size_t)tok*DD + d0);
    float4 cv = *(const float4*)(ctxadd + b*DD + d0);
    float4 rv = *(const float4*)(etab + ((size_t)sidx[eh]*EH + eh)*EHD + jj);
    float4 gv = *(const float4*)(egate + eh*EHD + jj);
    float4 o;
    o.x = ev.x + cv.x + rv.x * (1.f/(1.f+__expf(-gv.x)));
    o.y = ev.y + cv.y + rv.y * (1.f/(1.f+__expf(-gv.y)));
    o.z = ev.z + cv.z + rv.z * (1.f/(1.f+__expf(-gv.z)));
    o.w = ev.w + cv.w + rv.w * (1.f/(1.f+__expf(-gv.w)));
    *(float4*)(X + (size_t)row*DD + d0) = o;
    float ss = blockReduceSum128(o.x*o.x + o.y*o.y + o.z*o.z + o.w*o.w);
    float inv = rsqrtf(ss * (1.f/DD) + 1e-6f);
    float4 sc = ((const float4*)ln1)[tid];
    size_t off = (size_t)row*DD + d0;
    *(__half2*)(H + off)     = __floats2half2_rn(o.x*inv*sc.x, o.y*inv*sc.y);
    *(__half2*)(H + off + 2) = __floats2half2_rn(o.z*inv*sc.z, o.w*inv*sc.w);
}

// ---------------- RMSNorm -> fp16 plane ----------------
__global__ void rmsnorm_half_kernel(const float* __restrict__ X, const float* __restrict__ scale,
                                    __half* __restrict__ H) {
    int row = blockIdx.x;
    float4 v = ((const float4*)(X + (size_t)row*DD))[threadIdx.x];
    float ss = v.x*v.x + v.y*v.y + v.z*v.z + v.w*v.w;
    ss = blockReduceSum128(ss);
    float inv = rsqrtf(ss * (1.f/DD) + 1e-6f);
    float4 sc = ((const float4*)scale)[threadIdx.x];
    size_t off = (size_t)row*DD + threadIdx.x*4;
    *(__half2*)(H + off)     = __floats2half2_rn(v.x*inv*sc.x, v.y*inv*sc.y);
    *(__half2*)(H + off + 2) = __floats2half2_rn(v.z*inv*sc.z, v.w*inv*sc.w);
}

// ---------------- final RMSNorm (fp32 out) ----------------
__global__ void rmsnorm_kernel(const float* __restrict__ X, const float* __restrict__ scale,
                               float* __restrict__ Out) {
    int row = blockIdx.x;
    float4 v = ((const float4*)(X + (size_t)row*DD))[threadIdx.x];
    float ss = v.x*v.x + v.y*v.y + v.z*v.z + v.w*v.w;
    ss = blockReduceSum128(ss);
    float inv = rsqrtf(ss * (1.f/DD) + 1e-6f);
    float4 sc = ((const float4*)scale)[threadIdx.x];
    float4 o;
    o.x = v.x*inv*sc.x; o.y = v.y*inv*sc.y; o.z = v.z*inv*sc.z; o.w = v.w*inv*sc.w;
    ((float4*)(Out + (size_t)row*DD))[threadIdx.x] = o;
}

// ---------------- rope helper ----------------
__device__ __forceinline__ float4 rope4(float4 v, int t, int dv) {
    const float c = 9.210340371976184f / 64.f;
    float inv0 = __expf(-(float)dv * c);
    float inv1 = __expf(-(float)(dv+2) * c);
    float s0, c0, s1, c1;
    __sincosf((float)t * inv0, &s0, &c0);
    __sincosf((float)t * inv1, &s1, &c1);
    float4 r;
    r.x = v.x*c0 - v.y*s0;  r.y = v.x*s0 + v.y*c0;
    r.z = v.z*c1 - v.w*s1;  r.w = v.z*s1 + v.w*c1;
    return r;
}

// ---------------- HMMA causal flash attention: BQ=64, BK=64, HD=64, 256 threads ----------------
#define FPAD 72
#define FSMEM (3*64*FPAD*2 + 2*128*4 + 64*64*4)   // 45056

__global__ void __launch_bounds__(256) flash_kernel(const float* __restrict__ QKV,
        __half* __restrict__ Oh) {
    extern __shared__ char fsm[];
    __half* Qh = (__half*)fsm;
    __half* Kh = Qh + 64*FPAD;
    __half* Vt = Kh + 64*FPAD;
    float* smax = (float*)(Vt + 64*FPAD);
    float* ssum = smax + 128;
    float* obuf = ssum + 128;
    uint32_t uq = smem_to_u32(Qh);
    uint32_t uk = smem_to_u32(Kh);
    uint32_t uv = smem_to_u32(Vt);

    int bh = blockIdx.y;
    int b = bh >> 3, h = bh & 7;
    int q0 = blockIdx.x * 64;
    int tid = threadIdx.x, lane = tid & 31, wid = tid >> 5;
    int wm = wid & 3, wk2 = wid >> 2;
    int gid = lane >> 2, ctg = lane & 3;
    const int a_row = lane & 15;
    const int a_k   = (lane >> 4) * 8;
    const int b_row = (lane & 7) + ((lane >> 4) << 3);
    const int b_k   = ((lane >> 3) & 1) * 8;
    size_t base = ((size_t)b*TT)*1536 + h*HD;
    const float scl = 0.125f;

    for (int i = tid; i < 64*16; i += 256) {
        int r = i >> 4, dv = (i & 15) * 4;
        float4 v = rope4(*(const float4*)(QKV + base + (size_t)(q0 + r)*1536 + dv), q0 + r, dv);
        __half2* dst = (__half2*)(Qh + r*FPAD + dv);
        dst[0] = __floats2half2_rn(v.x, v.y);
        dst[1] = __floats2half2_rn(v.z, v.w);
    }

    float m0 = -1e30f, m1 = -1e30f, l0 = 0.f, l1 = 0.f;
    float oacc[8][4];
    #pragma unroll
    for (int i = 0; i < 8; i++)
        #pragma unroll
        for (int j = 0; j < 4; j++) oacc[i][j] = 0.f;

    int row0 = q0 + wm*16 + gid;
    int nkt = (q0 >> 6) + 1;
    for (int kt = 0; kt < nkt; kt++) {
        int k0 = kt * 64;
        __syncthreads();
        for (int i = tid; i < 64*16; i += 256) {
            int r = i >> 4, dv = (i & 15)*4;
            size_t g = base + (size_t)(k0 + r)*1536 + dv;
            float4 kv = rope4(*(const float4*)(QKV + g + 512), k0 + r, dv);
            __half2* kd = (__half2*)(Kh + r*FPAD + dv);
            kd[0] = __floats2half2_rn(kv.x, kv.y);
            kd[1] = __floats2half2_rn(kv.z, kv.w);
            float4 vv = *(const float4*)(QKV + g + 1024);
            Vt[(dv+0)*FPAD + r] = __float2half_rn(vv.x);
            Vt[(dv+1)*FPAD + r] = __float2half_rn(vv.y);
            Vt[(dv+2)*FPAD + r] = __float2half_rn(vv.z);
            Vt[(dv+3)*FPAD + r] = __float2half_rn(vv.w);
        }
        __syncthreads();
        float sacc[4][4];
        #pragma unroll
        for (int nt = 0; nt < 4; nt++)
            #pragma unroll
            for (int j = 0; j < 4; j++) sacc[nt][j] = 0.f;
        #pragma unroll
        for (int kk = 0; kk < 64; kk += 16) {
            uint32_t af[4], bf[2][4];
            LDSM4(af, uq + (uint32_t)((wm*16 + a_row)*FPAD + kk + a_k)*2);
            #pragma unroll
            for (int np = 0; np < 2; np++)
                LDSM4(bf[np], uk + (uint32_t)((wk2*32 + np*16 + b_row)*FPAD + kk + b_k)*2);
            #pragma unroll
            for (int nt = 0; nt < 4; nt++)
                HMMA(sacc[nt], af, bf[nt>>1][(nt&1)*2], bf[nt>>1][(nt&1)*2+1]);
        }
        bool diag = (kt == nkt - 1);
        #pragma unroll
        for (int nt = 0; nt < 4; nt++) {
            int col = k0 + wk2*32 + nt*8 + ctg*2;
            #pragma unroll
            for (int j = 0; j < 4; j++) {
                int cc = col + (j & 1);
                int rr = row0 + ((j >> 1) << 3);
                sacc[nt][j] = (!diag || cc <= rr) ? sacc[nt][j]*scl : -1e9f;
            }
        }
        float rm0 = fmaxf(fmaxf(sacc[0][0], sacc[0][1]), fmaxf(sacc[1][0], sacc[1][1]));
        rm0 = fmaxf(rm0, fmaxf(fmaxf(sacc[2][0], sacc[2][1]), fmaxf(sacc[3][0], sacc[3][1])));
        float rm1 = fmaxf(fmaxf(sacc[0][2], sacc[0][3]), fmaxf(sacc[1][2], sacc[1][3]));
        rm1 = fmaxf(rm1, fmaxf(fmaxf(sacc[2][2], sacc[2][3]), fmaxf(sacc[3][2], sacc[3][3])));
        rm0 = fmaxf(rm0, __shfl_xor_sync(0xffffffffu, rm0, 1));
        rm0 = fmaxf(rm0, __shfl_xor_sync(0xffffffffu, rm0, 2));
        rm1 = fmaxf(rm1, __shfl_xor_sync(0xffffffffu, rm1, 1));
        rm1 = fmaxf(rm1, __shfl_xor_sync(0xffffffffu, rm1, 2));
        if (ctg == 0) {
            smax[wk2*64 + wm*16 + gid]     = rm0;
            smax[wk2*64 + wm*16 + gid + 8] = rm1;
        }
        __syncthreads();
        float mx0 = fmaxf(smax[wm*16 + gid],     smax[64 + wm*16 + gid]);
        float mx1 = fmaxf(smax[wm*16 + gid + 8], smax[64 + wm*16 + gid + 8]);
        float mn0 = fmaxf(m0, mx0), mn1 = fmaxf(m1, mx1);
        float c0 = __expf(m0 - mn0), c1 = __expf(m1 - mn1);
        m0 = mn0; m1 = mn1;
        float rs0 = 0.f, rs1 = 0.f;
        #pragma unroll
        for (int nt = 0; nt < 4; nt++) {
            sacc[nt][0] = __expf(sacc[nt][0] - mn0); rs0 += sacc[nt][0];
            sacc[nt][1] = __expf(sacc[nt][1] - mn0); rs0 += sacc[nt][1];
            sacc[nt][2] = __expf(sacc[nt][2] - mn1); rs1 += sacc[nt][2];
            sacc[nt][3] = __expf(sacc[nt][3] - mn1); rs1 += sacc[nt][3];
        }
        rs0 += __shfl_xor_sync(0xffffffffu, rs0, 1);
        rs0 += __shfl_xor_sync(0xffffffffu, rs0, 2);
        rs1 += __shfl_xor_sync(0xffffffffu, rs1, 1);
        rs1 += __shfl_xor_sync(0xffffffffu, rs1, 2);
        if (ctg == 0) {
            ssum[wk2*64 + wm*16 + gid]     = rs0;
            ssum[wk2*64 + wm*16 + gid + 8] = rs1;
        }
        #pragma unroll
        for (int nh = 0; nh < 8; nh++) {
            oacc[nh][0] *= c0; oacc[nh][1] *= c0;
            oacc[nh][2] *= c1; oacc[nh][3] *= c1;
        }
        __syncthreads();
        l0 = l0*c0 + ssum[wm*16 + gid]     + ssum[64 + wm*16 + gid];
        l1 = l1*c1 + ssum[wm*16 + gid + 8] + ssum[64 + wm*16 + gid + 8];
        #pragma unroll
        for (int g = 0; g < 2; g++) {
            uint32_t pf[4];
            pf[0] = f22u(sacc[2*g][0],   sacc[2*g][1]);
            pf[1] = f22u(sacc[2*g][2],   sacc[2*g][3]);
            pf[2] = f22u(sacc[2*g+1][0], sacc[2*g+1][1]);
            pf[3] = f22u(sacc[2*g+1][2], sacc[2*g+1][3]);
            int kof = wk2*32 + g*16;
            #pragma unroll
            for (int nh = 0; nh < 4; nh++) {
                uint32_t bf2[4];
                LDSM4(bf2, uv + (uint32_t)((nh*16 + b_row)*FPAD + kof + b_k)*2);
                HMMA(oacc[2*nh],   pf, bf2[0], bf2[1]);
                HMMA(oacc[2*nh+1], pf, bf2[2], bf2[3]);
            }
        }
    }
    __syncthreads();
    if (wk2 == 1) {
        #pragma unroll
        for (int nh = 0; nh < 8; nh++) {
            int c = nh*8 + ctg*2;
            float* o0 = obuf + (wm*16 + gid)*64 + c;
            float* o1 = obuf + (wm*16 + gid + 8)*64 + c;
            o0[0] = oacc[nh][0]; o0[1] = oacc[nh][1];
            o1[0] = oacc[nh][2]; o1[1] = oacc[nh][3];
        }
    }
    __syncthreads();
    if (wk2 == 0) {
        float inv0 = 1.f / l0, inv1 = 1.f / l1;
        #pragma unroll
        for (int nh = 0; nh < 8; nh++) {
            int c = nh*8 + ctg*2;
            const float* o0 = obuf + (wm*16 + gid)*64 + c;
            const float* o1 = obuf + (wm*16 + gid + 8)*64 + c;
            float x0 = (oacc[nh][0] + o0[0]) * inv0;
            float x1 = (oacc[nh][1] + o0[1]) * inv0;
            float y0 = (oacc[nh][2] + o1[0]) * inv1;
            float y1 = (oacc[nh][3] + o1[1]) * inv1;
            size_t r0 = (size_t)(b*TT + q0 + wm*16 + gid)*DD + h*HD + c;
            size_t r1 = (size_t)(b*TT + q0 + wm*16 + gid + 8)*DD + h*HD + c;
            *(__half2*)(Oh + r0) = __floats2half2_rn(x0, x1);
            *(__half2*)(Oh + r1) = __floats2half2_rn(y0, y1);
        }
    }
}

// ---------------- salience logits ----------------
__global__ void logits_kernel(const float* __restrict__ X, const float* __restrict__ sal_W,
                              const float* __restrict__ sal_b, const float* __restrict__ temp,
                              float* __restrict__ out) {
    int row = blockIdx.x;
    int e = threadIdx.x >> 5, lane = threadIdx.x & 31;
    const float* xr = X + (size_t)row*DD;
    float acc = 0.f;
    for (int d = lane; d < DD; d += 32)
        acc += xr[d] * sal_W[d*EH + e];
    acc = warpReduceSum(acc);
    if (lane == 0) {
        float tp = log1pf(expf(temp[e])) + 0.3f;
        out[(size_t)row*EH + e] = (acc + sal_b[e]) / tp;
    }
}

// ---------------- masked softmax pool ----------------
__global__ void pool_kernel(const int* __restrict__ tokens, const float* __restrict__ logits,
                            const float* __restrict__ X, const float* __restrict__ gate_W,
                            const float* __restrict__ gate_b,
                            float* __restrict__ wv_out, float* __restrict__ u_out) {
    int b = blockIdx.x >> 2, e = blockIdx.x & 3;
    int tid = threadIdx.x;
    __shared__ float ws[TT];
    float lg4[4]; int mv4[4];
    float lmax = -1e30f; float lvalid = 0.f;
    #pragma unroll
    for (int p = 0; p < 4; p++) {
        int t = tid + p*128;
        int mv = (tokens[b*TT + t] != 0);
        float lgv = logits[((size_t)b*TT + t)*EH + e];
        float sf = mv ? lgv : -1e9f;
        lg4[p] = sf; mv4[p] = mv;
        lmax = fmaxf(lmax, sf);
        lvalid += (float)mv;
    }
    float mx = blockReduceMax128(lmax);
    float lsum = 0.f;
    #pragma unroll
    for (int p = 0; p < 4; p++) {
        int t = tid + p*128;
        float ev = mv4[p] ? expf(lg4[p] - mx) : 0.f;
        ws[t] = ev;
        lsum += ev;
    }
    float ssum = blockReduceSum128(lsum);
    float nvalid = blockReduceSum128(lvalid);
    float wsc = 1.f / (ssum + 1e-6f);
    __syncthreads();
    float acc = 0.f;
    const float* xb = X + ((size_t)b*TT)*DD + e*EHD + tid;
    for (int t = 0; t < TT; t++)
        acc += ws[t] * xb[(size_t)t*DD];
    acc *= wsc;
    wv_out[b*DD + e*EHD + tid] = acc;
    float gsum = blockReduceSum128(acc * gate_W[tid]);
    if (tid == 0) {
        float gl = gsum + gate_b[0];
        float u = (nvalid > 0.f) ? 1.f/(1.f+expf(-gl)) : 0.f;
        u_out[b*EH + e] = u;
    }
}

// ---------------- fast/slow state update ----------------
__global__ void update_kernel(const float* __restrict__ wv, const float* __restrict__ u,
                              const float* __restrict__ sal_rms,
                              const float* __restrict__ fast, const float* __restrict__ slow,
                              float* __restrict__ out_fast, float* __restrict__ out_slow) {
    int b = blockIdx.x, tid = threadIdx.x;
    float4 v = ((const float4*)(wv + b*DD))[tid];
    float ss = blockReduceSum128(v.x*v.x + v.y*v.y + v.z*v.z + v.w*v.w);
    float inv = rsqrtf(ss * (1.f/DD) + 1e-6f);
    float4 sr = ((const float4*)sal_rms)[tid];
    int e = tid >> 5;
    float uu = u[b*EH + e];
    float4 f = ((const float4*)(fast + b*DD))[tid];
    float4 s = ((const float4*)(slow + b*DD))[tid];
    float4 wn;
    wn.x = v.x*inv*sr.x; wn.y = v.y*inv*sr.y; wn.z = v.z*inv*sr.z; wn.w = v.w*inv*sr.w;
    float4 nf, ns;
    nf.x = (1.f-uu)*f.x + uu*wn.x;  nf.y = (1.f-uu)*f.y + uu*wn.y;
    nf.z = (1.f-uu)*f.z + uu*wn.z;  nf.w = (1.f-uu)*f.w + uu*wn.w;
    float ud = 0.1f*uu;
    ns.x = (1.f-ud)*s.x + ud*wn.x;  ns.y = (1.f-ud)*s.y + ud*wn.y;
    ns.z = (1.f-ud)*s.z + ud*wn.z;  ns.w = (1.f-ud)*s.w + ud*wn.w;
    ((float4*)(out_fast + b*DD))[tid] = nf;
    ((float4*)(out_slow + b*DD))[tid] = ns;
}

// ---------------- launch ----------------
extern "C" void kernel_launch(void* const* d_in, const int* in_sizes, int n_in,
                              void* d_out, int out_size) {
    const int*   tokens = (const int*)  d_in[0];
    const int*   prev   = (const int*)  d_in[1];
    const float* fast   = (const float*)d_in[2];
    const float* slow   = (const float*)d_in[3];
    const float* embed  = (const float*)d_in[4];
    const float* ctx_W  = (const float*)d_in[5];
    const float* ctx_b  = (const float*)d_in[6];
    const float* etab   = (const float*)d_in[7];
    const float* egate  = (const float*)d_in[8];
    const float* ln1    = (const float*)d_in[9];
    const float* Wq     = (const float*)d_in[10];
    const float* bq     = (const float*)d_in[11];
    const float* Wk     = (const float*)d_in[12];
    const float* bk     = (const float*)d_in[13];
    const float* Wv     = (const float*)d_in[14];
    const float* bv     = (const float*)d_in[15];
    const float* Wo     = (const float*)d_in[16];
    const float* bo     = (const float*)d_in[17];
    const float* ln2    = (const float*)d_in[18];
    const float* W1     = (const float*)d_in[19];
    const float* W2     = (const float*)d_in[20];
    const float* ln_f   = (const float*)d_in[21];
    const float* sal_W  = (const float*)d_in[22];
    const float* sal_b  = (const float*)d_in[23];
    const float* temp   = (const float*)d_in[24];
    const float* gate_W = (const float*)d_in[25];
    const float* gate_b = (const float*)d_in[26];
    const float* sal_rms= (const float*)d_in[27];
    float* out = (float*)d_out;

    float *gx, *gqkv, *gctx, *glog, *gwv, *gu;
    __half *nx, *at, *ff;
    __half *wA, *w1, *w2;
    cudaGetSymbolAddress((void**)&gx,   g_x);
    cudaGetSymbolAddress((void**)&gqkv, g_qkv);
    cudaGetSymbolAddress((void**)&gctx, g_ctx);
    cudaGetSymbolAddress((void**)&glog, g_logits);
    cudaGetSymbolAddress((void**)&gwv,  g_wv);
    cudaGetSymbolAddress((void**)&gu,   g_u);
    cudaGetSymbolAddress((void**)&nx,   g_nx);
    cudaGetSymbolAddress((void**)&at,   g_at);
    cudaGetSymbolAddress((void**)&ff,   g_ff);
    cudaGetSymbolAddress((void**)&wA,   g_wqkvo);
    cudaGetSymbolAddress((void**)&w1,   g_w1);
    cudaGetSymbolAddress((void**)&w2,   g_w2);

    cudaFuncSetAttribute(hgemm<0>, cudaFuncAttributeMaxDynamicSharedMemorySize, HSMEM);
    cudaFuncSetAttribute(hgemm<1>, cudaFuncAttributeMaxDynamicSharedMemorySize, HSMEM);
    cudaFuncSetAttribute(hgemm<4>, cudaFuncAttributeMaxDynamicSharedMemorySize, HSMEM);
    cudaFuncSetAttribute(hgemm_ffn, cudaFuncAttributeMaxDynamicSharedMemorySize, HSMEM);
    cudaFuncSetAttribute(flash_kernel, cudaFuncAttributeMaxDynamicSharedMemorySize, FSMEM);

    dim3 tb(32, 8);
    dim3 gD(NTOK/128, DD/128);
    dim3 gQKV(NTOK/128, (3*DD)/128);
    dim3 gFF(NTOK/128, FF/64);

    // ncu captures launch #4 -> fused-QKV hgemm.
    tsplit4_kernel<<<dim3(DD/32, DD/32, 4*LL), tb>>>(Wq, Wk, Wv, Wo, wA);                // 1
    ctx_kernel<<<BB, 512>>>(fast, slow, ctx_W, ctx_b, gctx);                             // 2
    embed_fused_kernel<<<NTOK, 128>>>(tokens, prev, embed, gctx, etab, egate, ln1,
                                      gx, nx);                                           // 3

    for (int l = 0; l < LL; l++) {
        size_t wo  = (size_t)l*4*DD*DD;
        size_t w1o = (size_t)l*2*FF*DD;
        size_t w2o = (size_t)l*DD*FF;
        if (l > 0)
            rmsnorm_half_kernel<<<NTOK, 128>>>(gx, ln1 + l*DD, nx);
        hgemm<0><<<gQKV, 256, HSMEM>>>(nx, wA + wo,
                                       bq + l*DD, bk + l*DD, bv + l*DD,
                                       nullptr, gqkv, NTOK, 3*DD, DD);
        if (l == 0) {
            tsplitW1_kernel<<<dim3(FF/32, DD/32, 2*LL), tb>>>(W1, w1);
            tsplit_kernel<<<dim3(DD/32, FF/32, LL), tb>>>(W2, DD, (size_t)FF*DD, w2, (size_t)DD*FF, FF);
        }
        flash_kernel<<<dim3(TT/64, BB*HH), 256, FSMEM>>>(gqkv, at);
        hgemm<1><<<gD, 256, HSMEM>>>(at, wA + wo + (size_t)1536*DD,
                                     bo + l*DD, nullptr, nullptr, gx,
                                     gx, NTOK, DD, DD);
        rmsnorm_half_kernel<<<NTOK, 128>>>(gx, ln2 + l*DD, nx);
        hgemm_ffn<<<gFF, 256, HSMEM>>>(nx, w1 + w1o, w1 + w1o + (size_t)FF*DD,
                                       ff, NTOK, FF, DD);
        hgemm<4><<<gD, 256, HSMEM>>>(ff, w2 + w2o,
                                     nullptr, nullptr, nullptr, gx,
                                     gx, NTOK, DD, FF);
    }
    rmsnorm_kernel<<<NTOK, 128>>>(gx, ln_f, out);
    logits_kernel<<<NTOK, 128>>>(out, sal_W, sal_b, temp, glog);
    pool_kernel<<<BB*EH, 128>>>(tokens, glog, out, gate_W, gate_b, gwv, gu);
    update_kernel<<<BB, 128>>>(gwv, gu, sal_rms, fast, slow,
                               out + (size_t)NTOK*DD,
                               out + (size_t)NTOK*DD + BB*DD);
}

// round 12
// speedup vs baseline: 1.3238x; 1.0254x over previous
#include <cuda_runtime.h>
#include <cuda_fp16.h>
#include <math.h>
#include <stdint.h>

// ---------------- problem constants ----------------
#define BB 32
#define TT 512
#define DD 512
#define LL 6
#define HH 8
#define HD 64
#define FF 2048      // 4*D
#define EH 4
#define EHD 128
#define MM 100000u
#define OVL 64
#define NTOK (BB*TT)   // 16384

// ---------------- scratch ----------------
__device__ float g_x[NTOK*DD];
__device__ float g_qkv[(size_t)NTOK*3*DD];
__device__ float g_ctx[BB*DD];
__device__ float g_logits[NTOK*EH];
__device__ float g_wv[BB*DD];
__device__ float g_u[BB*EH];
// fp16 activations (single plane)
__device__ __half g_nx[NTOK*DD];
__device__ __half g_at[NTOK*DD];
__device__ __half g_ff[(size_t)NTOK*FF];
// transposed fp16 weights: [N][K]
__device__ __half g_wqkvo[(size_t)LL*4*DD*DD];
__device__ __half g_w1[(size_t)LL*2*FF*DD];
__device__ __half g_w2[(size_t)LL*DD*FF];

// ---------------- PTX helpers ----------------
__device__ __forceinline__ uint32_t smem_to_u32(const void* p) {
    uint32_t a;
    asm("{ .reg .u64 t; cvta.to.shared.u64 t, %1; cvt.u32.u64 %0, t; }" : "=r"(a) : "l"(p));
    return a;
}
__device__ __forceinline__ void cp16(uint32_t dst, const void* src) {
    asm volatile("cp.async.cg.shared.global [%0], [%1], 16;" :: "r"(dst), "l"(src));
}
#define CP_COMMIT() asm volatile("cp.async.commit_group;" ::: "memory")
#define CP_WAIT2()  asm volatile("cp.async.wait_group 2;" ::: "memory")

#define LDSM4(r, addr) \
    asm volatile("ldmatrix.sync.aligned.m8n8.x4.shared.b16 {%0,%1,%2,%3}, [%4];" \
        : "=r"((r)[0]), "=r"((r)[1]), "=r"((r)[2]), "=r"((r)[3]) : "r"(addr))

#define HMMA(c, a, b0, b1) \
    asm volatile("mma.sync.aligned.m16n8k16.row.col.f32.f16.f16.f32 " \
        "{%0,%1,%2,%3}, {%4,%5,%6,%7}, {%8,%9}, {%0,%1,%2,%3};" \
        : "+f"((c)[0]), "+f"((c)[1]), "+f"((c)[2]), "+f"((c)[3]) \
        : "r"((a)[0]), "r"((a)[1]), "r"((a)[2]), "r"((a)[3]), "r"(b0), "r"(b1))

__device__ __forceinline__ uint32_t f22u(float a, float b) {
    __half2 h = __floats2half2_rn(a, b);
    return *(uint32_t*)&h;
}

// ---------------- reduction helpers ----------------
__device__ __forceinline__ float warpReduceSum(float v) {
    #pragma unroll
    for (int o = 16; o; o >>= 1) v += __shfl_xor_sync(0xffffffffu, v, o);
    return v;
}
__device__ __forceinline__ float warpReduceMax(float v) {
    #pragma unroll
    for (int o = 16; o; o >>= 1) v = fmaxf(v, __shfl_xor_sync(0xffffffffu, v, o));
    return v;
}
__device__ __forceinline__ float blockReduceSum128(float v) {
    __shared__ float sm[4];
    __syncthreads();
    v = warpReduceSum(v);
    if ((threadIdx.x & 31) == 0) sm[threadIdx.x >> 5] = v;
    __syncthreads();
    return sm[0] + sm[1] + sm[2] + sm[3];
}
__device__ __forceinline__ float blockReduceMax128(float v) {
    __shared__ float sm[4];
    __syncthreads();
    v = warpReduceMax(v);
    if ((threadIdx.x & 31) == 0) sm[threadIdx.x >> 5] = v;
    __syncthreads();
    return fmaxf(fmaxf(sm[0], sm[1]), fmaxf(sm[2], sm[3]));
}

// ---------------- 4-source transpose to fp16 (Wq/Wk/Wv/Wo stacked) ----------------
__global__ void tsplit4_kernel(const float* __restrict__ s0, const float* __restrict__ s1,
                               const float* __restrict__ s2, const float* __restrict__ s3,
                               __half* __restrict__ dst) {
    __shared__ float t[32][33];
    int z = blockIdx.z;
    int l = z >> 2, sel = z & 3;
    const float* S = (sel == 0 ? s0 : sel == 1 ? s1 : sel == 2 ? s2 : s3) + (size_t)l*DD*DD;
    __half* Hd = dst + (size_t)z*DD*DD;
    int n0 = blockIdx.x*32, k0 = blockIdx.y*32;
    int x = threadIdx.x, y = threadIdx.y;
    #pragma unroll
    for (int i = 0; i < 32; i += 8) t[y+i][x] = S[(size_t)(k0+y+i)*DD + n0+x];
    __syncthreads();
    #pragma unroll
    for (int i = 0; i < 32; i += 8)
        Hd[(size_t)(n0+y+i)*DD + k0+x] = __float2half_rn(t[x][y+i]);
}

// ---------------- generic transpose to fp16 ----------------
__global__ void tsplit_kernel(const float* __restrict__ src, int ldsrc, size_t srcStride,
                              __half* __restrict__ dst, size_t dstStride, int K) {
    __shared__ float t[32][33];
    int l = blockIdx.z;
    const float* S = src + (size_t)l*srcStride;
    __half* Hd = dst + (size_t)l*dstStride;
    int n0 = blockIdx.x*32, k0 = blockIdx.y*32;
    int x = threadIdx.x, y = threadIdx.y;
    #pragma unroll
    for (int i = 0; i < 32; i += 8) t[y+i][x] = S[(size_t)(k0+y+i)*ldsrc + n0+x];
    __syncthreads();
    #pragma unroll
    for (int i = 0; i < 32; i += 8)
        Hd[(size_t)(n0+y+i)*K + k0+x] = __float2half_rn(t[x][y+i]);
}

// ---------------- W1 transpose to fp16 ----------------
__global__ void tsplitW1_kernel(const float* __restrict__ W1, __half* __restrict__ dst) {
    __shared__ float t[32][33];
    int z = blockIdx.z;
    int l = z >> 1, half = z & 1;
    const float* S = W1 + (size_t)l*DD*2*FF + (size_t)half*FF;
    __half* Hd = dst + (size_t)l*2*FF*DD + (size_t)half*FF*DD;
    int n0 = blockIdx.x*32, k0 = blockIdx.y*32;
    int x = threadIdx.x, y = threadIdx.y;
    #pragma unroll
    for (int i = 0; i < 32; i += 8) t[y+i][x] = S[(size_t)(k0+y+i)*(2*FF) + n0+x];
    __syncthreads();
    #pragma unroll
    for (int i = 0; i < 32; i += 8)
        Hd[(size_t)(n0+y+i)*DD + k0+x] = __float2half_rn(t[x][y+i]);
}

// ---------------- fp16 HMMA GEMM (single pass, 4-stage cp.async) ----------------
// MODE 0: +bias3 (QKV select) ; 1: +bias +res ; 4: +res
#define TILE_B 10240
#define STAGE_B 20480
#define HSMEM (4*STAGE_B)

__device__ __forceinline__ void load_stage(uint32_t sb,
        const __half* A, const __half* B, int K, int kof, int tid) {
    #pragma unroll
    for (int i = 0; i < 2; i++) {
        int e = tid + i*256;
        int row = e >> 2, seg = e & 3;
        uint32_t off = (uint32_t)(row*80 + seg*16);
        size_t g = (size_t)row*K + kof + seg*8;
        cp16(sb + off,          A + g);
        cp16(sb + TILE_B + off, B + g);
    }
}

template<int MODE>
__global__ void __launch_bounds__(256, 2)
hgemm(const __half* __restrict__ A, const __half* __restrict__ B,
      const float* __restrict__ bias, const float* __restrict__ bias2,
      const float* __restrict__ bias3,
      const float* __restrict__ Res,
      float* __restrict__ C,
      int M, int N, int K) {
    extern __shared__ char dsm[];
    uint32_t sb = smem_to_u32(dsm);
    int tid = threadIdx.x, lane = tid & 31, wid = tid >> 5;
    int m0 = blockIdx.x * 128, n0 = blockIdx.y * 128;
    int wm = (wid & 1) * 64, wn = (wid >> 1) * 32;
    const __half* Ab = A + (size_t)m0*K;
    const __half* Bb = B + (size_t)n0*K;
    int NC = K >> 5;

    load_stage(sb,             Ab, Bb, K, 0,  tid); CP_COMMIT();
    load_stage(sb + STAGE_B,   Ab, Bb, K, 32, tid); CP_COMMIT();
    load_stage(sb + 2*STAGE_B, Ab, Bb, K, 64, tid); CP_COMMIT();

    float acc[4][4][4];
    #pragma unroll
    for (int a = 0; a < 4; a++)
        #pragma unroll
        for (int b = 0; b < 4; b++)
            #pragma unroll
            for (int c = 0; c < 4; c++) acc[a][b][c] = 0.f;

    const int a_row = lane & 15;
    const int a_k   = (lane >> 4) * 8;
    const int b_row = (lane & 7) + ((lane >> 4) << 3);
    const int b_k   = ((lane >> 3) & 1) * 8;

    for (int i = 0; i < NC; i++) {
        CP_WAIT2();
        __syncthreads();
        if (i + 3 < NC)
            load_stage(sb + (uint32_t)((i+3) & 3)*STAGE_B, Ab, Bb, K, (i+3)*32, tid);
        CP_COMMIT();
        uint32_t st = sb + (uint32_t)(i & 3)*STAGE_B;
        #pragma unroll
        for (int kk = 0; kk < 32; kk += 16) {
            uint32_t a4[4][4], b2[2][4];
            #pragma unroll
            for (int mt = 0; mt < 4; mt++) {
                uint32_t ad = st + (uint32_t)((wm + mt*16 + a_row)*80 + (kk + a_k)*2);
                LDSM4(a4[mt], ad);
            }
            #pragma unroll
            for (int np = 0; np < 2; np++) {
                uint32_t bd = st + TILE_B + (uint32_t)((wn + np*16 + b_row)*80 + (kk + b_k)*2);
                LDSM4(b2[np], bd);
            }
            #pragma unroll
            for (int mt = 0; mt < 4; mt++)
                #pragma unroll
                for (int nt = 0; nt < 4; nt++)
                    HMMA(acc[mt][nt], a4[mt], b2[nt>>1][(nt&1)*2], b2[nt>>1][(nt&1)*2+1]);
        }
    }

    int gid = lane >> 2, ctg = lane & 3;
    #pragma unroll
    for (int mt = 0; mt < 4; mt++)
        #pragma unroll
        for (int nt = 0; nt < 4; nt++) {
            int r0 = m0 + wm + mt*16 + gid;
            int cc = n0 + wn + nt*8 + ctg*2;
            float2 v0 = make_float2(acc[mt][nt][0], acc[mt][nt][1]);
            float2 v1 = make_float2(acc[mt][nt][2], acc[mt][nt][3]);
            if (MODE == 0) {
                const float* bp = (cc < 512) ? (bias + cc)
                                : (cc < 1024) ? (bias2 + cc - 512) : (bias3 + cc - 1024);
                float2 bb = *(const float2*)bp;
                v0.x += bb.x; v0.y += bb.y; v1.x += bb.x; v1.y += bb.y;
            }
            if (MODE == 1) {
                float2 bb = *(const float2*)(bias + cc);
                v0.x += bb.x; v0.y += bb.y; v1.x += bb.x; v1.y += bb.y;
            }
            if (MODE == 1 || MODE == 4) {
                float2 ra = *(const float2*)(Res + (size_t)r0*N + cc);
                float2 rb = *(const float2*)(Res + (size_t)(r0+8)*N + cc);
                v0.x += ra.x; v0.y += ra.y; v1.x += rb.x; v1.y += rb.y;
            }
            *(float2*)(C + (size_t)r0*N + cc) = v0;
            *(float2*)(C + (size_t)(r0+8)*N + cc) = v1;
        }
}

// ---------------- fused gate+value FFN GEMM ----------------
#define FT_BG 10240
#define FT_BV 15360

__device__ __forceinline__ void load_stage_ffn(uint32_t sb,
        const __half* A, const __half* Bg, const __half* Bv, int K, int kof, int tid) {
    #pragma unroll
    for (int i = 0; i < 2; i++) {
        int e = tid + i*256;
        int row = e >> 2, seg = e & 3;
        uint32_t off = (uint32_t)(row*80 + seg*16);
        cp16(sb + off, A + (size_t)row*K + kof + seg*8);
    }
    {
        int row = tid >> 2, seg = tid & 3;
        uint32_t off = (uint32_t)(row*80 + seg*16);
        size_t g = (size_t)row*K + kof + seg*8;
        cp16(sb + FT_BG + off, Bg + g);
        cp16(sb + FT_BV + off, Bv + g);
    }
}

__global__ void __launch_bounds__(256, 2)
hgemm_ffn(const __half* __restrict__ A, const __half* __restrict__ Bg,
          const __half* __restrict__ Bv, __half* __restrict__ Out,
          int M, int N, int K) {
    extern __shared__ char dsm[];
    uint32_t sb = smem_to_u32(dsm);
    int tid = threadIdx.x, lane = tid & 31, wid = tid >> 5;
    int m0 = blockIdx.x * 128, n0 = blockIdx.y * 64;
    int wm = (wid & 1) * 64, wn = (wid >> 1) * 16;
    const __half* Ab  = A  + (size_t)m0*K;
    const __half* Bgb = Bg + (size_t)n0*K;
    const __half* Bvb = Bv + (size_t)n0*K;
    int NC = K >> 5;

    load_stage_ffn(sb,             Ab, Bgb, Bvb, K, 0,  tid); CP_COMMIT();
    load_stage_ffn(sb + STAGE_B,   Ab, Bgb, Bvb, K, 32, tid); CP_COMMIT();
    load_stage_ffn(sb + 2*STAGE_B, Ab, Bgb, Bvb, K, 64, tid); CP_COMMIT();

    float ag[4][2][4], av[4][2][4];
    #pragma unroll
    for (int a = 0; a < 4; a++)
        #pragma unroll
        for (int b = 0; b < 2; b++)
            #pragma unroll
            for (int c = 0; c < 4; c++) { ag[a][b][c] = 0.f; av[a][b][c] = 0.f; }

    const int a_row = lane & 15;
    const int a_k   = (lane >> 4) * 8;
    const int b_row = (lane & 7) + ((lane >> 4) << 3);
    const int b_k   = ((lane >> 3) & 1) * 8;

    for (int i = 0; i < NC; i++) {
        CP_WAIT2();
        __syncthreads();
        if (i + 3 < NC)
            load_stage_ffn(sb + (uint32_t)((i+3) & 3)*STAGE_B, Ab, Bgb, Bvb, K, (i+3)*32, tid);
        CP_COMMIT();
        uint32_t st = sb + (uint32_t)(i & 3)*STAGE_B;
        #pragma unroll
        for (int kk = 0; kk < 32; kk += 16) {
            uint32_t a4[4][4], bg[4], bv2[4];
            #pragma unroll
            for (int mt = 0; mt < 4; mt++) {
                uint32_t ad = st + (uint32_t)((wm + mt*16 + a_row)*80 + (kk + a_k)*2);
                LDSM4(a4[mt], ad);
            }
            uint32_t brow = (uint32_t)((wn + b_row)*80 + (kk + b_k)*2);
            LDSM4(bg,  st + FT_BG + brow);
            LDSM4(bv2, st + FT_BV + brow);
            #pragma unroll
            for (int mt = 0; mt < 4; mt++) {
                HMMA(ag[mt][0], a4[mt], bg[0],  bg[1]);
                HMMA(ag[mt][1], a4[mt], bg[2],  bg[3]);
                HMMA(av[mt][0], a4[mt], bv2[0], bv2[1]);
                HMMA(av[mt][1], a4[mt], bv2[2], bv2[3]);
            }
        }
    }

    int gid = lane >> 2, ctg = lane & 3;
    #pragma unroll
    for (int mt = 0; mt < 4; mt++)
        #pragma unroll
        for (int nt = 0; nt < 2; nt++) {
            int r0 = m0 + wm + mt*16 + gid;
            int cc = n0 + wn + nt*8 + ctg*2;
            float g0 = ag[mt][nt][0], g1 = ag[mt][nt][1];
            float g2 = ag[mt][nt][2], g3 = ag[mt][nt][3];
            float s0 = g0/(1.f+__expf(-g0))*av[mt][nt][0];
            float s1 = g1/(1.f+__expf(-g1))*av[mt][nt][1];
            float s2 = g2/(1.f+__expf(-g2))*av[mt][nt][2];
            float s3 = g3/(1.f+__expf(-g3))*av[mt][nt][3];
            *(__half2*)(Out + (size_t)r0*N + cc)     = __floats2half2_rn(s0, s1);
            *(__half2*)(Out + (size_t)(r0+8)*N + cc) = __floats2half2_rn(s2, s3);
        }
}

// ---------------- context projection ----------------
__global__ void ctx_kernel(const float* __restrict__ fast, const float* __restrict__ slow,
                           const float* __restrict__ W, const float* __restrict__ bias,
                           float* __restrict__ out) {
    int b = blockIdx.x, d = threadIdx.x;
    float acc = bias[d];
    const float* fb = fast + b*DD;
    const float* sb = slow + b*DD;
    for (int k = 0; k < DD; k++) acc += fb[k] * W[(size_t)k*DD + d];
    for (int k = 0; k < DD; k++) acc += sb[k] * W[(size_t)(k+DD)*DD + d];
    out[b*DD + d] = acc;
}

// ---------------- embedding + context + engram + fused layer-0 rmsnorm ----------------
__global__ void embed_fused_kernel(const int* __restrict__ tokens, const int* __restrict__ prev,
                                   const float* __restrict__ embed, const float* __restrict__ ctxadd,
                                   const float* __restrict__ etab, const float* __restrict__ egate,
                                   const float* __restrict__ ln1,
                                   float* __restrict__ X, __half* __restrict__ H) {
    int row = blockIdx.x;
    int b = row >> 9, t = row & 511;
    __shared__ unsigned int sidx[EH];
    int tid = threadIdx.x;
    if (tid < EH) {
        unsigned int xseed = 131u + (unsigned)tid * 1009u;
        unsigned int hs = 0u;
        #pragma unroll
        for (int i = 0; i < 4; i++) {
            unsigned int p = xseed; xseed = xseed * 31u + 1u;
            int pos = t - i;
            unsigned int tok = (pos >= 0) ? (unsigned)tokens[b*TT + pos]
                                          : (unsigned)prev[b*OVL + OVL + pos];
            hs += tok * p;
        }
        sidx[tid] = hs % MM;
    }
    __syncthreads();
    int d0 = tid * 4;
    int eh = tid >> 5;
    int jj = d0 & 127;
    int tok = tokens[b*TT + t];
    float4 ev = *(const float4*)(embed + (size_t)tok*DD + d0);
    float4 cv = *(const float4*)(ctxadd + b*DD + d0);
    float4 rv = *(const float4*)(etab + ((size_t)sidx[eh]*EH + eh)*EHD + jj);
    float4 gv = *(const float4*)(egate + eh*EHD + jj);
    float4 o;
    o.x = ev.x + cv.x + rv.x * (1.f/(1.f+__expf(-gv.x)));
    o.y = ev.y + cv.y + rv.y * (1.f/(1.f+__expf(-gv.y)));
    o.z = ev.z + cv.z + rv.z * (1.f/(1.f+__expf(-gv.z)));
    o.w = ev.w + cv.w + rv.w * (1.f/(1.f+__expf(-gv.w)));
    *(float4*)(X + (size_t)row*DD + d0) = o;
    float ss = blockReduceSum128(o.x*o.x + o.y*o.y + o.z*o.z + o.w*o.w);
    float inv = rsqrtf(ss * (1.f/DD) + 1e-6f);
    float4 sc = ((const float4*)ln1)[tid];
    size_t off = (size_t)row*DD + d0;
    *(__half2*)(H + off)     = __floats2half2_rn(o.x*inv*sc.x, o.y*inv*sc.y);
    *(__half2*)(H + off + 2) = __floats2half2_rn(o.z*inv*sc.z, o.w*inv*sc.w);
}

// ---------------- RMSNorm -> fp16 plane ----------------
__global__ void rmsnorm_half_kernel(const float* __restrict__ X, const float* __restrict__ scale,
                                    __half* __restrict__ H) {
    int row = blockIdx.x;
    float4 v = ((const float4*)(X + (size_t)row*DD))[threadIdx.x];
    float ss = v.x*v.x + v.y*v.y + v.z*v.z + v.w*v.w;
    ss = blockReduceSum128(ss);
    float inv = rsqrtf(ss * (1.f/DD) + 1e-6f);
    float4 sc = ((const float4*)scale)[threadIdx.x];
    size_t off = (size_t)row*DD + threadIdx.x*4;
    *(__half2*)(H + off)     = __floats2half2_rn(v.x*inv*sc.x, v.y*inv*sc.y);
    *(__half2*)(H + off + 2) = __floats2half2_rn(v.z*inv*sc.z, v.w*inv*sc.w);
}

// ---------------- final RMSNorm (fp32 out) ----------------
__global__ void rmsnorm_kernel(const float* __restrict__ X, const float* __restrict__ scale,
                               float* __restrict__ Out) {
    int row = blockIdx.x;
    float4 v = ((const float4*)(X + (size_t)row*DD))[threadIdx.x];
    float ss = v.x*v.x + v.y*v.y + v.z*v.z + v.w*v.w;
    ss = blockReduceSum128(ss);
    float inv = rsqrtf(ss * (1.f/DD) + 1e-6f);
    float4 sc = ((const float4*)scale)[threadIdx.x];
    float4 o;
    o.x = v.x*inv*sc.x; o.y = v.y*inv*sc.y; o.z = v.z*inv*sc.z; o.w = v.w*inv*sc.w;
    ((float4*)(Out + (size_t)row*DD))[threadIdx.x] = o;
}

// ---------------- rope helper ----------------
__device__ __forceinline__ float4 rope4(float4 v, int t, int dv) {
    const float c = 9.210340371976184f / 64.f;
    float inv0 = __expf(-(float)dv * c);
    float inv1 = __expf(-(float)(dv+2) * c);
    float s0, c0, s1, c1;
    __sincosf((float)t * inv0, &s0, &c0);
    __sincosf((float)t * inv1, &s1, &c1);
    float4 r;
    r.x = v.x*c0 - v.y*s0;  r.y = v.x*s0 + v.y*c0;
    r.z = v.z*c1 - v.w*s1;  r.w = v.z*s1 + v.w*c1;
    return r;
}

// ---------------- HMMA causal flash attention: BQ=128, BK=64, HD=64, 256 threads ----------------
// each warp owns a full 16-row x 64-col stripe: softmax is warp-local, no cross-warp combine.
#define FPAD 72
#define FSMEM ((128 + 64 + 64)*FPAD*2)   // Qh 128x72 + Kh 64x72 + Vt 64x72 halves = 36864

__global__ void __launch_bounds__(256, 2) flash_kernel(const float* __restrict__ QKV,
        __half* __restrict__ Oh) {
    extern __shared__ char fsm[];
    __half* Qh = (__half*)fsm;
    __half* Kh = Qh + 128*FPAD;
    __half* Vt = Kh + 64*FPAD;
    uint32_t uq = smem_to_u32(Qh);
    uint32_t uk = smem_to_u32(Kh);
    uint32_t uv = smem_to_u32(Vt);

    int bh = blockIdx.y;
    int b = bh >> 3, h = bh & 7;
    int q0 = blockIdx.x * 128;
    int tid = threadIdx.x, lane = tid & 31, wid = tid >> 5;   // warp = m-stripe
    int gid = lane >> 2, ctg = lane & 3;
    const int a_row = lane & 15;
    const int a_k   = (lane >> 4) * 8;
    const int b_row = (lane & 7) + ((lane >> 4) << 3);
    const int b_k   = ((lane >> 3) & 1) * 8;
    size_t base = ((size_t)b*TT)*1536 + h*HD;
    const float scl = 0.125f;

    // load Q (rope, fp16): 128 rows
    for (int i = tid; i < 128*16; i += 256) {
        int r = i >> 4, dv = (i & 15) * 4;
        float4 v = rope4(*(const float4*)(QKV + base + (size_t)(q0 + r)*1536 + dv), q0 + r, dv);
        __half2* dst = (__half2*)(Qh + r*FPAD + dv);
        dst[0] = __floats2half2_rn(v.x, v.y);
        dst[1] = __floats2half2_rn(v.z, v.w);
    }

    float m0 = -1e30f, m1 = -1e30f, l0 = 0.f, l1 = 0.f;
    float oacc[8][4];
    #pragma unroll
    for (int i = 0; i < 8; i++)
        #pragma unroll
        for (int j = 0; j < 4; j++) oacc[i][j] = 0.f;

    int row0 = q0 + wid*16 + gid;
    int nkt = (q0 >> 6) + 2;
    for (int kt = 0; kt < nkt; kt++) {
        int k0 = kt * 64;
        __syncthreads();
        for (int i = tid; i < 64*16; i += 256) {
            int r = i >> 4, dv = (i & 15)*4;
            size_t g = base + (size_t)(k0 + r)*1536 + dv;
            float4 kv = rope4(*(const float4*)(QKV + g + 512), k0 + r, dv);
            __half2* kd = (__half2*)(Kh + r*FPAD + dv);
            kd[0] = __floats2half2_rn(kv.x, kv.y);
            kd[1] = __floats2half2_rn(kv.z, kv.w);
            float4 vv = *(const float4*)(QKV + g + 1024);
            Vt[(dv+0)*FPAD + r] = __float2half_rn(vv.x);
            Vt[(dv+1)*FPAD + r] = __float2half_rn(vv.y);
            Vt[(dv+2)*FPAD + r] = __float2half_rn(vv.z);
            Vt[(dv+3)*FPAD + r] = __float2half_rn(vv.w);
        }
        __syncthreads();
        // S (16x64) = Q[wid] @ K^T
        float sacc[8][4];
        #pragma unroll
        for (int nt = 0; nt < 8; nt++)
            #pragma unroll
            for (int j = 0; j < 4; j++) sacc[nt][j] = 0.f;
        #pragma unroll
        for (int kk = 0; kk < 64; kk += 16) {
            uint32_t af[4], bf[4][4];
            LDSM4(af, uq + (uint32_t)((wid*16 + a_row)*FPAD + kk + a_k)*2);
            #pragma unroll
            for (int np = 0; np < 4; np++)
                LDSM4(bf[np], uk + (uint32_t)((np*16 + b_row)*FPAD + kk + b_k)*2);
            #pragma unroll
            for (int np = 0; np < 4; np++) {
                HMMA(sacc[2*np],   af, bf[np][0], bf[np][1]);
                HMMA(sacc[2*np+1], af, bf[np][2], bf[np][3]);
            }
        }
        // scale + causal mask (only near-diagonal tiles need it)
        if (kt >= nkt - 2) {
            #pragma unroll
            for (int nt = 0; nt < 8; nt++) {
                int col = k0 + nt*8 + ctg*2;
                #pragma unroll
                for (int j = 0; j < 4; j++) {
                    int cc = col + (j & 1);
                    int rr = row0 + ((j >> 1) << 3);
                    sacc[nt][j] = (cc <= rr) ? sacc[nt][j]*scl : -1e9f;
                }
            }
        } else {
            #pragma unroll
            for (int nt = 0; nt < 8; nt++)
                #pragma unroll
                for (int j = 0; j < 4; j++) sacc[nt][j] *= scl;
        }
        // warp-local row max / sum (rows gid and gid+8)
        float rm0 = -1e30f, rm1 = -1e30f;
        #pragma unroll
        for (int nt = 0; nt < 8; nt++) {
            rm0 = fmaxf(rm0, fmaxf(sacc[nt][0], sacc[nt][1]));
            rm1 = fmaxf(rm1, fmaxf(sacc[nt][2], sacc[nt][3]));
        }
        rm0 = fmaxf(rm0, __shfl_xor_sync(0xffffffffu, rm0, 1));
        rm0 = fmaxf(rm0, __shfl_xor_sync(0xffffffffu, rm0, 2));
        rm1 = fmaxf(rm1, __shfl_xor_sync(0xffffffffu, rm1, 1));
        rm1 = fmaxf(rm1, __shfl_xor_sync(0xffffffffu, rm1, 2));
        float mn0 = fmaxf(m0, rm0), mn1 = fmaxf(m1, rm1);
        float c0 = __expf(m0 - mn0), c1 = __expf(m1 - mn1);
        m0 = mn0; m1 = mn1;
        float rs0 = 0.f, rs1 = 0.f;
        #pragma unroll
        for (int nt = 0; nt < 8; nt++) {
            sacc[nt][0] = __expf(sacc[nt][0] - mn0); rs0 += sacc[nt][0];
            sacc[nt][1] = __expf(sacc[nt][1] - mn0); rs0 += sacc[nt][1];
            sacc[nt][2] = __expf(sacc[nt][2] - mn1); rs1 += sacc[nt][2];
            sacc[nt][3] = __expf(sacc[nt][3] - mn1); rs1 += sacc[nt][3];
        }
        rs0 += __shfl_xor_sync(0xffffffffu, rs0, 1);
        rs0 += __shfl_xor_sync(0xffffffffu, rs0, 2);
        rs1 += __shfl_xor_sync(0xffffffffu, rs1, 1);
        rs1 += __shfl_xor_sync(0xffffffffu, rs1, 2);
        l0 = l0*c0 + rs0;
        l1 = l1*c1 + rs1;
        #pragma unroll
        for (int nh = 0; nh < 8; nh++) {
            oacc[nh][0] *= c0; oacc[nh][1] *= c0;
            oacc[nh][2] *= c1; oacc[nh][3] *= c1;
        }
        // PV: A = P (m16 k64), B = Vt
        #pragma unroll
        for (int g = 0; g < 4; g++) {
            uint32_t pf[4];
            pf[0] = f22u(sacc[2*g][0],   sacc[2*g][1]);
            pf[1] = f22u(sacc[2*g][2],   sacc[2*g][3]);
            pf[2] = f22u(sacc[2*g+1][0], sacc[2*g+1][1]);
            pf[3] = f22u(sacc[2*g+1][2], sacc[2*g+1][3]);
            int kof = g*16;
            #pragma unroll
            for (int nh = 0; nh < 4; nh++) {
                uint32_t bf2[4];
                LDSM4(bf2, uv + (uint32_t)((nh*16 + b_row)*FPAD + kof + b_k)*2);
                HMMA(oacc[2*nh],   pf, bf2[0], bf2[1]);
                HMMA(oacc[2*nh+1], pf, bf2[2], bf2[3]);
            }
        }
    }
    // epilogue: warp-owned rows, no combine
    float inv0 = 1.f / l0, inv1 = 1.f / l1;
    #pragma unroll
    for (int nh = 0; nh < 8; nh++) {
        int c = nh*8 + ctg*2;
        size_t r0 = (size_t)(b*TT + row0)*DD + h*HD + c;
        size_t r1 = (size_t)(b*TT + row0 + 8)*DD + h*HD + c;
        *(__half2*)(Oh + r0) = __floats2half2_rn(oacc[nh][0]*inv0, oacc[nh][1]*inv0);
        *(__half2*)(Oh + r1) = __floats2half2_rn(oacc[nh][2]*inv1, oacc[nh][3]*inv1);
    }
}

// ---------------- salience logits ----------------
__global__ void logits_kernel(const float* __restrict__ X, const float* __restrict__ sal_W,
                              const float* __restrict__ sal_b, const float* __restrict__ temp,
                              float* __restrict__ out) {
    int row = blockIdx.x;
    int e = threadIdx.x >> 5, lane = threadIdx.x & 31;
    const float* xr = X + (size_t)row*DD;
    float acc = 0.f;
    for (int d = lane; d < DD; d += 32)
        acc += xr[d] * sal_W[d*EH + e];
    acc = warpReduceSum(acc);
    if (lane == 0) {
        float tp = log1pf(expf(temp[e])) + 0.3f;
        out[(size_t)row*EH + e] = (acc + sal_b[e]) / tp;
    }
}

// ---------------- masked softmax pool ----------------
__global__ void pool_kernel(const int* __restrict__ tokens, const float* __restrict__ logits,
                            const float* __restrict__ X, const float* __restrict__ gate_W,
                            const float* __restrict__ gate_b,
                            float* __restrict__ wv_out, float* __restrict__ u_out) {
    int b = blockIdx.x >> 2, e = blockIdx.x & 3;
    int tid = threadIdx.x;
    __shared__ float ws[TT];
    float lg4[4]; int mv4[4];
    float lmax = -1e30f; float lvalid = 0.f;
    #pragma unroll
    for (int p = 0; p < 4; p++) {
        int t = tid + p*128;
        int mv = (tokens[b*TT + t] != 0);
        float lgv = logits[((size_t)b*TT + t)*EH + e];
        float sf = mv ? lgv : -1e9f;
        lg4[p] = sf; mv4[p] = mv;
        lmax = fmaxf(lmax, sf);
        lvalid += (float)mv;
    }
    float mx = blockReduceMax128(lmax);
    float lsum = 0.f;
    #pragma unroll
    for (int p = 0; p < 4; p++) {
        int t = tid + p*128;
        float ev = mv4[p] ? expf(lg4[p] - mx) : 0.f;
        ws[t] = ev;
        lsum += ev;
    }
    float ssum = blockReduceSum128(lsum);
    float nvalid = blockReduceSum128(lvalid);
    float wsc = 1.f / (ssum + 1e-6f);
    __syncthreads();
    float acc = 0.f;
    const float* xb = X + ((size_t)b*TT)*DD + e*EHD + tid;
    for (int t = 0; t < TT; t++)
        acc += ws[t] * xb[(size_t)t*DD];
    acc *= wsc;
    wv_out[b*DD + e*EHD + tid] = acc;
    float gsum = blockReduceSum128(acc * gate_W[tid]);
    if (tid == 0) {
        float gl = gsum + gate_b[0];
        float u = (nvalid > 0.f) ? 1.f/(1.f+expf(-gl)) : 0.f;
        u_out[b*EH + e] = u;
    }
}

// ---------------- fast/slow state update ----------------
__global__ void update_kernel(const float* __restrict__ wv, const float* __restrict__ u,
                              const float* __restrict__ sal_rms,
                              const float* __restrict__ fast, const float* __restrict__ slow,
                              float* __restrict__ out_fast, float* __restrict__ out_slow) {
    int b = blockIdx.x, tid = threadIdx.x;
    float4 v = ((const float4*)(wv + b*DD))[tid];
    float ss = blockReduceSum128(v.x*v.x + v.y*v.y + v.z*v.z + v.w*v.w);
    float inv = rsqrtf(ss * (1.f/DD) + 1e-6f);
    float4 sr = ((const float4*)sal_rms)[tid];
    int e = tid >> 5;
    float uu = u[b*EH + e];
    float4 f = ((const float4*)(fast + b*DD))[tid];
    float4 s = ((const float4*)(slow + b*DD))[tid];
    float4 wn;
    wn.x = v.x*inv*sr.x; wn.y = v.y*inv*sr.y; wn.z = v.z*inv*sr.z; wn.w = v.w*inv*sr.w;
    float4 nf, ns;
    nf.x = (1.f-uu)*f.x + uu*wn.x;  nf.y = (1.f-uu)*f.y + uu*wn.y;
    nf.z = (1.f-uu)*f.z + uu*wn.z;  nf.w = (1.f-uu)*f.w + uu*wn.w;
    float ud = 0.1f*uu;
    ns.x = (1.f-ud)*s.x + ud*wn.x;  ns.y = (1.f-ud)*s.y + ud*wn.y;
    ns.z = (1.f-ud)*s.z + ud*wn.z;  ns.w = (1.f-ud)*s.w + ud*wn.w;
    ((float4*)(out_fast + b*DD))[tid] = nf;
    ((float4*)(out_slow + b*DD))[tid] = ns;
}

// ---------------- launch ----------------
extern "C" void kernel_launch(void* const* d_in, const int* in_sizes, int n_in,
                              void* d_out, int out_size) {
    const int*   tokens = (const int*)  d_in[0];
    const int*   prev   = (const int*)  d_in[1];
    const float* fast   = (const float*)d_in[2];
    const float* slow   = (const float*)d_in[3];
    const float* embed  = (const float*)d_in[4];
    const float* ctx_W  = (const float*)d_in[5];
    const float* ctx_b  = (const float*)d_in[6];
    const float* etab   = (const float*)d_in[7];
    const float* egate  = (const float*)d_in[8];
    const float* ln1    = (const float*)d_in[9];
    const float* Wq     = (const float*)d_in[10];
    const float* bq     = (const float*)d_in[11];
    const float* Wk     = (const float*)d_in[12];
    const float* bk     = (const float*)d_in[13];
    const float* Wv     = (const float*)d_in[14];
    const float* bv     = (const float*)d_in[15];
    const float* Wo     = (const float*)d_in[16];
    const float* bo     = (const float*)d_in[17];
    const float* ln2    = (const float*)d_in[18];
    const float* W1     = (const float*)d_in[19];
    const float* W2     = (const float*)d_in[20];
    const float* ln_f   = (const float*)d_in[21];
    const float* sal_W  = (const float*)d_in[22];
    const float* sal_b  = (const float*)d_in[23];
    const float* temp   = (const float*)d_in[24];
    const float* gate_W = (const float*)d_in[25];
    const float* gate_b = (const float*)d_in[26];
    const float* sal_rms= (const float*)d_in[27];
    float* out = (float*)d_out;

    float *gx, *gqkv, *gctx, *glog, *gwv, *gu;
    __half *nx, *at, *ff;
    __half *wA, *w1, *w2;
    cudaGetSymbolAddress((void**)&gx,   g_x);
    cudaGetSymbolAddress((void**)&gqkv, g_qkv);
    cudaGetSymbolAddress((void**)&gctx, g_ctx);
    cudaGetSymbolAddress((void**)&glog, g_logits);
    cudaGetSymbolAddress((void**)&gwv,  g_wv);
    cudaGetSymbolAddress((void**)&gu,   g_u);
    cudaGetSymbolAddress((void**)&nx,   g_nx);
    cudaGetSymbolAddress((void**)&at,   g_at);
    cudaGetSymbolAddress((void**)&ff,   g_ff);
    cudaGetSymbolAddress((void**)&wA,   g_wqkvo);
    cudaGetSymbolAddress((void**)&w1,   g_w1);
    cudaGetSymbolAddress((void**)&w2,   g_w2);

    cudaFuncSetAttribute(hgemm<0>, cudaFuncAttributeMaxDynamicSharedMemorySize, HSMEM);
    cudaFuncSetAttribute(hgemm<1>, cudaFuncAttributeMaxDynamicSharedMemorySize, HSMEM);
    cudaFuncSetAttribute(hgemm<4>, cudaFuncAttributeMaxDynamicSharedMemorySize, HSMEM);
    cudaFuncSetAttribute(hgemm_ffn, cudaFuncAttributeMaxDynamicSharedMemorySize, HSMEM);
    cudaFuncSetAttribute(flash_kernel, cudaFuncAttributeMaxDynamicSharedMemorySize, FSMEM);

    dim3 tb(32, 8);
    dim3 gD(NTOK/128, DD/128);
    dim3 gQKV(NTOK/128, (3*DD)/128);
    dim3 gFF(NTOK/128, FF/64);

    // ncu captures launch #4 -> fused-QKV hgemm.
    tsplit4_kernel<<<dim3(DD/32, DD/32, 4*LL), tb>>>(Wq, Wk, Wv, Wo, wA);                // 1
    ctx_kernel<<<BB, 512>>>(fast, slow, ctx_W, ctx_b, gctx);                             // 2
    embed_fused_kernel<<<NTOK, 128>>>(tokens, prev, embed, gctx, etab, egate, ln1,
                                      gx, nx);                                           // 3

    for (int l = 0; l < LL; l++) {
        size_t wo  = (size_t)l*4*DD*DD;
        size_t w1o = (size_t)l*2*FF*DD;
        size_t w2o = (size_t)l*DD*FF;
        if (l > 0)
            rmsnorm_half_kernel<<<NTOK, 128>>>(gx, ln1 + l*DD, nx);
        hgemm<0><<<gQKV, 256, HSMEM>>>(nx, wA + wo,
                                       bq + l*DD, bk + l*DD, bv + l*DD,
                                       nullptr, gqkv, NTOK, 3*DD, DD);
        if (l == 0) {
            tsplitW1_kernel<<<dim3(FF/32, DD/32, 2*LL), tb>>>(W1, w1);
            tsplit_kernel<<<dim3(DD/32, FF/32, LL), tb>>>(W2, DD, (size_t)FF*DD, w2, (size_t)DD*FF, FF);
        }
        flash_kernel<<<dim3(TT/128, BB*HH), 256, FSMEM>>>(gqkv, at);
        hgemm<1><<<gD, 256, HSMEM>>>(at, wA + wo + (size_t)1536*DD,
                                     bo + l*DD, nullptr, nullptr, gx,
                                     gx, NTOK, DD, DD);
        rmsnorm_half_kernel<<<NTOK, 128>>>(gx, ln2 + l*DD, nx);
        hgemm_ffn<<<gFF, 256, HSMEM>>>(nx, w1 + w1o, w1 + w1o + (size_t)FF*DD,
                                       ff, NTOK, FF, DD);
        hgemm<4><<<gD, 256, HSMEM>>>(ff, w2 + w2o,
                                     nullptr, nullptr, nullptr, gx,
                                     gx, NTOK, DD, FF);
    }
    rmsnorm_kernel<<<NTOK, 128>>>(gx, ln_f, out);
    logits_kernel<<<NTOK, 128>>>(out, sal_W, sal_b, temp, glog);
    pool_kernel<<<BB*EH, 128>>>(tokens, glog, out, gate_W, gate_b, gwv, gu);
    update_kernel<<<BB, 128>>>(gwv, gu, sal_rms, fast, slow,
                               out + (size_t)NTOK*DD,
                               out + (size_t)NTOK*DD + BB*DD);
}

// round 13
// speedup vs baseline: 1.3462x; 1.0169x over previous
#include <cuda_runtime.h>
#include <cuda_fp16.h>
#include <math.h>
#include <stdint.h>

// ---------------- problem constants ----------------
#define BB 32
#define TT 512
#define DD 512
#define LL 6
#define HH 8
#define HD 64
#define FF 2048      // 4*D
#define EH 4
#define EHD 128
#define MM 100000u
#define OVL 64
#define NTOK (BB*TT)   // 16384

// ---------------- scratch ----------------
__device__ float g_x[NTOK*DD];
__device__ float g_ctx[BB*DD];
__device__ float g_logits[NTOK*EH];
__device__ float g_wv[BB*DD];
__device__ float g_u[BB*EH];
// fp16 activations
__device__ __half g_qkv[(size_t)NTOK*3*DD];
__device__ __half g_nx[NTOK*DD];
__device__ __half g_at[NTOK*DD];
__device__ __half g_ff[(size_t)NTOK*FF];
// transposed fp16 weights: [N][K]
__device__ __half g_wqkvo[(size_t)LL*4*DD*DD];
__device__ __half g_w1[(size_t)LL*2*FF*DD];
__device__ __half g_w2[(size_t)LL*DD*FF];

// ---------------- PTX helpers ----------------
__device__ __forceinline__ uint32_t smem_to_u32(const void* p) {
    uint32_t a;
    asm("{ .reg .u64 t; cvta.to.shared.u64 t, %1; cvt.u32.u64 %0, t; }" : "=r"(a) : "l"(p));
    return a;
}
__device__ __forceinline__ void cp16(uint32_t dst, const void* src) {
    asm volatile("cp.async.cg.shared.global [%0], [%1], 16;" :: "r"(dst), "l"(src));
}
#define CP_COMMIT() asm volatile("cp.async.commit_group;" ::: "memory")
#define CP_WAIT2()  asm volatile("cp.async.wait_group 2;" ::: "memory")

#define LDSM4(r, addr) \
    asm volatile("ldmatrix.sync.aligned.m8n8.x4.shared.b16 {%0,%1,%2,%3}, [%4];" \
        : "=r"((r)[0]), "=r"((r)[1]), "=r"((r)[2]), "=r"((r)[3]) : "r"(addr))

#define HMMA(c, a, b0, b1) \
    asm volatile("mma.sync.aligned.m16n8k16.row.col.f32.f16.f16.f32 " \
        "{%0,%1,%2,%3}, {%4,%5,%6,%7}, {%8,%9}, {%0,%1,%2,%3};" \
        : "+f"((c)[0]), "+f"((c)[1]), "+f"((c)[2]), "+f"((c)[3]) \
        : "r"((a)[0]), "r"((a)[1]), "r"((a)[2]), "r"((a)[3]), "r"(b0), "r"(b1))

__device__ __forceinline__ uint32_t f22u(float a, float b) {
    __half2 h = __floats2half2_rn(a, b);
    return *(uint32_t*)&h;
}

// ---------------- reduction helpers ----------------
__device__ __forceinline__ float warpReduceSum(float v) {
    #pragma unroll
    for (int o = 16; o; o >>= 1) v += __shfl_xor_sync(0xffffffffu, v, o);
    return v;
}
__device__ __forceinline__ float warpReduceMax(float v) {
    #pragma unroll
    for (int o = 16; o; o >>= 1) v = fmaxf(v, __shfl_xor_sync(0xffffffffu, v, o));
    return v;
}
__device__ __forceinline__ float blockReduceSum128(float v) {
    __shared__ float sm[4];
    __syncthreads();
    v = warpReduceSum(v);
    if ((threadIdx.x & 31) == 0) sm[threadIdx.x >> 5] = v;
    __syncthreads();
    return sm[0] + sm[1] + sm[2] + sm[3];
}
__device__ __forceinline__ float blockReduceMax128(float v) {
    __shared__ float sm[4];
    __syncthreads();
    v = warpReduceMax(v);
    if ((threadIdx.x & 31) == 0) sm[threadIdx.x >> 5] = v;
    __syncthreads();
    return fmaxf(fmaxf(sm[0], sm[1]), fmaxf(sm[2], sm[3]));
}

// ---------------- 4-source transpose to fp16 (Wq/Wk/Wv/Wo stacked) ----------------
__global__ void tsplit4_kernel(const float* __restrict__ s0, const float* __restrict__ s1,
                               const float* __restrict__ s2, const float* __restrict__ s3,
                               __half* __restrict__ dst) {
    __shared__ float t[32][33];
    int z = blockIdx.z;
    int l = z >> 2, sel = z & 3;
    const float* S = (sel == 0 ? s0 : sel == 1 ? s1 : sel == 2 ? s2 : s3) + (size_t)l*DD*DD;
    __half* Hd = dst + (size_t)z*DD*DD;
    int n0 = blockIdx.x*32, k0 = blockIdx.y*32;
    int x = threadIdx.x, y = threadIdx.y;
    #pragma unroll
    for (int i = 0; i < 32; i += 8) t[y+i][x] = S[(size_t)(k0+y+i)*DD + n0+x];
    __syncthreads();
    #pragma unroll
    for (int i = 0; i < 32; i += 8)
        Hd[(size_t)(n0+y+i)*DD + k0+x] = __float2half_rn(t[x][y+i]);
}

// ---------------- generic transpose to fp16 ----------------
__global__ void tsplit_kernel(const float* __restrict__ src, int ldsrc, size_t srcStride,
                              __half* __restrict__ dst, size_t dstStride, int K) {
    __shared__ float t[32][33];
    int l = blockIdx.z;
    const float* S = src + (size_t)l*srcStride;
    __half* Hd = dst + (size_t)l*dstStride;
    int n0 = blockIdx.x*32, k0 = blockIdx.y*32;
    int x = threadIdx.x, y = threadIdx.y;
    #pragma unroll
    for (int i = 0; i < 32; i += 8) t[y+i][x] = S[(size_t)(k0+y+i)*ldsrc + n0+x];
    __syncthreads();
    #pragma unroll
    for (int i = 0; i < 32; i += 8)
        Hd[(size_t)(n0+y+i)*K + k0+x] = __float2half_rn(t[x][y+i]);
}

// ---------------- W1 transpose to fp16 ----------------
__global__ void tsplitW1_kernel(const float* __restrict__ W1, __half* __restrict__ dst) {
    __shared__ float t[32][33];
    int z = blockIdx.z;
    int l = z >> 1, half = z & 1;
    const float* S = W1 + (size_t)l*DD*2*FF + (size_t)half*FF;
    __half* Hd = dst + (size_t)l*2*FF*DD + (size_t)half*FF*DD;
    int n0 = blockIdx.x*32, k0 = blockIdx.y*32;
    int x = threadIdx.x, y = threadIdx.y;
    #pragma unroll
    for (int i = 0; i < 32; i += 8) t[y+i][x] = S[(size_t)(k0+y+i)*(2*FF) + n0+x];
    __syncthreads();
    #pragma unroll
    for (int i = 0; i < 32; i += 8)
        Hd[(size_t)(n0+y+i)*DD + k0+x] = __float2half_rn(t[x][y+i]);
}

// ---------------- fp16 HMMA GEMM (single pass, 4-stage cp.async) ----------------
// MODE 0: +bias3 (QKV select), fp16 out ; 1: +bias +res, fp32 out ; 4: +res, fp32 out
#define TILE_B 10240
#define STAGE_B 20480
#define HSMEM (4*STAGE_B)

__device__ __forceinline__ void load_stage(uint32_t sb,
        const __half* A, const __half* B, int K, int kof, int tid) {
    #pragma unroll
    for (int i = 0; i < 2; i++) {
        int e = tid + i*256;
        int row = e >> 2, seg = e & 3;
        uint32_t off = (uint32_t)(row*80 + seg*16);
        size_t g = (size_t)row*K + kof + seg*8;
        cp16(sb + off,          A + g);
        cp16(sb + TILE_B + off, B + g);
    }
}

template<int MODE>
__global__ void __launch_bounds__(256, 2)
hgemm(const __half* __restrict__ A, const __half* __restrict__ B,
      const float* __restrict__ bias, const float* __restrict__ bias2,
      const float* __restrict__ bias3,
      const float* __restrict__ Res,
      float* __restrict__ C, __half* __restrict__ OutH,
      int M, int N, int K) {
    extern __shared__ char dsm[];
    uint32_t sb = smem_to_u32(dsm);
    int tid = threadIdx.x, lane = tid & 31, wid = tid >> 5;
    int m0 = blockIdx.x * 128, n0 = blockIdx.y * 128;
    int wm = (wid & 1) * 64, wn = (wid >> 1) * 32;
    const __half* Ab = A + (size_t)m0*K;
    const __half* Bb = B + (size_t)n0*K;
    int NC = K >> 5;

    load_stage(sb,             Ab, Bb, K, 0,  tid); CP_COMMIT();
    load_stage(sb + STAGE_B,   Ab, Bb, K, 32, tid); CP_COMMIT();
    load_stage(sb + 2*STAGE_B, Ab, Bb, K, 64, tid); CP_COMMIT();

    float acc[4][4][4];
    #pragma unroll
    for (int a = 0; a < 4; a++)
        #pragma unroll
        for (int b = 0; b < 4; b++)
            #pragma unroll
            for (int c = 0; c < 4; c++) acc[a][b][c] = 0.f;

    const int a_row = lane & 15;
    const int a_k   = (lane >> 4) * 8;
    const int b_row = (lane & 7) + ((lane >> 4) << 3);
    const int b_k   = ((lane >> 3) & 1) * 8;

    for (int i = 0; i < NC; i++) {
        CP_WAIT2();
        __syncthreads();
        if (i + 3 < NC)
            load_stage(sb + (uint32_t)((i+3) & 3)*STAGE_B, Ab, Bb, K, (i+3)*32, tid);
        CP_COMMIT();
        uint32_t st = sb + (uint32_t)(i & 3)*STAGE_B;
        #pragma unroll
        for (int kk = 0; kk < 32; kk += 16) {
            uint32_t a4[4][4], b2[2][4];
            #pragma unroll
            for (int mt = 0; mt < 4; mt++) {
                uint32_t ad = st + (uint32_t)((wm + mt*16 + a_row)*80 + (kk + a_k)*2);
                LDSM4(a4[mt], ad);
            }
            #pragma unroll
            for (int np = 0; np < 2; np++) {
                uint32_t bd = st + TILE_B + (uint32_t)((wn + np*16 + b_row)*80 + (kk + b_k)*2);
                LDSM4(b2[np], bd);
            }
            #pragma unroll
            for (int mt = 0; mt < 4; mt++)
                #pragma unroll
                for (int nt = 0; nt < 4; nt++)
                    HMMA(acc[mt][nt], a4[mt], b2[nt>>1][(nt&1)*2], b2[nt>>1][(nt&1)*2+1]);
        }
    }

    int gid = lane >> 2, ctg = lane & 3;
    #pragma unroll
    for (int mt = 0; mt < 4; mt++)
        #pragma unroll
        for (int nt = 0; nt < 4; nt++) {
            int r0 = m0 + wm + mt*16 + gid;
            int cc = n0 + wn + nt*8 + ctg*2;
            float2 v0 = make_float2(acc[mt][nt][0], acc[mt][nt][1]);
            float2 v1 = make_float2(acc[mt][nt][2], acc[mt][nt][3]);
            if (MODE == 0) {
                const float* bp = (cc < 512) ? (bias + cc)
                                : (cc < 1024) ? (bias2 + cc - 512) : (bias3 + cc - 1024);
                float2 bb = *(const float2*)bp;
                v0.x += bb.x; v0.y += bb.y; v1.x += bb.x; v1.y += bb.y;
                *(__half2*)(OutH + (size_t)r0*N + cc)     = __floats2half2_rn(v0.x, v0.y);
                *(__half2*)(OutH + (size_t)(r0+8)*N + cc) = __floats2half2_rn(v1.x, v1.y);
            } else {
                if (MODE == 1) {
                    float2 bb = *(const float2*)(bias + cc);
                    v0.x += bb.x; v0.y += bb.y; v1.x += bb.x; v1.y += bb.y;
                }
                float2 ra = *(const float2*)(Res + (size_t)r0*N + cc);
                float2 rb = *(const float2*)(Res + (size_t)(r0+8)*N + cc);
                v0.x += ra.x; v0.y += ra.y; v1.x += rb.x; v1.y += rb.y;
                *(float2*)(C + (size_t)r0*N + cc) = v0;
                *(float2*)(C + (size_t)(r0+8)*N + cc) = v1;
            }
        }
}

// ---------------- fused gate+value FFN GEMM ----------------
#define FT_BG 10240
#define FT_BV 15360

__device__ __forceinline__ void load_stage_ffn(uint32_t sb,
        const __half* A, const __half* Bg, const __half* Bv, int K, int kof, int tid) {
    #pragma unroll
    for (int i = 0; i < 2; i++) {
        int e = tid + i*256;
        int row = e >> 2, seg = e & 3;
        uint32_t off = (uint32_t)(row*80 + seg*16);
        cp16(sb + off, A + (size_t)row*K + kof + seg*8);
    }
    {
        int row = tid >> 2, seg = tid & 3;
        uint32_t off = (uint32_t)(row*80 + seg*16);
        size_t g = (size_t)row*K + kof + seg*8;
        cp16(sb + FT_BG + off, Bg + g);
        cp16(sb + FT_BV + off, Bv + g);
    }
}

__global__ void __launch_bounds__(256, 2)
hgemm_ffn(const __half* __restrict__ A, const __half* __restrict__ Bg,
          const __half* __restrict__ Bv, __half* __restrict__ Out,
          int M, int N, int K) {
    extern __shared__ char dsm[];
    uint32_t sb = smem_to_u32(dsm);
    int tid = threadIdx.x, lane = tid & 31, wid = tid >> 5;
    int m0 = blockIdx.x * 128, n0 = blockIdx.y * 64;
    int wm = (wid & 1) * 64, wn = (wid >> 1) * 16;
    const __half* Ab  = A  + (size_t)m0*K;
    const __half* Bgb = Bg + (size_t)n0*K;
    const __half* Bvb = Bv + (size_t)n0*K;
    int NC = K >> 5;

    load_stage_ffn(sb,             Ab, Bgb, Bvb, K, 0,  tid); CP_COMMIT();
    load_stage_ffn(sb + STAGE_B,   Ab, Bgb, Bvb, K, 32, tid); CP_COMMIT();
    load_stage_ffn(sb + 2*STAGE_B, Ab, Bgb, Bvb, K, 64, tid); CP_COMMIT();

    float ag[4][2][4], av[4][2][4];
    #pragma unroll
    for (int a = 0; a < 4; a++)
        #pragma unroll
        for (int b = 0; b < 2; b++)
            #pragma unroll
            for (int c = 0; c < 4; c++) { ag[a][b][c] = 0.f; av[a][b][c] = 0.f; }

    const int a_row = lane & 15;
    const int a_k   = (lane >> 4) * 8;
    const int b_row = (lane & 7) + ((lane >> 4) << 3);
    const int b_k   = ((lane >> 3) & 1) * 8;

    for (int i = 0; i < NC; i++) {
        CP_WAIT2();
        __syncthreads();
        if (i + 3 < NC)
            load_stage_ffn(sb + (uint32_t)((i+3) & 3)*STAGE_B, Ab, Bgb, Bvb, K, (i+3)*32, tid);
        CP_COMMIT();
        uint32_t st = sb + (uint32_t)(i & 3)*STAGE_B;
        #pragma unroll
        for (int kk = 0; kk < 32; kk += 16) {
            uint32_t a4[4][4], bg[4], bv2[4];
            #pragma unroll
            for (int mt = 0; mt < 4; mt++) {
                uint32_t ad = st + (uint32_t)((wm + mt*16 + a_row)*80 + (kk + a_k)*2);
                LDSM4(a4[mt], ad);
            }
            uint32_t brow = (uint32_t)((wn + b_row)*80 + (kk + b_k)*2);
            LDSM4(bg,  st + FT_BG + brow);
            LDSM4(bv2, st + FT_BV + brow);
            #pragma unroll
            for (int mt = 0; mt < 4; mt++) {
                HMMA(ag[mt][0], a4[mt], bg[0],  bg[1]);
                HMMA(ag[mt][1], a4[mt], bg[2],  bg[3]);
                HMMA(av[mt][0], a4[mt], bv2[0], bv2[1]);
                HMMA(av[mt][1], a4[mt], bv2[2], bv2[3]);
            }
        }
    }

    int gid = lane >> 2, ctg = lane & 3;
    #pragma unroll
    for (int mt = 0; mt < 4; mt++)
        #pragma unroll
        for (int nt = 0; nt < 2; nt++) {
            int r0 = m0 + wm + mt*16 + gid;
            int cc = n0 + wn + nt*8 + ctg*2;
            float g0 = ag[mt][nt][0], g1 = ag[mt][nt][1];
            float g2 = ag[mt][nt][2], g3 = ag[mt][nt][3];
            float s0 = g0/(1.f+__expf(-g0))*av[mt][nt][0];
            float s1 = g1/(1.f+__expf(-g1))*av[mt][nt][1];
            float s2 = g2/(1.f+__expf(-g2))*av[mt][nt][2];
            float s3 = g3/(1.f+__expf(-g3))*av[mt][nt][3];
            *(__half2*)(Out + (size_t)r0*N + cc)     = __floats2half2_rn(s0, s1);
            *(__half2*)(Out + (size_t)(r0+8)*N + cc) = __floats2half2_rn(s2, s3);
        }
}

// ---------------- context projection ----------------
__global__ void ctx_kernel(const float* __restrict__ fast, const float* __restrict__ slow,
                           const float* __restrict__ W, const float* __restrict__ bias,
                           float* __restrict__ out) {
    int b = blockIdx.x, d = threadIdx.x;
    float acc = bias[d];
    const float* fb = fast + b*DD;
    const float* sb = slow + b*DD;
    for (int k = 0; k < DD; k++) acc += fb[k] * W[(size_t)k*DD + d];
    for (int k = 0; k < DD; k++) acc += sb[k] * W[(size_t)(k+DD)*DD + d];
    out[b*DD + d] = acc;
}

// ---------------- embedding + context + engram + fused layer-0 rmsnorm ----------------
__global__ void embed_fused_kernel(const int* __restrict__ tokens, const int* __restrict__ prev,
                                   const float* __restrict__ embed, const float* __restrict__ ctxadd,
                                   const float* __restrict__ etab, const float* __restrict__ egate,
                                   const float* __restrict__ ln1,
                                   float* __restrict__ X, __half* __restrict__ H) {
    int row = blockIdx.x;
    int b = row >> 9, t = row & 511;
    __shared__ unsigned int sidx[EH];
    int tid = threadIdx.x;
    if (tid < EH) {
        unsigned int xseed = 131u + (unsigned)tid * 1009u;
        unsigned int hs = 0u;
        #pragma unroll
        for (int i = 0; i < 4; i++) {
            unsigned int p = xseed; xseed = xseed * 31u + 1u;
            int pos = t - i;
            unsigned int tok = (pos >= 0) ? (unsigned)tokens[b*TT + pos]
                                          : (unsigned)prev[b*OVL + OVL + pos];
            hs += tok * p;
        }
        sidx[tid] = hs % MM;
    }
    __syncthreads();
    int d0 = tid * 4;
    int eh = tid >> 5;
    int jj = d0 & 127;
    int tok = tokens[b*TT + t];
    float4 ev = *(const float4*)(embed + (size_t)tok*DD + d0);
    float4 cv = *(const float4*)(ctxadd + b*DD + d0);
    float4 rv = *(const float4*)(etab + ((size_t)sidx[eh]*EH + eh)*EHD + jj);
    float4 gv = *(const float4*)(egate + eh*EHD + jj);
    float4 o;
    o.x = ev.x + cv.x + rv.x * (1.f/(1.f+__expf(-gv.x)));
    o.y = ev.y + cv.y + rv.y * (1.f/(1.f+__expf(-gv.y)));
    o.z = ev.z + cv.z + rv.z * (1.f/(1.f+__expf(-gv.z)));
    o.w = ev.w + cv.w + rv.w * (1.f/(1.f+__expf(-gv.w)));
    *(float4*)(X + (size_t)row*DD + d0) = o;
    float ss = blockReduceSum128(o.x*o.x + o.y*o.y + o.z*o.z + o.w*o.w);
    float inv = rsqrtf(ss * (1.f/DD) + 1e-6f);
    float4 sc = ((const float4*)ln1)[tid];
    size_t off = (size_t)row*DD + d0;
    *(__half2*)(H + off)     = __floats2half2_rn(o.x*inv*sc.x, o.y*inv*sc.y);
    *(__half2*)(H + off + 2) = __floats2half2_rn(o.z*inv*sc.z, o.w*inv*sc.w);
}

// ---------------- RMSNorm -> fp16 plane ----------------
__global__ void rmsnorm_half_kernel(const float* __restrict__ X, const float* __restrict__ scale,
                                    __half* __restrict__ H) {
    int row = blockIdx.x;
    float4 v = ((const float4*)(X + (size_t)row*DD))[threadIdx.x];
    float ss = v.x*v.x + v.y*v.y + v.z*v.z + v.w*v.w;
    ss = blockReduceSum128(ss);
    float inv = rsqrtf(ss * (1.f/DD) + 1e-6f);
    float4 sc = ((const float4*)scale)[threadIdx.x];
    size_t off = (size_t)row*DD + threadIdx.x*4;
    *(__half2*)(H + off)     = __floats2half2_rn(v.x*inv*sc.x, v.y*inv*sc.y);
    *(__half2*)(H + off + 2) = __floats2half2_rn(v.z*inv*sc.z, v.w*inv*sc.w);
}

// ---------------- final RMSNorm (fp32 out) ----------------
__global__ void rmsnorm_kernel(const float* __restrict__ X, const float* __restrict__ scale,
                               float* __restrict__ Out) {
    int row = blockIdx.x;
    float4 v = ((const float4*)(X + (size_t)row*DD))[threadIdx.x];
    float ss = v.x*v.x + v.y*v.y + v.z*v.z + v.w*v.w;
    ss = blockReduceSum128(ss);
    float inv = rsqrtf(ss * (1.f/DD) + 1e-6f);
    float4 sc = ((const float4*)scale)[threadIdx.x];
    float4 o;
    o.x = v.x*inv*sc.x; o.y = v.y*inv*sc.y; o.z = v.z*inv*sc.z; o.w = v.w*inv*sc.w;
    ((float4*)(Out + (size_t)row*DD))[threadIdx.x] = o;
}

// ---------------- rope helper ----------------
__device__ __forceinline__ float4 rope4(float4 v, int t, int dv) {
    const float c = 9.210340371976184f / 64.f;
    float inv0 = __expf(-(float)dv * c);
    float inv1 = __expf(-(float)(dv+2) * c);
    float s0, c0, s1, c1;
    __sincosf((float)t * inv0, &s0, &c0);
    __sincosf((float)t * inv1, &s1, &c1);
    float4 r;
    r.x = v.x*c0 - v.y*s0;  r.y = v.x*s0 + v.y*c0;
    r.z = v.z*c1 - v.w*s1;  r.w = v.z*s1 + v.w*c1;
    return r;
}
__device__ __forceinline__ float4 h4f(const __half2* p) {
    float2 a = __half22float2(p[0]);
    float2 b = __half22float2(p[1]);
    return make_float4(a.x, a.y, b.x, b.y);
}

// ---------------- HMMA causal flash attention: BQ=128, BK=64, HD=64, fp16 QKV in ----------------
#define FPAD 72
#define FSMEM ((128 + 64 + 64)*FPAD*2)   // 36864

__global__ void __launch_bounds__(256, 2) flash_kernel(const __half* __restrict__ QKV,
        __half* __restrict__ Oh) {
    extern __shared__ char fsm[];
    __half* Qh = (__half*)fsm;
    __half* Kh = Qh + 128*FPAD;
    __half* Vt = Kh + 64*FPAD;
    uint32_t uq = smem_to_u32(Qh);
    uint32_t uk = smem_to_u32(Kh);
    uint32_t uv = smem_to_u32(Vt);

    int bh = blockIdx.y;
    int b = bh >> 3, h = bh & 7;
    int q0 = blockIdx.x * 128;
    int tid = threadIdx.x, lane = tid & 31, wid = tid >> 5;
    int gid = lane >> 2, ctg = lane & 3;
    const int a_row = lane & 15;
    const int a_k   = (lane >> 4) * 8;
    const int b_row = (lane & 7) + ((lane >> 4) << 3);
    const int b_k   = ((lane >> 3) & 1) * 8;
    size_t base = ((size_t)b*TT)*1536 + h*HD;
    const float scl = 0.125f;

    // load Q (fp16 in, rope in fp32 regs)
    for (int i = tid; i < 128*16; i += 256) {
        int r = i >> 4, dv = (i & 15) * 4;
        float4 v = h4f((const __half2*)(QKV + base + (size_t)(q0 + r)*1536 + dv));
        v = rope4(v, q0 + r, dv);
        __half2* dst = (__half2*)(Qh + r*FPAD + dv);
        dst[0] = __floats2half2_rn(v.x, v.y);
        dst[1] = __floats2half2_rn(v.z, v.w);
    }

    float m0 = -1e30f, m1 = -1e30f, l0 = 0.f, l1 = 0.f;
    float oacc[8][4];
    #pragma unroll
    for (int i = 0; i < 8; i++)
        #pragma unroll
        for (int j = 0; j < 4; j++) oacc[i][j] = 0.f;

    int row0 = q0 + wid*16 + gid;
    int nkt = (q0 >> 6) + 2;
    for (int kt = 0; kt < nkt; kt++) {
        int k0 = kt * 64;
        __syncthreads();
        for (int i = tid; i < 64*16; i += 256) {
            int r = i >> 4, dv = (i & 15)*4;
            size_t g = base + (size_t)(k0 + r)*1536 + dv;
            float4 kv = h4f((const __half2*)(QKV + g + 512));
            kv = rope4(kv, k0 + r, dv);
            __half2* kd = (__half2*)(Kh + r*FPAD + dv);
            kd[0] = __floats2half2_rn(kv.x, kv.y);
            kd[1] = __floats2half2_rn(kv.z, kv.w);
            __half2 v0 = ((const __half2*)(QKV + g + 1024))[0];
            __half2 v1 = ((const __half2*)(QKV + g + 1024))[1];
            Vt[(dv+0)*FPAD + r] = __low2half(v0);
            Vt[(dv+1)*FPAD + r] = __high2half(v0);
            Vt[(dv+2)*FPAD + r] = __low2half(v1);
            Vt[(dv+3)*FPAD + r] = __high2half(v1);
        }
        __syncthreads();
        float sacc[8][4];
        #pragma unroll
        for (int nt = 0; nt < 8; nt++)
            #pragma unroll
            for (int j = 0; j < 4; j++) sacc[nt][j] = 0.f;
        #pragma unroll
        for (int kk = 0; kk < 64; kk += 16) {
            uint32_t af[4], bf[4][4];
            LDSM4(af, uq + (uint32_t)((wid*16 + a_row)*FPAD + kk + a_k)*2);
            #pragma unroll
            for (int np = 0; np < 4; np++)
                LDSM4(bf[np], uk + (uint32_t)((np*16 + b_row)*FPAD + kk + b_k)*2);
            #pragma unroll
            for (int np = 0; np < 4; np++) {
                HMMA(sacc[2*np],   af, bf[np][0], bf[np][1]);
                HMMA(sacc[2*np+1], af, bf[np][2], bf[np][3]);
            }
        }
        if (kt >= nkt - 2) {
            #pragma unroll
            for (int nt = 0; nt < 8; nt++) {
                int col = k0 + nt*8 + ctg*2;
                #pragma unroll
                for (int j = 0; j < 4; j++) {
                    int cc = col + (j & 1);
                    int rr = row0 + ((j >> 1) << 3);
                    sacc[nt][j] = (cc <= rr) ? sacc[nt][j]*scl : -1e9f;
                }
            }
        } else {
            #pragma unroll
            for (int nt = 0; nt < 8; nt++)
                #pragma unroll
                for (int j = 0; j < 4; j++) sacc[nt][j] *= scl;
        }
        float rm0 = -1e30f, rm1 = -1e30f;
        #pragma unroll
        for (int nt = 0; nt < 8; nt++) {
            rm0 = fmaxf(rm0, fmaxf(sacc[nt][0], sacc[nt][1]));
            rm1 = fmaxf(rm1, fmaxf(sacc[nt][2], sacc[nt][3]));
        }
        rm0 = fmaxf(rm0, __shfl_xor_sync(0xffffffffu, rm0, 1));
        rm0 = fmaxf(rm0, __shfl_xor_sync(0xffffffffu, rm0, 2));
        rm1 = fmaxf(rm1, __shfl_xor_sync(0xffffffffu, rm1, 1));
        rm1 = fmaxf(rm1, __shfl_xor_sync(0xffffffffu, rm1, 2));
        float mn0 = fmaxf(m0, rm0), mn1 = fmaxf(m1, rm1);
        float c0 = __expf(m0 - mn0), c1 = __expf(m1 - mn1);
        m0 = mn0; m1 = mn1;
        float rs0 = 0.f, rs1 = 0.f;
        #pragma unroll
        for (int nt = 0; nt < 8; nt++) {
            sacc[nt][0] = __expf(sacc[nt][0] - mn0); rs0 += sacc[nt][0];
            sacc[nt][1] = __expf(sacc[nt][1] - mn0); rs0 += sacc[nt][1];
            sacc[nt][2] = __expf(sacc[nt][2] - mn1); rs1 += sacc[nt][2];
            sacc[nt][3] = __expf(sacc[nt][3] - mn1); rs1 += sacc[nt][3];
        }
        rs0 += __shfl_xor_sync(0xffffffffu, rs0, 1);
        rs0 += __shfl_xor_sync(0xffffffffu, rs0, 2);
        rs1 += __shfl_xor_sync(0xffffffffu, rs1, 1);
        rs1 += __shfl_xor_sync(0xffffffffu, rs1, 2);
        l0 = l0*c0 + rs0;
        l1 = l1*c1 + rs1;
        #pragma unroll
        for (int nh = 0; nh < 8; nh++) {
            oacc[nh][0] *= c0; oacc[nh][1] *= c0;
            oacc[nh][2] *= c1; oacc[nh][3] *= c1;
        }
        #pragma unroll
        for (int g = 0; g < 4; g++) {
            uint32_t pf[4];
            pf[0] = f22u(sacc[2*g][0],   sacc[2*g][1]);
            pf[1] = f22u(sacc[2*g][2],   sacc[2*g][3]);
            pf[2] = f22u(sacc[2*g+1][0], sacc[2*g+1][1]);
            pf[3] = f22u(sacc[2*g+1][2], sacc[2*g+1][3]);
            int kof = g*16;
            #pragma unroll
            for (int nh = 0; nh < 4; nh++) {
                uint32_t bf2[4];
                LDSM4(bf2, uv + (uint32_t)((nh*16 + b_row)*FPAD + kof + b_k)*2);
                HMMA(oacc[2*nh],   pf, bf2[0], bf2[1]);
                HMMA(oacc[2*nh+1], pf, bf2[2], bf2[3]);
            }
        }
    }
    float inv0 = 1.f / l0, inv1 = 1.f / l1;
    #pragma unroll
    for (int nh = 0; nh < 8; nh++) {
        int c = nh*8 + ctg*2;
        size_t r0 = (size_t)(b*TT + row0)*DD + h*HD + c;
        size_t r1 = (size_t)(b*TT + row0 + 8)*DD + h*HD + c;
        *(__half2*)(Oh + r0) = __floats2half2_rn(oacc[nh][0]*inv0, oacc[nh][1]*inv0);
        *(__half2*)(Oh + r1) = __floats2half2_rn(oacc[nh][2]*inv1, oacc[nh][3]*inv1);
    }
}

// ---------------- salience logits ----------------
__global__ void logits_kernel(const float* __restrict__ X, const float* __restrict__ sal_W,
                              const float* __restrict__ sal_b, const float* __restrict__ temp,
                              float* __restrict__ out) {
    int row = blockIdx.x;
    int e = threadIdx.x >> 5, lane = threadIdx.x & 31;
    const float* xr = X + (size_t)row*DD;
    float acc = 0.f;
    for (int d = lane; d < DD; d += 32)
        acc += xr[d] * sal_W[d*EH + e];
    acc = warpReduceSum(acc);
    if (lane == 0) {
        float tp = log1pf(expf(temp[e])) + 0.3f;
        out[(size_t)row*EH + e] = (acc + sal_b[e]) / tp;
    }
}

// ---------------- masked softmax pool ----------------
__global__ void pool_kernel(const int* __restrict__ tokens, const float* __restrict__ logits,
                            const float* __restrict__ X, const float* __restrict__ gate_W,
                            const float* __restrict__ gate_b,
                            float* __restrict__ wv_out, float* __restrict__ u_out) {
    int b = blockIdx.x >> 2, e = blockIdx.x & 3;
    int tid = threadIdx.x;
    __shared__ float ws[TT];
    float lg4[4]; int mv4[4];
    float lmax = -1e30f; float lvalid = 0.f;
    #pragma unroll
    for (int p = 0; p < 4; p++) {
        int t = tid + p*128;
        int mv = (tokens[b*TT + t] != 0);
        float lgv = logits[((size_t)b*TT + t)*EH + e];
        float sf = mv ? lgv : -1e9f;
        lg4[p] = sf; mv4[p] = mv;
        lmax = fmaxf(lmax, sf);
        lvalid += (float)mv;
    }
    float mx = blockReduceMax128(lmax);
    float lsum = 0.f;
    #pragma unroll
    for (int p = 0; p < 4; p++) {
        int t = tid + p*128;
        float ev = mv4[p] ? expf(lg4[p] - mx) : 0.f;
        ws[t] = ev;
        lsum += ev;
    }
    float ssum = blockReduceSum128(lsum);
    float nvalid = blockReduceSum128(lvalid);
    float wsc = 1.f / (ssum + 1e-6f);
    __syncthreads();
    float acc = 0.f;
    const float* xb = X + ((size_t)b*TT)*DD + e*EHD + tid;
    for (int t = 0; t < TT; t++)
        acc += ws[t] * xb[(size_t)t*DD];
    acc *= wsc;
    wv_out[b*DD + e*EHD + tid] = acc;
    float gsum = blockReduceSum128(acc * gate_W[tid]);
    if (tid == 0) {
        float gl = gsum + gate_b[0];
        float u = (nvalid > 0.f) ? 1.f/(1.f+expf(-gl)) : 0.f;
        u_out[b*EH + e] = u;
    }
}

// ---------------- fast/slow state update ----------------
__global__ void update_kernel(const float* __restrict__ wv, const float* __restrict__ u,
                              const float* __restrict__ sal_rms,
                              const float* __restrict__ fast, const float* __restrict__ slow,
                              float* __restrict__ out_fast, float* __restrict__ out_slow) {
    int b = blockIdx.x, tid = threadIdx.x;
    float4 v = ((const float4*)(wv + b*DD))[tid];
    float ss = blockReduceSum128(v.x*v.x + v.y*v.y + v.z*v.z + v.w*v.w);
    float inv = rsqrtf(ss * (1.f/DD) + 1e-6f);
    float4 sr = ((const float4*)sal_rms)[tid];
    int e = tid >> 5;
    float uu = u[b*EH + e];
    float4 f = ((const float4*)(fast + b*DD))[tid];
    float4 s = ((const float4*)(slow + b*DD))[tid];
    float4 wn;
    wn.x = v.x*inv*sr.x; wn.y = v.y*inv*sr.y; wn.z = v.z*inv*sr.z; wn.w = v.w*inv*sr.w;
    float4 nf, ns;
    nf.x = (1.f-uu)*f.x + uu*wn.x;  nf.y = (1.f-uu)*f.y + uu*wn.y;
    nf.z = (1.f-uu)*f.z + uu*wn.z;  nf.w = (1.f-uu)*f.w + uu*wn.w;
    float ud = 0.1f*uu;
    ns.x = (1.f-ud)*s.x + ud*wn.x;  ns.y = (1.f-ud)*s.y + ud*wn.y;
    ns.z = (1.f-ud)*s.z + ud*wn.z;  ns.w = (1.f-ud)*s.w + ud*wn.w;
    ((float4*)(out_fast + b*DD))[tid] = nf;
    ((float4*)(out_slow + b*DD))[tid] = ns;
}

// ---------------- launch ----------------
extern "C" void kernel_launch(void* const* d_in, const int* in_sizes, int n_in,
                              void* d_out, int out_size) {
    const int*   tokens = (const int*)  d_in[0];
    const int*   prev   = (const int*)  d_in[1];
    const float* fast   = (const float*)d_in[2];
    const float* slow   = (const float*)d_in[3];
    const float* embed  = (const float*)d_in[4];
    const float* ctx_W  = (const float*)d_in[5];
    const float* ctx_b  = (const float*)d_in[6];
    const float* etab   = (const float*)d_in[7];
    const float* egate  = (const float*)d_in[8];
    const float* ln1    = (const float*)d_in[9];
    const float* Wq     = (const float*)d_in[10];
    const float* bq     = (const float*)d_in[11];
    const float* Wk     = (const float*)d_in[12];
    const float* bk     = (const float*)d_in[13];
    const float* Wv     = (const float*)d_in[14];
    const float* bv     = (const float*)d_in[15];
    const float* Wo     = (const float*)d_in[16];
    const float* bo     = (const float*)d_in[17];
    const float* ln2    = (const float*)d_in[18];
    const float* W1     = (const float*)d_in[19];
    const float* W2     = (const float*)d_in[20];
    const float* ln_f   = (const float*)d_in[21];
    const float* sal_W  = (const float*)d_in[22];
    const float* sal_b  = (const float*)d_in[23];
    const float* temp   = (const float*)d_in[24];
    const float* gate_W = (const float*)d_in[25];
    const float* gate_b = (const float*)d_in[26];
    const float* sal_rms= (const float*)d_in[27];
    float* out = (float*)d_out;

    float *gx, *gctx, *glog, *gwv, *gu;
    __half *gqkv, *nx, *at, *ff;
    __half *wA, *w1, *w2;
    cudaGetSymbolAddress((void**)&gx,   g_x);
    cudaGetSymbolAddress((void**)&gqkv, g_qkv);
    cudaGetSymbolAddress((void**)&gctx, g_ctx);
    cudaGetSymbolAddress((void**)&glog, g_logits);
    cudaGetSymbolAddress((void**)&gwv,  g_wv);
    cudaGetSymbolAddress((void**)&gu,   g_u);
    cudaGetSymbolAddress((void**)&nx,   g_nx);
    cudaGetSymbolAddress((void**)&at,   g_at);
    cudaGetSymbolAddress((void**)&ff,   g_ff);
    cudaGetSymbolAddress((void**)&wA,   g_wqkvo);
    cudaGetSymbolAddress((void**)&w1,   g_w1);
    cudaGetSymbolAddress((void**)&w2,   g_w2);

    cudaFuncSetAttribute(hgemm<0>, cudaFuncAttributeMaxDynamicSharedMemorySize, HSMEM);
    cudaFuncSetAttribute(hgemm<1>, cudaFuncAttributeMaxDynamicSharedMemorySize, HSMEM);
    cudaFuncSetAttribute(hgemm<4>, cudaFuncAttributeMaxDynamicSharedMemorySize, HSMEM);
    cudaFuncSetAttribute(hgemm_ffn, cudaFuncAttributeMaxDynamicSharedMemorySize, HSMEM);
    cudaFuncSetAttribute(flash_kernel, cudaFuncAttributeMaxDynamicSharedMemorySize, FSMEM);

    dim3 tb(32, 8);
    dim3 gD(NTOK/128, DD/128);
    dim3 gQKV(NTOK/128, (3*DD)/128);
    dim3 gFF(NTOK/128, FF/64);

    // ncu captures launch #4 -> fused-QKV hgemm.
    tsplit4_kernel<<<dim3(DD/32, DD/32, 4*LL), tb>>>(Wq, Wk, Wv, Wo, wA);                // 1
    ctx_kernel<<<BB, 512>>>(fast, slow, ctx_W, ctx_b, gctx);                             // 2
    embed_fused_kernel<<<NTOK, 128>>>(tokens, prev, embed, gctx, etab, egate, ln1,
                                      gx, nx);                                           // 3

    for (int l = 0; l < LL; l++) {
        size_t wo  = (size_t)l*4*DD*DD;
        size_t w1o = (size_t)l*2*FF*DD;
        size_t w2o = (size_t)l*DD*FF;
        if (l > 0)
            rmsnorm_half_kernel<<<NTOK, 128>>>(gx, ln1 + l*DD, nx);
        hgemm<0><<<gQKV, 256, HSMEM>>>(nx, wA + wo,
                                       bq + l*DD, bk + l*DD, bv + l*DD,
                                       nullptr, nullptr, gqkv, NTOK, 3*DD, DD);
        if (l == 0) {
            tsplitW1_kernel<<<dim3(FF/32, DD/32, 2*LL), tb>>>(W1, w1);
            tsplit_kernel<<<dim3(DD/32, FF/32, LL), tb>>>(W2, DD, (size_t)FF*DD, w2, (size_t)DD*FF, FF);
        }
        flash_kernel<<<dim3(TT/128, BB*HH), 256, FSMEM>>>(gqkv, at);
        hgemm<1><<<gD, 256, HSMEM>>>(at, wA + wo + (size_t)1536*DD,
                                     bo + l*DD, nullptr, nullptr, gx,
                                     gx, nullptr, NTOK, DD, DD);
        rmsnorm_half_kernel<<<NTOK, 128>>>(gx, ln2 + l*DD, nx);
        hgemm_ffn<<<gFF, 256, HSMEM>>>(nx, w1 + w1o, w1 + w1o + (size_t)FF*DD,
                                       ff, NTOK, FF, DD);
        hgemm<4><<<gD, 256, HSMEM>>>(ff, w2 + w2o,
                                     nullptr, nullptr, nullptr, gx,
                                     gx, nullptr, NTOK, DD, FF);
    }
    rmsnorm_kernel<<<NTOK, 128>>>(gx, ln_f, out);
    logits_kernel<<<NTOK, 128>>>(out, sal_W, sal_b, temp, glog);
    pool_kernel<<<BB*EH, 128>>>(tokens, glog, out, gate_W, gate_b, gwv, gu);
    update_kernel<<<BB, 128>>>(gwv, gu, sal_rms, fast, slow,
                               out + (size_t)NTOK*DD,
                               out + (size_t)NTOK*DD + BB*DD);
}

// round 14
// speedup vs baseline: 1.3568x; 1.0079x over previous
#include <cuda_runtime.h>
#include <cuda_fp16.h>
#include <math.h>
#include <stdint.h>

// ---------------- problem constants ----------------
#define BB 32
#define TT 512
#define DD 512
#define LL 6
#define HH 8
#define HD 64
#define FF 2048      // 4*D
#define EH 4
#define EHD 128
#define MM 100000u
#define OVL 64
#define NTOK (BB*TT)   // 16384

// ---------------- scratch ----------------
__device__ float g_x[NTOK*DD];
__device__ float g_ctx[BB*DD];
__device__ float g_logits[NTOK*EH];
__device__ float g_wv[BB*DD];
__device__ float g_u[BB*EH];
// fp16 activations
__device__ __half g_qkv[(size_t)NTOK*3*DD];
__device__ __half g_nx[NTOK*DD];
__device__ __half g_at[NTOK*DD];
__device__ __half g_ff[(size_t)NTOK*FF];
// transposed fp16 weights: [N][K]
__device__ __half g_wqkvo[(size_t)LL*4*DD*DD];
__device__ __half g_w1[(size_t)LL*2*FF*DD];
__device__ __half g_w2[(size_t)LL*DD*FF];

// ---------------- PTX helpers ----------------
__device__ __forceinline__ uint32_t smem_to_u32(const void* p) {
    uint32_t a;
    asm("{ .reg .u64 t; cvta.to.shared.u64 t, %1; cvt.u32.u64 %0, t; }" : "=r"(a) : "l"(p));
    return a;
}
__device__ __forceinline__ void cp16(uint32_t dst, const void* src) {
    asm volatile("cp.async.cg.shared.global [%0], [%1], 16;" :: "r"(dst), "l"(src));
}
#define CP_COMMIT() asm volatile("cp.async.commit_group;" ::: "memory")
#define CP_WAIT2()  asm volatile("cp.async.wait_group 2;" ::: "memory")

#define LDSM4(r, addr) \
    asm volatile("ldmatrix.sync.aligned.m8n8.x4.shared.b16 {%0,%1,%2,%3}, [%4];" \
        : "=r"((r)[0]), "=r"((r)[1]), "=r"((r)[2]), "=r"((r)[3]) : "r"(addr))

#define HMMA(c, a, b0, b1) \
    asm volatile("mma.sync.aligned.m16n8k16.row.col.f32.f16.f16.f32 " \
        "{%0,%1,%2,%3}, {%4,%5,%6,%7}, {%8,%9}, {%0,%1,%2,%3};" \
        : "+f"((c)[0]), "+f"((c)[1]), "+f"((c)[2]), "+f"((c)[3]) \
        : "r"((a)[0]), "r"((a)[1]), "r"((a)[2]), "r"((a)[3]), "r"(b0), "r"(b1))

__device__ __forceinline__ uint32_t f22u(float a, float b) {
    __half2 h = __floats2half2_rn(a, b);
    return *(uint32_t*)&h;
}

// ---------------- reduction helpers ----------------
__device__ __forceinline__ float warpReduceSum(float v) {
    #pragma unroll
    for (int o = 16; o; o >>= 1) v += __shfl_xor_sync(0xffffffffu, v, o);
    return v;
}
__device__ __forceinline__ float warpReduceMax(float v) {
    #pragma unroll
    for (int o = 16; o; o >>= 1) v = fmaxf(v, __shfl_xor_sync(0xffffffffu, v, o));
    return v;
}
__device__ __forceinline__ float blockReduceSum128(float v) {
    __shared__ float sm[4];
    __syncthreads();
    v = warpReduceSum(v);
    if ((threadIdx.x & 31) == 0) sm[threadIdx.x >> 5] = v;
    __syncthreads();
    return sm[0] + sm[1] + sm[2] + sm[3];
}
__device__ __forceinline__ float blockReduceSum512(float v) {
    __shared__ float sm[16];
    __syncthreads();
    v = warpReduceSum(v);
    if ((threadIdx.x & 31) == 0) sm[threadIdx.x >> 5] = v;
    __syncthreads();
    float r = 0.f;
    #pragma unroll
    for (int i = 0; i < 16; i++) r += sm[i];
    return r;
}
__device__ __forceinline__ float blockReduceMax512(float v) {
    __shared__ float sm[16];
    __syncthreads();
    v = warpReduceMax(v);
    if ((threadIdx.x & 31) == 0) sm[threadIdx.x >> 5] = v;
    __syncthreads();
    float r = -1e30f;
    #pragma unroll
    for (int i = 0; i < 16; i++) r = fmaxf(r, sm[i]);
    return r;
}

// ---------------- 4-source transpose to fp16 (Wq/Wk/Wv/Wo stacked) ----------------
__global__ void tsplit4_kernel(const float* __restrict__ s0, const float* __restrict__ s1,
                               const float* __restrict__ s2, const float* __restrict__ s3,
                               __half* __restrict__ dst) {
    __shared__ float t[32][33];
    int z = blockIdx.z;
    int l = z >> 2, sel = z & 3;
    const float* S = (sel == 0 ? s0 : sel == 1 ? s1 : sel == 2 ? s2 : s3) + (size_t)l*DD*DD;
    __half* Hd = dst + (size_t)z*DD*DD;
    int n0 = blockIdx.x*32, k0 = blockIdx.y*32;
    int x = threadIdx.x, y = threadIdx.y;
    #pragma unroll
    for (int i = 0; i < 32; i += 8) t[y+i][x] = S[(size_t)(k0+y+i)*DD + n0+x];
    __syncthreads();
    #pragma unroll
    for (int i = 0; i < 32; i += 8)
        Hd[(size_t)(n0+y+i)*DD + k0+x] = __float2half_rn(t[x][y+i]);
}

// ---------------- generic transpose to fp16 ----------------
__global__ void tsplit_kernel(const float* __restrict__ src, int ldsrc, size_t srcStride,
                              __half* __restrict__ dst, size_t dstStride, int K) {
    __shared__ float t[32][33];
    int l = blockIdx.z;
    const float* S = src + (size_t)l*srcStride;
    __half* Hd = dst + (size_t)l*dstStride;
    int n0 = blockIdx.x*32, k0 = blockIdx.y*32;
    int x = threadIdx.x, y = threadIdx.y;
    #pragma unroll
    for (int i = 0; i < 32; i += 8) t[y+i][x] = S[(size_t)(k0+y+i)*ldsrc + n0+x];
    __syncthreads();
    #pragma unroll
    for (int i = 0; i < 32; i += 8)
        Hd[(size_t)(n0+y+i)*K + k0+x] = __float2half_rn(t[x][y+i]);
}

// ---------------- W1 transpose to fp16 ----------------
__global__ void tsplitW1_kernel(const float* __restrict__ W1, __half* __restrict__ dst) {
    __shared__ float t[32][33];
    int z = blockIdx.z;
    int l = z >> 1, half = z & 1;
    const float* S = W1 + (size_t)l*DD*2*FF + (size_t)half*FF;
    __half* Hd = dst + (size_t)l*2*FF*DD + (size_t)half*FF*DD;
    int n0 = blockIdx.x*32, k0 = blockIdx.y*32;
    int x = threadIdx.x, y = threadIdx.y;
    #pragma unroll
    for (int i = 0; i < 32; i += 8) t[y+i][x] = S[(size_t)(k0+y+i)*(2*FF) + n0+x];
    __syncthreads();
    #pragma unroll
    for (int i = 0; i < 32; i += 8)
        Hd[(size_t)(n0+y+i)*DD + k0+x] = __float2half_rn(t[x][y+i]);
}

// ---------------- fp16 HMMA GEMM (single pass, 4-stage cp.async) ----------------
// MODE 0: +bias3 (QKV select), fp16 out ; 1: +bias +res, fp32 out ; 4: +res, fp32 out
#define TILE_B 10240
#define STAGE_B 20480
#define HSMEM (4*STAGE_B)

__device__ __forceinline__ void load_stage(uint32_t sb,
        const __half* A, const __half* B, int K, int kof, int tid) {
    #pragma unroll
    for (int i = 0; i < 2; i++) {
        int e = tid + i*256;
        int row = e >> 2, seg = e & 3;
        uint32_t off = (uint32_t)(row*80 + seg*16);
        size_t g = (size_t)row*K + kof + seg*8;
        cp16(sb + off,          A + g);
        cp16(sb + TILE_B + off, B + g);
    }
}

template<int MODE>
__global__ void __launch_bounds__(256, 2)
hgemm(const __half* __restrict__ A, const __half* __restrict__ B,
      const float* __restrict__ bias, const float* __restrict__ bias2,
      const float* __restrict__ bias3,
      const float* __restrict__ Res,
      float* __restrict__ C, __half* __restrict__ OutH,
      int M, int N, int K) {
    extern __shared__ char dsm[];
    uint32_t sb = smem_to_u32(dsm);
    int tid = threadIdx.x, lane = tid & 31, wid = tid >> 5;
    int m0 = blockIdx.x * 128, n0 = blockIdx.y * 128;
    int wm = (wid & 1) * 64, wn = (wid >> 1) * 32;
    const __half* Ab = A + (size_t)m0*K;
    const __half* Bb = B + (size_t)n0*K;
    int NC = K >> 5;

    load_stage(sb,             Ab, Bb, K, 0,  tid); CP_COMMIT();
    load_stage(sb + STAGE_B,   Ab, Bb, K, 32, tid); CP_COMMIT();
    load_stage(sb + 2*STAGE_B, Ab, Bb, K, 64, tid); CP_COMMIT();

    float acc[4][4][4];
    #pragma unroll
    for (int a = 0; a < 4; a++)
        #pragma unroll
        for (int b = 0; b < 4; b++)
            #pragma unroll
            for (int c = 0; c < 4; c++) acc[a][b][c] = 0.f;

    const int a_row = lane & 15;
    const int a_k   = (lane >> 4) * 8;
    const int b_row = (lane & 7) + ((lane >> 4) << 3);
    const int b_k   = ((lane >> 3) & 1) * 8;

    for (int i = 0; i < NC; i++) {
        CP_WAIT2();
        __syncthreads();
        if (i + 3 < NC)
            load_stage(sb + (uint32_t)((i+3) & 3)*STAGE_B, Ab, Bb, K, (i+3)*32, tid);
        CP_COMMIT();
        uint32_t st = sb + (uint32_t)(i & 3)*STAGE_B;
        #pragma unroll
        for (int kk = 0; kk < 32; kk += 16) {
            uint32_t a4[4][4], b2[2][4];
            #pragma unroll
            for (int mt = 0; mt < 4; mt++) {
                uint32_t ad = st + (uint32_t)((wm + mt*16 + a_row)*80 + (kk + a_k)*2);
                LDSM4(a4[mt], ad);
            }
            #pragma unroll
            for (int np = 0; np < 2; np++) {
                uint32_t bd = st + TILE_B + (uint32_t)((wn + np*16 + b_row)*80 + (kk + b_k)*2);
                LDSM4(b2[np], bd);
            }
            #pragma unroll
            for (int mt = 0; mt < 4; mt++)
                #pragma unroll
                for (int nt = 0; nt < 4; nt++)
                    HMMA(acc[mt][nt], a4[mt], b2[nt>>1][(nt&1)*2], b2[nt>>1][(nt&1)*2+1]);
        }
    }

    int gid = lane >> 2, ctg = lane & 3;
    #pragma unroll
    for (int mt = 0; mt < 4; mt++)
        #pragma unroll
        for (int nt = 0; nt < 4; nt++) {
            int r0 = m0 + wm + mt*16 + gid;
            int cc = n0 + wn + nt*8 + ctg*2;
            float2 v0 = make_float2(acc[mt][nt][0], acc[mt][nt][1]);
            float2 v1 = make_float2(acc[mt][nt][2], acc[mt][nt][3]);
            if (MODE == 0) {
                const float* bp = (cc < 512) ? (bias + cc)
                                : (cc < 1024) ? (bias2 + cc - 512) : (bias3 + cc - 1024);
                float2 bb = *(const float2*)bp;
                v0.x += bb.x; v0.y += bb.y; v1.x += bb.x; v1.y += bb.y;
                *(__half2*)(OutH + (size_t)r0*N + cc)     = __floats2half2_rn(v0.x, v0.y);
                *(__half2*)(OutH + (size_t)(r0+8)*N + cc) = __floats2half2_rn(v1.x, v1.y);
            } else {
                if (MODE == 1) {
                    float2 bb = *(const float2*)(bias + cc);
                    v0.x += bb.x; v0.y += bb.y; v1.x += bb.x; v1.y += bb.y;
                }
                float2 ra = *(const float2*)(Res + (size_t)r0*N + cc);
                float2 rb = *(const float2*)(Res + (size_t)(r0+8)*N + cc);
                v0.x += ra.x; v0.y += ra.y; v1.x += rb.x; v1.y += rb.y;
                *(float2*)(C + (size_t)r0*N + cc) = v0;
                *(float2*)(C + (size_t)(r0+8)*N + cc) = v1;
            }
        }
}

// ---------------- fused gate+value FFN GEMM ----------------
#define FT_BG 10240
#define FT_BV 15360

__device__ __forceinline__ void load_stage_ffn(uint32_t sb,
        const __half* A, const __half* Bg, const __half* Bv, int K, int kof, int tid) {
    #pragma unroll
    for (int i = 0; i < 2; i++) {
        int e = tid + i*256;
        int row = e >> 2, seg = e & 3;
        uint32_t off = (uint32_t)(row*80 + seg*16);
        cp16(sb + off, A + (size_t)row*K + kof + seg*8);
    }
    {
        int row = tid >> 2, seg = tid & 3;
        uint32_t off = (uint32_t)(row*80 + seg*16);
        size_t g = (size_t)row*K + kof + seg*8;
        cp16(sb + FT_BG + off, Bg + g);
        cp16(sb + FT_BV + off, Bv + g);
    }
}

__global__ void __launch_bounds__(256, 2)
hgemm_ffn(const __half* __restrict__ A, const __half* __restrict__ Bg,
          const __half* __restrict__ Bv, __half* __restrict__ Out,
          int M, int N, int K) {
    extern __shared__ char dsm[];
    uint32_t sb = smem_to_u32(dsm);
    int tid = threadIdx.x, lane = tid & 31, wid = tid >> 5;
    int m0 = blockIdx.x * 128, n0 = blockIdx.y * 64;
    int wm = (wid & 1) * 64, wn = (wid >> 1) * 16;
    const __half* Ab  = A  + (size_t)m0*K;
    const __half* Bgb = Bg + (size_t)n0*K;
    const __half* Bvb = Bv + (size_t)n0*K;
    int NC = K >> 5;

    load_stage_ffn(sb,             Ab, Bgb, Bvb, K, 0,  tid); CP_COMMIT();
    load_stage_ffn(sb + STAGE_B,   Ab, Bgb, Bvb, K, 32, tid); CP_COMMIT();
    load_stage_ffn(sb + 2*STAGE_B, Ab, Bgb, Bvb, K, 64, tid); CP_COMMIT();

    float ag[4][2][4], av[4][2][4];
    #pragma unroll
    for (int a = 0; a < 4; a++)
        #pragma unroll
        for (int b = 0; b < 2; b++)
            #pragma unroll
            for (int c = 0; c < 4; c++) { ag[a][b][c] = 0.f; av[a][b][c] = 0.f; }

    const int a_row = lane & 15;
    const int a_k   = (lane >> 4) * 8;
    const int b_row = (lane & 7) + ((lane >> 4) << 3);
    const int b_k   = ((lane >> 3) & 1) * 8;

    for (int i = 0; i < NC; i++) {
        CP_WAIT2();
        __syncthreads();
        if (i + 3 < NC)
            load_stage_ffn(sb + (uint32_t)((i+3) & 3)*STAGE_B, Ab, Bgb, Bvb, K, (i+3)*32, tid);
        CP_COMMIT();
        uint32_t st = sb + (uint32_t)(i & 3)*STAGE_B;
        #pragma unroll
        for (int kk = 0; kk < 32; kk += 16) {
            uint32_t a4[4][4], bg[4], bv2[4];
            #pragma unroll
            for (int mt = 0; mt < 4; mt++) {
                uint32_t ad = st + (uint32_t)((wm + mt*16 + a_row)*80 + (kk + a_k)*2);
                LDSM4(a4[mt], ad);
            }
            uint32_t brow = (uint32_t)((wn + b_row)*80 + (kk + b_k)*2);
            LDSM4(bg,  st + FT_BG + brow);
            LDSM4(bv2, st + FT_BV + brow);
            #pragma unroll
            for (int mt = 0; mt < 4; mt++) {
                HMMA(ag[mt][0], a4[mt], bg[0],  bg[1]);
                HMMA(ag[mt][1], a4[mt], bg[2],  bg[3]);
                HMMA(av[mt][0], a4[mt], bv2[0], bv2[1]);
                HMMA(av[mt][1], a4[mt], bv2[2], bv2[3]);
            }
        }
    }

    int gid = lane >> 2, ctg = lane & 3;
    #pragma unroll
    for (int mt = 0; mt < 4; mt++)
        #pragma unroll
        for (int nt = 0; nt < 2; nt++) {
            int r0 = m0 + wm + mt*16 + gid;
            int cc = n0 + wn + nt*8 + ctg*2;
            float g0 = ag[mt][nt][0], g1 = ag[mt][nt][1];
            float g2 = ag[mt][nt][2], g3 = ag[mt][nt][3];
            float s0 = g0/(1.f+__expf(-g0))*av[mt][nt][0];
            float s1 = g1/(1.f+__expf(-g1))*av[mt][nt][1];
            float s2 = g2/(1.f+__expf(-g2))*av[mt][nt][2];
            float s3 = g3/(1.f+__expf(-g3))*av[mt][nt][3];
            *(__half2*)(Out + (size_t)r0*N + cc)     = __floats2half2_rn(s0, s1);
            *(__half2*)(Out + (size_t)(r0+8)*N + cc) = __floats2half2_rn(s2, s3);
        }
}

// ---------------- context projection ----------------
__global__ void ctx_kernel(const float* __restrict__ fast, const float* __restrict__ slow,
                           const float* __restrict__ W, const float* __restrict__ bias,
                           float* __restrict__ out) {
    int b = blockIdx.x, d = threadIdx.x;
    float acc = bias[d];
    const float* fb = fast + b*DD;
    const float* sb = slow + b*DD;
    for (int k = 0; k < DD; k++) acc += fb[k] * W[(size_t)k*DD + d];
    for (int k = 0; k < DD; k++) acc += sb[k] * W[(size_t)(k+DD)*DD + d];
    out[b*DD + d] = acc;
}

// ---------------- embedding + context + engram + fused layer-0 rmsnorm ----------------
__global__ void embed_fused_kernel(const int* __restrict__ tokens, const int* __restrict__ prev,
                                   const float* __restrict__ embed, const float* __restrict__ ctxadd,
                                   const float* __restrict__ etab, const float* __restrict__ egate,
                                   const float* __restrict__ ln1,
                                   float* __restrict__ X, __half* __restrict__ H) {
    int row = blockIdx.x;
    int b = row >> 9, t = row & 511;
    __shared__ unsigned int sidx[EH];
    int tid = threadIdx.x;
    if (tid < EH) {
        unsigned int xseed = 131u + (unsigned)tid * 1009u;
        unsigned int hs = 0u;
        #pragma unroll
        for (int i = 0; i < 4; i++) {
            unsigned int p = xseed; xseed = xseed * 31u + 1u;
            int pos = t - i;
            unsigned int tok = (pos >= 0) ? (unsigned)tokens[b*TT + pos]
                                          : (unsigned)prev[b*OVL + OVL + pos];
            hs += tok * p;
        }
        sidx[tid] = hs % MM;
    }
    __syncthreads();
    int d0 = tid * 4;
    int eh = tid >> 5;
    int jj = d0 & 127;
    int tok = tokens[b*TT + t];
    float4 ev = *(const float4*)(embed + (size_t)tok*DD + d0);
    float4 cv = *(const float4*)(ctxadd + b*DD + d0);
    float4 rv = *(const float4*)(etab + ((size_t)sidx[eh]*EH + eh)*EHD + jj);
    float4 gv = *(const float4*)(egate + eh*EHD + jj);
    float4 o;
    o.x = ev.x + cv.x + rv.x * (1.f/(1.f+__expf(-gv.x)));
    o.y = ev.y + cv.y + rv.y * (1.f/(1.f+__expf(-gv.y)));
    o.z = ev.z + cv.z + rv.z * (1.f/(1.f+__expf(-gv.z)));
    o.w = ev.w + cv.w + rv.w * (1.f/(1.f+__expf(-gv.w)));
    *(float4*)(X + (size_t)row*DD + d0) = o;
    float ss = blockReduceSum128(o.x*o.x + o.y*o.y + o.z*o.z + o.w*o.w);
    float inv = rsqrtf(ss * (1.f/DD) + 1e-6f);
    float4 sc = ((const float4*)ln1)[tid];
    size_t off = (size_t)row*DD + d0;
    *(__half2*)(H + off)     = __floats2half2_rn(o.x*inv*sc.x, o.y*inv*sc.y);
    *(__half2*)(H + off + 2) = __floats2half2_rn(o.z*inv*sc.z, o.w*inv*sc.w);
}

// ---------------- RMSNorm -> fp16 plane ----------------
__global__ void rmsnorm_half_kernel(const float* __restrict__ X, const float* __restrict__ scale,
                                    __half* __restrict__ H) {
    int row = blockIdx.x;
    float4 v = ((const float4*)(X + (size_t)row*DD))[threadIdx.x];
    float ss = v.x*v.x + v.y*v.y + v.z*v.z + v.w*v.w;
    ss = blockReduceSum128(ss);
    float inv = rsqrtf(ss * (1.f/DD) + 1e-6f);
    float4 sc = ((const float4*)scale)[threadIdx.x];
    size_t off = (size_t)row*DD + threadIdx.x*4;
    *(__half2*)(H + off)     = __floats2half2_rn(v.x*inv*sc.x, v.y*inv*sc.y);
    *(__half2*)(H + off + 2) = __floats2half2_rn(v.z*inv*sc.z, v.w*inv*sc.w);
}

// ---------------- final RMSNorm (fp32 out) ----------------
__global__ void rmsnorm_kernel(const float* __restrict__ X, const float* __restrict__ scale,
                               float* __restrict__ Out) {
    int row = blockIdx.x;
    float4 v = ((const float4*)(X + (size_t)row*DD))[threadIdx.x];
    float ss = v.x*v.x + v.y*v.y + v.z*v.z + v.w*v.w;
    ss = blockReduceSum128(ss);
    float inv = rsqrtf(ss * (1.f/DD) + 1e-6f);
    float4 sc = ((const float4*)scale)[threadIdx.x];
    float4 o;
    o.x = v.x*inv*sc.x; o.y = v.y*inv*sc.y; o.z = v.z*inv*sc.z; o.w = v.w*inv*sc.w;
    ((float4*)(Out + (size_t)row*DD))[threadIdx.x] = o;
}

// ---------------- rope helper ----------------
__device__ __forceinline__ float4 rope4(float4 v, int t, int dv) {
    const float c = 9.210340371976184f / 64.f;
    float inv0 = __expf(-(float)dv * c);
    float inv1 = __expf(-(float)(dv+2) * c);
    float s0, c0, s1, c1;
    __sincosf((float)t * inv0, &s0, &c0);
    __sincosf((float)t * inv1, &s1, &c1);
    float4 r;
    r.x = v.x*c0 - v.y*s0;  r.y = v.x*s0 + v.y*c0;
    r.z = v.z*c1 - v.w*s1;  r.w = v.z*s1 + v.w*c1;
    return r;
}
__device__ __forceinline__ float4 h4f(const __half2* p) {
    float2 a = __half22float2(p[0]);
    float2 b = __half22float2(p[1]);
    return make_float4(a.x, a.y, b.x, b.y);
}

// ---------------- HMMA causal flash attention: BQ=128, BK=64, HD=64, fp16 QKV in ----------------
// heaviest q-blocks scheduled first (longest-job-first wave balancing)
#define FPAD 72
#define FSMEM ((128 + 64 + 64)*FPAD*2)   // 36864

__global__ void __launch_bounds__(256, 2) flash_kernel(const __half* __restrict__ QKV,
        __half* __restrict__ Oh) {
    extern __shared__ char fsm[];
    __half* Qh = (__half*)fsm;
    __half* Kh = Qh + 128*FPAD;
    __half* Vt = Kh + 64*FPAD;
    uint32_t uq = smem_to_u32(Qh);
    uint32_t uk = smem_to_u32(Kh);
    uint32_t uv = smem_to_u32(Vt);

    int bh = blockIdx.y;
    int b = bh >> 3, h = bh & 7;
    int q0 = ((int)gridDim.x - 1 - (int)blockIdx.x) * 128;   // heavy tiles first
    int tid = threadIdx.x, lane = tid & 31, wid = tid >> 5;
    int gid = lane >> 2, ctg = lane & 3;
    const int a_row = lane & 15;
    const int a_k   = (lane >> 4) * 8;
    const int b_row = (lane & 7) + ((lane >> 4) << 3);
    const int b_k   = ((lane >> 3) & 1) * 8;
    size_t base = ((size_t)b*TT)*1536 + h*HD;
    const float scl = 0.125f;

    for (int i = tid; i < 128*16; i += 256) {
        int r = i >> 4, dv = (i & 15) * 4;
        float4 v = h4f((const __half2*)(QKV + base + (size_t)(q0 + r)*1536 + dv));
        v = rope4(v, q0 + r, dv);
        __half2* dst = (__half2*)(Qh + r*FPAD + dv);
        dst[0] = __floats2half2_rn(v.x, v.y);
        dst[1] = __floats2half2_rn(v.z, v.w);
    }

    float m0 = -1e30f, m1 = -1e30f, l0 = 0.f, l1 = 0.f;
    float oacc[8][4];
    #pragma unroll
    for (int i = 0; i < 8; i++)
        #pragma unroll
        for (int j = 0; j < 4; j++) oacc[i][j] = 0.f;

    int row0 = q0 + wid*16 + gid;
    int nkt = (q0 >> 6) + 2;
    for (int kt = 0; kt < nkt; kt++) {
        int k0 = kt * 64;
        __syncthreads();
        for (int i = tid; i < 64*16; i += 256) {
            int r = i >> 4, dv = (i & 15)*4;
            size_t g = base + (size_t)(k0 + r)*1536 + dv;
            float4 kv = h4f((const __half2*)(QKV + g + 512));
            kv = rope4(kv, k0 + r, dv);
            __half2* kd = (__half2*)(Kh + r*FPAD + dv);
            kd[0] = __floats2half2_rn(kv.x, kv.y);
            kd[1] = __floats2half2_rn(kv.z, kv.w);
            __half2 v0 = ((const __half2*)(QKV + g + 1024))[0];
            __half2 v1 = ((const __half2*)(QKV + g + 1024))[1];
            Vt[(dv+0)*FPAD + r] = __low2half(v0);
            Vt[(dv+1)*FPAD + r] = __high2half(v0);
            Vt[(dv+2)*FPAD + r] = __low2half(v1);
            Vt[(dv+3)*FPAD + r] = __high2half(v1);
        }
        __syncthreads();
        float sacc[8][4];
        #pragma unroll
        for (int nt = 0; nt < 8; nt++)
            #pragma unroll
            for (int j = 0; j < 4; j++) sacc[nt][j] = 0.f;
        #pragma unroll
        for (int kk = 0; kk < 64; kk += 16) {
            uint32_t af[4], bf[4][4];
            LDSM4(af, uq + (uint32_t)((wid*16 + a_row)*FPAD + kk + a_k)*2);
            #pragma unroll
            for (int np = 0; np < 4; np++)
                LDSM4(bf[np], uk + (uint32_t)((np*16 + b_row)*FPAD + kk + b_k)*2);
            #pragma unroll
            for (int np = 0; np < 4; np++) {
                HMMA(sacc[2*np],   af, bf[np][0], bf[np][1]);
                HMMA(sacc[2*np+1], af, bf[np][2], bf[np][3]);
            }
        }
        if (kt >= nkt - 2) {
            #pragma unroll
            for (int nt = 0; nt < 8; nt++) {
                int col = k0 + nt*8 + ctg*2;
                #pragma unroll
                for (int j = 0; j < 4; j++) {
                    int cc = col + (j & 1);
                    int rr = row0 + ((j >> 1) << 3);
                    sacc[nt][j] = (cc <= rr) ? sacc[nt][j]*scl : -1e9f;
                }
            }
        } else {
            #pragma unroll
            for (int nt = 0; nt < 8; nt++)
                #pragma unroll
                for (int j = 0; j < 4; j++) sacc[nt][j] *= scl;
        }
        float rm0 = -1e30f, rm1 = -1e30f;
        #pragma unroll
        for (int nt = 0; nt < 8; nt++) {
            rm0 = fmaxf(rm0, fmaxf(sacc[nt][0], sacc[nt][1]));
            rm1 = fmaxf(rm1, fmaxf(sacc[nt][2], sacc[nt][3]));
        }
        rm0 = fmaxf(rm0, __shfl_xor_sync(0xffffffffu, rm0, 1));
        rm0 = fmaxf(rm0, __shfl_xor_sync(0xffffffffu, rm0, 2));
        rm1 = fmaxf(rm1, __shfl_xor_sync(0xffffffffu, rm1, 1));
        rm1 = fmaxf(rm1, __shfl_xor_sync(0xffffffffu, rm1, 2));
        float mn0 = fmaxf(m0, rm0), mn1 = fmaxf(m1, rm1);
        float c0 = __expf(m0 - mn0), c1 = __expf(m1 - mn1);
        m0 = mn0; m1 = mn1;
        float rs0 = 0.f, rs1 = 0.f;
        #pragma unroll
        for (int nt = 0; nt < 8; nt++) {
            sacc[nt][0] = __expf(sacc[nt][0] - mn0); rs0 += sacc[nt][0];
            sacc[nt][1] = __expf(sacc[nt][1] - mn0); rs0 += sacc[nt][1];
            sacc[nt][2] = __expf(sacc[nt][2] - mn1); rs1 += sacc[nt][2];
            sacc[nt][3] = __expf(sacc[nt][3] - mn1); rs1 += sacc[nt][3];
        }
        rs0 += __shfl_xor_sync(0xffffffffu, rs0, 1);
        rs0 += __shfl_xor_sync(0xffffffffu, rs0, 2);
        rs1 += __shfl_xor_sync(0xffffffffu, rs1, 1);
        rs1 += __shfl_xor_sync(0xffffffffu, rs1, 2);
        l0 = l0*c0 + rs0;
        l1 = l1*c1 + rs1;
        #pragma unroll
        for (int nh = 0; nh < 8; nh++) {
            oacc[nh][0] *= c0; oacc[nh][1] *= c0;
            oacc[nh][2] *= c1; oacc[nh][3] *= c1;
        }
        #pragma unroll
        for (int g = 0; g < 4; g++) {
            uint32_t pf[4];
            pf[0] = f22u(sacc[2*g][0],   sacc[2*g][1]);
            pf[1] = f22u(sacc[2*g][2],   sacc[2*g][3]);
            pf[2] = f22u(sacc[2*g+1][0], sacc[2*g+1][1]);
            pf[3] = f22u(sacc[2*g+1][2], sacc[2*g+1][3]);
            int kof = g*16;
            #pragma unroll
            for (int nh = 0; nh < 4; nh++) {
                uint32_t bf2[4];
                LDSM4(bf2, uv + (uint32_t)((nh*16 + b_row)*FPAD + kof + b_k)*2);
                HMMA(oacc[2*nh],   pf, bf2[0], bf2[1]);
                HMMA(oacc[2*nh+1], pf, bf2[2], bf2[3]);
            }
        }
    }
    float inv0 = 1.f / l0, inv1 = 1.f / l1;
    #pragma unroll
    for (int nh = 0; nh < 8; nh++) {
        int c = nh*8 + ctg*2;
        size_t r0 = (size_t)(b*TT + row0)*DD + h*HD + c;
        size_t r1 = (size_t)(b*TT + row0 + 8)*DD + h*HD + c;
        *(__half2*)(Oh + r0) = __floats2half2_rn(oacc[nh][0]*inv0, oacc[nh][1]*inv0);
        *(__half2*)(Oh + r1) = __floats2half2_rn(oacc[nh][2]*inv1, oacc[nh][3]*inv1);
    }
}

// ---------------- salience logits ----------------
__global__ void logits_kernel(const float* __restrict__ X, const float* __restrict__ sal_W,
                              const float* __restrict__ sal_b, const float* __restrict__ temp,
                              float* __restrict__ out) {
    int row = blockIdx.x;
    int e = threadIdx.x >> 5, lane = threadIdx.x & 31;
    const float* xr = X + (size_t)row*DD;
    float acc = 0.f;
    for (int d = lane; d < DD; d += 32)
        acc += xr[d] * sal_W[d*EH + e];
    acc = warpReduceSum(acc);
    if (lane == 0) {
        float tp = log1pf(expf(temp[e])) + 0.3f;
        out[(size_t)row*EH + e] = (acc + sal_b[e]) / tp;
    }
}

// ---------------- masked softmax pool (512 threads: 1 thread per t; 4-way split d-sum) ----------------
__global__ void __launch_bounds__(512) pool_kernel(
        const int* __restrict__ tokens, const float* __restrict__ logits,
        const float* __restrict__ X, const float* __restrict__ gate_W,
        const float* __restrict__ gate_b,
        float* __restrict__ wv_out, float* __restrict__ u_out) {
    int b = blockIdx.x >> 2, e = blockIdx.x & 3;
    int tid = threadIdx.x;
    __shared__ float ws[TT];
    __shared__ float part[4][EHD];
    // phase 1: one thread per t
    int t = tid;
    int mv = (tokens[b*TT + t] != 0);
    float lgv = logits[((size_t)b*TT + t)*EH + e];
    float sf = mv ? lgv : -1e9f;
    float mx = blockReduceMax512(sf);
    float ev = mv ? expf(sf - mx) : 0.f;
    ws[t] = ev;
    float ssum = blockReduceSum512(ev);       // syncs also publish ws[]
    float nvalid = blockReduceSum512((float)mv);
    float wsc = 1.f / (ssum + 1e-6f);
    // phase 2: weighted sum over t, split 4 ways
    int tc = tid >> 7, d = tid & 127;
    float acc = 0.f;
    const float* xb = X + ((size_t)b*TT + tc*128)*DD + e*EHD + d;
    #pragma unroll 4
    for (int tt = 0; tt < 128; tt++)
        acc += ws[tc*128 + tt] * xb[(size_t)tt*DD];
    part[tc][d] = acc;
    __syncthreads();
    if (tc == 0) {
        float a = (part[0][d] + part[1][d] + part[2][d] + part[3][d]) * wsc;
        wv_out[b*DD + e*EHD + d] = a;
        part[0][d] = a * gate_W[d];
    }
    __syncthreads();
    if (tid < 32) {
        float g = part[0][tid] + part[0][tid+32] + part[0][tid+64] + part[0][tid+96];
        g = warpReduceSum(g);
        if (tid == 0) {
            float gl = g + gate_b[0];
            u_out[b*EH + e] = (nvalid > 0.f) ? 1.f/(1.f+expf(-gl)) : 0.f;
        }
    }
}

// ---------------- fast/slow state update ----------------
__global__ void update_kernel(const float* __restrict__ wv, const float* __restrict__ u,
                              const float* __restrict__ sal_rms,
                              const float* __restrict__ fast, const float* __restrict__ slow,
                              float* __restrict__ out_fast, float* __restrict__ out_slow) {
    int b = blockIdx.x, tid = threadIdx.x;
    float4 v = ((const float4*)(wv + b*DD))[tid];
    float ss = blockReduceSum128(v.x*v.x + v.y*v.y + v.z*v.z + v.w*v.w);
    float inv = rsqrtf(ss * (1.f/DD) + 1e-6f);
    float4 sr = ((const float4*)sal_rms)[tid];
    int e = tid >> 5;
    float uu = u[b*EH + e];
    float4 f = ((const float4*)(fast + b*DD))[tid];
    float4 s = ((const float4*)(slow + b*DD))[tid];
    float4 wn;
    wn.x = v.x*inv*sr.x; wn.y = v.y*inv*sr.y; wn.z = v.z*inv*sr.z; wn.w = v.w*inv*sr.w;
    float4 nf, ns;
    nf.x = (1.f-uu)*f.x + uu*wn.x;  nf.y = (1.f-uu)*f.y + uu*wn.y;
    nf.z = (1.f-uu)*f.z + uu*wn.z;  nf.w = (1.f-uu)*f.w + uu*wn.w;
    float ud = 0.1f*uu;
    ns.x = (1.f-ud)*s.x + ud*wn.x;  ns.y = (1.f-ud)*s.y + ud*wn.y;
    ns.z = (1.f-ud)*s.z + ud*wn.z;  ns.w = (1.f-ud)*s.w + ud*wn.w;
    ((float4*)(out_fast + b*DD))[tid] = nf;
    ((float4*)(out_slow + b*DD))[tid] = ns;
}

// ---------------- launch ----------------
extern "C" void kernel_launch(void* const* d_in, const int* in_sizes, int n_in,
                              void* d_out, int out_size) {
    const int*   tokens = (const int*)  d_in[0];
    const int*   prev   = (const int*)  d_in[1];
    const float* fast   = (const float*)d_in[2];
    const float* slow   = (const float*)d_in[3];
    const float* embed  = (const float*)d_in[4];
    const float* ctx_W  = (const float*)d_in[5];
    const float* ctx_b  = (const float*)d_in[6];
    const float* etab   = (const float*)d_in[7];
    const float* egate  = (const float*)d_in[8];
    const float* ln1    = (const float*)d_in[9];
    const float* Wq     = (const float*)d_in[10];
    const float* bq     = (const float*)d_in[11];
    const float* Wk     = (const float*)d_in[12];
    const float* bk     = (const float*)d_in[13];
    const float* Wv     = (const float*)d_in[14];
    const float* bv     = (const float*)d_in[15];
    const float* Wo     = (const float*)d_in[16];
    const float* bo     = (const float*)d_in[17];
    const float* ln2    = (const float*)d_in[18];
    const float* W1     = (const float*)d_in[19];
    const float* W2     = (const float*)d_in[20];
    const float* ln_f   = (const float*)d_in[21];
    const float* sal_W  = (const float*)d_in[22];
    const float* sal_b  = (const float*)d_in[23];
    const float* temp   = (const float*)d_in[24];
    const float* gate_W = (const float*)d_in[25];
    const float* gate_b = (const float*)d_in[26];
    const float* sal_rms= (const float*)d_in[27];
    float* out = (float*)d_out;

    float *gx, *gctx, *glog, *gwv, *gu;
    __half *gqkv, *nx, *at, *ff;
    __half *wA, *w1, *w2;
    cudaGetSymbolAddress((void**)&gx,   g_x);
    cudaGetSymbolAddress((void**)&gqkv, g_qkv);
    cudaGetSymbolAddress((void**)&gctx, g_ctx);
    cudaGetSymbolAddress((void**)&glog, g_logits);
    cudaGetSymbolAddress((void**)&gwv,  g_wv);
    cudaGetSymbolAddress((void**)&gu,   g_u);
    cudaGetSymbolAddress((void**)&nx,   g_nx);
    cudaGetSymbolAddress((void**)&at,   g_at);
    cudaGetSymbolAddress((void**)&ff,   g_ff);
    cudaGetSymbolAddress((void**)&wA,   g_wqkvo);
    cudaGetSymbolAddress((void**)&w1,   g_w1);
    cudaGetSymbolAddress((void**)&w2,   g_w2);

    cudaFuncSetAttribute(hgemm<0>, cudaFuncAttributeMaxDynamicSharedMemorySize, HSMEM);
    cudaFuncSetAttribute(hgemm<1>, cudaFuncAttributeMaxDynamicSharedMemorySize, HSMEM);
    cudaFuncSetAttribute(hgemm<4>, cudaFuncAttributeMaxDynamicSharedMemorySize, HSMEM);
    cudaFuncSetAttribute(hgemm_ffn, cudaFuncAttributeMaxDynamicSharedMemorySize, HSMEM);
    cudaFuncSetAttribute(flash_kernel, cudaFuncAttributeMaxDynamicSharedMemorySize, FSMEM);

    dim3 tb(32, 8);
    dim3 gD(NTOK/128, DD/128);
    dim3 gQKV(NTOK/128, (3*DD)/128);
    dim3 gFF(NTOK/128, FF/64);

    // ncu captures launch #4 -> fused-QKV hgemm.
    tsplit4_kernel<<<dim3(DD/32, DD/32, 4*LL), tb>>>(Wq, Wk, Wv, Wo, wA);                // 1
    ctx_kernel<<<BB, 512>>>(fast, slow, ctx_W, ctx_b, gctx);                             // 2
    embed_fused_kernel<<<NTOK, 128>>>(tokens, prev, embed, gctx, etab, egate, ln1,
                                      gx, nx);                                           // 3

    for (int l = 0; l < LL; l++) {
        size_t wo  = (size_t)l*4*DD*DD;
        size_t w1o = (size_t)l*2*FF*DD;
        size_t w2o = (size_t)l*DD*FF;
        if (l > 0)
            rmsnorm_half_kernel<<<NTOK, 128>>>(gx, ln1 + l*DD, nx);
        hgemm<0><<<gQKV, 256, HSMEM>>>(nx, wA + wo,
                                       bq + l*DD, bk + l*DD, bv + l*DD,
                                       nullptr, nullptr, gqkv, NTOK, 3*DD, DD);
        if (l == 0) {
            tsplitW1_kernel<<<dim3(FF/32, DD/32, 2*LL), tb>>>(W1, w1);
            tsplit_kernel<<<dim3(DD/32, FF/32, LL), tb>>>(W2, DD, (size_t)FF*DD, w2, (size_t)DD*FF, FF);
        }
        flash_kernel<<<dim3(TT/128, BB*HH), 256, FSMEM>>>(gqkv, at);
        hgemm<1><<<gD, 256, HSMEM>>>(at, wA + wo + (size_t)1536*DD,
                                     bo + l*DD, nullptr, nullptr, gx,
                                     gx, nullptr, NTOK, DD, DD);
        rmsnorm_half_kernel<<<NTOK, 128>>>(gx, ln2 + l*DD, nx);
        hgemm_ffn<<<gFF, 256, HSMEM>>>(nx, w1 + w1o, w1 + w1o + (size_t)FF*DD,
                                       ff, NTOK, FF, DD);
        hgemm<4><<<gD, 256, HSMEM>>>(ff, w2 + w2o,
                                     nullptr, nullptr, nullptr, gx,
                                     gx, nullptr, NTOK, DD, FF);
    }
    rmsnorm_kernel<<<NTOK, 128>>>(gx, ln_f, out);
    logits_kernel<<<NTOK, 128>>>(out, sal_W, sal_b, temp, glog);
    pool_kernel<<<BB*EH, 512>>>(tokens, glog, out, gate_W, gate_b, gwv, gu);
    update_kernel<<<BB, 128>>>(gwv, gu, sal_rms, fast, slow,
                               out + (size_t)NTOK*DD,
                               out + (size_t)NTOK*DD + BB*DD);
}

// round 15
// speedup vs baseline: 1.3602x; 1.0025x over previous
#include <cuda_runtime.h>
#include <cuda_fp16.h>
#include <math.h>
#include <stdint.h>

// ---------------- problem constants ----------------
#define BB 32
#define TT 512
#define DD 512
#define LL 6
#define HH 8
#define HD 64
#define FF 2048      // 4*D
#define EH 4
#define EHD 128
#define MM 100000u
#define OVL 64
#define NTOK (BB*TT)   // 16384

// ---------------- scratch ----------------
__device__ float g_x[NTOK*DD];
__device__ float g_ctx[BB*DD];
__device__ float g_logits[NTOK*EH];
__device__ float g_wv[BB*DD];
__device__ float g_u[BB*EH];
// fp16 activations
__device__ __half g_qkv[(size_t)NTOK*3*DD];
__device__ __half g_nx[NTOK*DD];
__device__ __half g_at[NTOK*DD];
__device__ __half g_ff[(size_t)NTOK*FF];
// transposed fp16 weights: [N][K]
__device__ __half g_wqkvo[(size_t)LL*4*DD*DD];
__device__ __half g_w1[(size_t)LL*2*FF*DD];
__device__ __half g_w2[(size_t)LL*DD*FF];

// ---------------- PTX helpers ----------------
__device__ __forceinline__ uint32_t smem_to_u32(const void* p) {
    uint32_t a;
    asm("{ .reg .u64 t; cvta.to.shared.u64 t, %1; cvt.u32.u64 %0, t; }" : "=r"(a) : "l"(p));
    return a;
}
__device__ __forceinline__ void cp16(uint32_t dst, const void* src) {
    asm volatile("cp.async.cg.shared.global [%0], [%1], 16;" :: "r"(dst), "l"(src));
}
#define CP_COMMIT() asm volatile("cp.async.commit_group;" ::: "memory")
#define CP_WAIT2()  asm volatile("cp.async.wait_group 2;" ::: "memory")

#define LDSM4(r, addr) \
    asm volatile("ldmatrix.sync.aligned.m8n8.x4.shared.b16 {%0,%1,%2,%3}, [%4];" \
        : "=r"((r)[0]), "=r"((r)[1]), "=r"((r)[2]), "=r"((r)[3]) : "r"(addr))

#define HMMA(c, a, b0, b1) \
    asm volatile("mma.sync.aligned.m16n8k16.row.col.f32.f16.f16.f32 " \
        "{%0,%1,%2,%3}, {%4,%5,%6,%7}, {%8,%9}, {%0,%1,%2,%3};" \
        : "+f"((c)[0]), "+f"((c)[1]), "+f"((c)[2]), "+f"((c)[3]) \
        : "r"((a)[0]), "r"((a)[1]), "r"((a)[2]), "r"((a)[3]), "r"(b0), "r"(b1))

__device__ __forceinline__ uint32_t f22u(float a, float b) {
    __half2 h = __floats2half2_rn(a, b);
    return *(uint32_t*)&h;
}

// ---------------- reduction helpers ----------------
__device__ __forceinline__ float warpReduceSum(float v) {
    #pragma unroll
    for (int o = 16; o; o >>= 1) v += __shfl_xor_sync(0xffffffffu, v, o);
    return v;
}
__device__ __forceinline__ float warpReduceMax(float v) {
    #pragma unroll
    for (int o = 16; o; o >>= 1) v = fmaxf(v, __shfl_xor_sync(0xffffffffu, v, o));
    return v;
}
__device__ __forceinline__ float blockReduceSum128(float v) {
    __shared__ float sm[4];
    __syncthreads();
    v = warpReduceSum(v);
    if ((threadIdx.x & 31) == 0) sm[threadIdx.x >> 5] = v;
    __syncthreads();
    return sm[0] + sm[1] + sm[2] + sm[3];
}
__device__ __forceinline__ float blockReduceSum512(float v) {
    __shared__ float sm[16];
    __syncthreads();
    v = warpReduceSum(v);
    if ((threadIdx.x & 31) == 0) sm[threadIdx.x >> 5] = v;
    __syncthreads();
    float r = 0.f;
    #pragma unroll
    for (int i = 0; i < 16; i++) r += sm[i];
    return r;
}
__device__ __forceinline__ float blockReduceMax512(float v) {
    __shared__ float sm[16];
    __syncthreads();
    v = warpReduceMax(v);
    if ((threadIdx.x & 31) == 0) sm[threadIdx.x >> 5] = v;
    __syncthreads();
    float r = -1e30f;
    #pragma unroll
    for (int i = 0; i < 16; i++) r = fmaxf(r, sm[i]);
    return r;
}
// group reduce: 512 threads = 4 groups of 4 warps; sum within each 128-thread group
__device__ __forceinline__ float groupReduceSum128of512(float v) {
    __shared__ float sm[16];
    __syncthreads();
    v = warpReduceSum(v);
    if ((threadIdx.x & 31) == 0) sm[threadIdx.x >> 5] = v;
    __syncthreads();
    int g4 = (threadIdx.x >> 7) << 2;
    return sm[g4] + sm[g4+1] + sm[g4+2] + sm[g4+3];
}

// ---------------- 4-source transpose to fp16 (Wq/Wk/Wv/Wo stacked) ----------------
__global__ void tsplit4_kernel(const float* __restrict__ s0, const float* __restrict__ s1,
                               const float* __restrict__ s2, const float* __restrict__ s3,
                               __half* __restrict__ dst) {
    __shared__ float t[32][33];
    int z = blockIdx.z;
    int l = z >> 2, sel = z & 3;
    const float* S = (sel == 0 ? s0 : sel == 1 ? s1 : sel == 2 ? s2 : s3) + (size_t)l*DD*DD;
    __half* Hd = dst + (size_t)z*DD*DD;
    int n0 = blockIdx.x*32, k0 = blockIdx.y*32;
    int x = threadIdx.x, y = threadIdx.y;
    #pragma unroll
    for (int i = 0; i < 32; i += 8) t[y+i][x] = S[(size_t)(k0+y+i)*DD + n0+x];
    __syncthreads();
    #pragma unroll
    for (int i = 0; i < 32; i += 8)
        Hd[(size_t)(n0+y+i)*DD + k0+x] = __float2half_rn(t[x][y+i]);
}

// ---------------- generic transpose to fp16 ----------------
__global__ void tsplit_kernel(const float* __restrict__ src, int ldsrc, size_t srcStride,
                              __half* __restrict__ dst, size_t dstStride, int K) {
    __shared__ float t[32][33];
    int l = blockIdx.z;
    const float* S = src + (size_t)l*srcStride;
    __half* Hd = dst + (size_t)l*dstStride;
    int n0 = blockIdx.x*32, k0 = blockIdx.y*32;
    int x = threadIdx.x, y = threadIdx.y;
    #pragma unroll
    for (int i = 0; i < 32; i += 8) t[y+i][x] = S[(size_t)(k0+y+i)*ldsrc + n0+x];
    __syncthreads();
    #pragma unroll
    for (int i = 0; i < 32; i += 8)
        Hd[(size_t)(n0+y+i)*K + k0+x] = __float2half_rn(t[x][y+i]);
}

// ---------------- W1 transpose to fp16 ----------------
__global__ void tsplitW1_kernel(const float* __restrict__ W1, __half* __restrict__ dst) {
    __shared__ float t[32][33];
    int z = blockIdx.z;
    int l = z >> 1, half = z & 1;
    const float* S = W1 + (size_t)l*DD*2*FF + (size_t)half*FF;
    __half* Hd = dst + (size_t)l*2*FF*DD + (size_t)half*FF*DD;
    int n0 = blockIdx.x*32, k0 = blockIdx.y*32;
    int x = threadIdx.x, y = threadIdx.y;
    #pragma unroll
    for (int i = 0; i < 32; i += 8) t[y+i][x] = S[(size_t)(k0+y+i)*(2*FF) + n0+x];
    __syncthreads();
    #pragma unroll
    for (int i = 0; i < 32; i += 8)
        Hd[(size_t)(n0+y+i)*DD + k0+x] = __float2half_rn(t[x][y+i]);
}

// ---------------- fp16 HMMA GEMM (single pass, 4-stage cp.async) ----------------
// MODE 0: +bias3 (QKV select), fp16 out ; 1: +bias +res, fp32 out ; 4: +res, fp32 out
#define TILE_B 10240
#define STAGE_B 20480
#define HSMEM (4*STAGE_B)

__device__ __forceinline__ void load_stage(uint32_t sb,
        const __half* A, const __half* B, int K, int kof, int tid) {
    #pragma unroll
    for (int i = 0; i < 2; i++) {
        int e = tid + i*256;
        int row = e >> 2, seg = e & 3;
        uint32_t off = (uint32_t)(row*80 + seg*16);
        size_t g = (size_t)row*K + kof + seg*8;
        cp16(sb + off,          A + g);
        cp16(sb + TILE_B + off, B + g);
    }
}

template<int MODE>
__global__ void __launch_bounds__(256, 2)
hgemm(const __half* __restrict__ A, const __half* __restrict__ B,
      const float* __restrict__ bias, const float* __restrict__ bias2,
      const float* __restrict__ bias3,
      const float* __restrict__ Res,
      float* __restrict__ C, __half* __restrict__ OutH,
      int M, int N, int K) {
    extern __shared__ char dsm[];
    uint32_t sb = smem_to_u32(dsm);
    int tid = threadIdx.x, lane = tid & 31, wid = tid >> 5;
    int m0 = blockIdx.x * 128, n0 = blockIdx.y * 128;
    int wm = (wid & 1) * 64, wn = (wid >> 1) * 32;
    const __half* Ab = A + (size_t)m0*K;
    const __half* Bb = B + (size_t)n0*K;
    int NC = K >> 5;

    load_stage(sb,             Ab, Bb, K, 0,  tid); CP_COMMIT();
    load_stage(sb + STAGE_B,   Ab, Bb, K, 32, tid); CP_COMMIT();
    load_stage(sb + 2*STAGE_B, Ab, Bb, K, 64, tid); CP_COMMIT();

    float acc[4][4][4];
    #pragma unroll
    for (int a = 0; a < 4; a++)
        #pragma unroll
        for (int b = 0; b < 4; b++)
            #pragma unroll
            for (int c = 0; c < 4; c++) acc[a][b][c] = 0.f;

    const int a_row = lane & 15;
    const int a_k   = (lane >> 4) * 8;
    const int b_row = (lane & 7) + ((lane >> 4) << 3);
    const int b_k   = ((lane >> 3) & 1) * 8;

    for (int i = 0; i < NC; i++) {
        CP_WAIT2();
        __syncthreads();
        if (i + 3 < NC)
            load_stage(sb + (uint32_t)((i+3) & 3)*STAGE_B, Ab, Bb, K, (i+3)*32, tid);
        CP_COMMIT();
        uint32_t st = sb + (uint32_t)(i & 3)*STAGE_B;
        #pragma unroll
        for (int kk = 0; kk < 32; kk += 16) {
            uint32_t a4[4][4], b2[2][4];
            #pragma unroll
            for (int mt = 0; mt < 4; mt++) {
                uint32_t ad = st + (uint32_t)((wm + mt*16 + a_row)*80 + (kk + a_k)*2);
                LDSM4(a4[mt], ad);
            }
            #pragma unroll
            for (int np = 0; np < 2; np++) {
                uint32_t bd = st + TILE_B + (uint32_t)((wn + np*16 + b_row)*80 + (kk + b_k)*2);
                LDSM4(b2[np], bd);
            }
            #pragma unroll
            for (int mt = 0; mt < 4; mt++)
                #pragma unroll
                for (int nt = 0; nt < 4; nt++)
                    HMMA(acc[mt][nt], a4[mt], b2[nt>>1][(nt&1)*2], b2[nt>>1][(nt&1)*2+1]);
        }
    }

    int gid = lane >> 2, ctg = lane & 3;
    #pragma unroll
    for (int mt = 0; mt < 4; mt++)
        #pragma unroll
        for (int nt = 0; nt < 4; nt++) {
            int r0 = m0 + wm + mt*16 + gid;
            int cc = n0 + wn + nt*8 + ctg*2;
            float2 v0 = make_float2(acc[mt][nt][0], acc[mt][nt][1]);
            float2 v1 = make_float2(acc[mt][nt][2], acc[mt][nt][3]);
            if (MODE == 0) {
                const float* bp = (cc < 512) ? (bias + cc)
                                : (cc < 1024) ? (bias2 + cc - 512) : (bias3 + cc - 1024);
                float2 bb = *(const float2*)bp;
                v0.x += bb.x; v0.y += bb.y; v1.x += bb.x; v1.y += bb.y;
                *(__half2*)(OutH + (size_t)r0*N + cc)     = __floats2half2_rn(v0.x, v0.y);
                *(__half2*)(OutH + (size_t)(r0+8)*N + cc) = __floats2half2_rn(v1.x, v1.y);
            } else {
                if (MODE == 1) {
                    float2 bb = *(const float2*)(bias + cc);
                    v0.x += bb.x; v0.y += bb.y; v1.x += bb.x; v1.y += bb.y;
                }
                float2 ra = *(const float2*)(Res + (size_t)r0*N + cc);
                float2 rb = *(const float2*)(Res + (size_t)(r0+8)*N + cc);
                v0.x += ra.x; v0.y += ra.y; v1.x += rb.x; v1.y += rb.y;
                *(float2*)(C + (size_t)r0*N + cc) = v0;
                *(float2*)(C + (size_t)(r0+8)*N + cc) = v1;
            }
        }
}

// ---------------- fused gate+value FFN GEMM ----------------
#define FT_BG 10240
#define FT_BV 15360

__device__ __forceinline__ void load_stage_ffn(uint32_t sb,
        const __half* A, const __half* Bg, const __half* Bv, int K, int kof, int tid) {
    #pragma unroll
    for (int i = 0; i < 2; i++) {
        int e = tid + i*256;
        int row = e >> 2, seg = e & 3;
        uint32_t off = (uint32_t)(row*80 + seg*16);
        cp16(sb + off, A + (size_t)row*K + kof + seg*8);
    }
    {
        int row = tid >> 2, seg = tid & 3;
        uint32_t off = (uint32_t)(row*80 + seg*16);
        size_t g = (size_t)row*K + kof + seg*8;
        cp16(sb + FT_BG + off, Bg + g);
        cp16(sb + FT_BV + off, Bv + g);
    }
}

__global__ void __launch_bounds__(256, 2)
hgemm_ffn(const __half* __restrict__ A, const __half* __restrict__ Bg,
          const __half* __restrict__ Bv, __half* __restrict__ Out,
          int M, int N, int K) {
    extern __shared__ char dsm[];
    uint32_t sb = smem_to_u32(dsm);
    int tid = threadIdx.x, lane = tid & 31, wid = tid >> 5;
    int m0 = blockIdx.x * 128, n0 = blockIdx.y * 64;
    int wm = (wid & 1) * 64, wn = (wid >> 1) * 16;
    const __half* Ab  = A  + (size_t)m0*K;
    const __half* Bgb = Bg + (size_t)n0*K;
    const __half* Bvb = Bv + (size_t)n0*K;
    int NC = K >> 5;

    load_stage_ffn(sb,             Ab, Bgb, Bvb, K, 0,  tid); CP_COMMIT();
    load_stage_ffn(sb + STAGE_B,   Ab, Bgb, Bvb, K, 32, tid); CP_COMMIT();
    load_stage_ffn(sb + 2*STAGE_B, Ab, Bgb, Bvb, K, 64, tid); CP_COMMIT();

    float ag[4][2][4], av[4][2][4];
    #pragma unroll
    for (int a = 0; a < 4; a++)
        #pragma unroll
        for (int b = 0; b < 2; b++)
            #pragma unroll
            for (int c = 0; c < 4; c++) { ag[a][b][c] = 0.f; av[a][b][c] = 0.f; }

    const int a_row = lane & 15;
    const int a_k   = (lane >> 4) * 8;
    const int b_row = (lane & 7) + ((lane >> 4) << 3);
    const int b_k   = ((lane >> 3) & 1) * 8;

    for (int i = 0; i < NC; i++) {
        CP_WAIT2();
        __syncthreads();
        if (i + 3 < NC)
            load_stage_ffn(sb + (uint32_t)((i+3) & 3)*STAGE_B, Ab, Bgb, Bvb, K, (i+3)*32, tid);
        CP_COMMIT();
        uint32_t st = sb + (uint32_t)(i & 3)*STAGE_B;
        #pragma unroll
        for (int kk = 0; kk < 32; kk += 16) {
            uint32_t a4[4][4], bg[4], bv2[4];
            #pragma unroll
            for (int mt = 0; mt < 4; mt++) {
                uint32_t ad = st + (uint32_t)((wm + mt*16 + a_row)*80 + (kk + a_k)*2);
                LDSM4(a4[mt], ad);
            }
            uint32_t brow = (uint32_t)((wn + b_row)*80 + (kk + b_k)*2);
            LDSM4(bg,  st + FT_BG + brow);
            LDSM4(bv2, st + FT_BV + brow);
            #pragma unroll
            for (int mt = 0; mt < 4; mt++) {
                HMMA(ag[mt][0], a4[mt], bg[0],  bg[1]);
                HMMA(ag[mt][1], a4[mt], bg[2],  bg[3]);
                HMMA(av[mt][0], a4[mt], bv2[0], bv2[1]);
                HMMA(av[mt][1], a4[mt], bv2[2], bv2[3]);
            }
        }
    }

    int gid = lane >> 2, ctg = lane & 3;
    #pragma unroll
    for (int mt = 0; mt < 4; mt++)
        #pragma unroll
        for (int nt = 0; nt < 2; nt++) {
            int r0 = m0 + wm + mt*16 + gid;
            int cc = n0 + wn + nt*8 + ctg*2;
            float g0 = ag[mt][nt][0], g1 = ag[mt][nt][1];
            float g2 = ag[mt][nt][2], g3 = ag[mt][nt][3];
            float s0 = g0/(1.f+__expf(-g0))*av[mt][nt][0];
            float s1 = g1/(1.f+__expf(-g1))*av[mt][nt][1];
            float s2 = g2/(1.f+__expf(-g2))*av[mt][nt][2];
            float s3 = g3/(1.f+__expf(-g3))*av[mt][nt][3];
            *(__half2*)(Out + (size_t)r0*N + cc)     = __floats2half2_rn(s0, s1);
            *(__half2*)(Out + (size_t)(r0+8)*N + cc) = __floats2half2_rn(s2, s3);
        }
}

// ---------------- context projection ----------------
__global__ void ctx_kernel(const float* __restrict__ fast, const float* __restrict__ slow,
                           const float* __restrict__ W, const float* __restrict__ bias,
                           float* __restrict__ out) {
    int b = blockIdx.x, d = threadIdx.x;
    float acc = bias[d];
    const float* fb = fast + b*DD;
    const float* sb = slow + b*DD;
    for (int k = 0; k < DD; k++) acc += fb[k] * W[(size_t)k*DD + d];
    for (int k = 0; k < DD; k++) acc += sb[k] * W[(size_t)(k+DD)*DD + d];
    out[b*DD + d] = acc;
}

// ---------------- embedding + context + engram + fused layer-0 rmsnorm ----------------
__global__ void embed_fused_kernel(const int* __restrict__ tokens, const int* __restrict__ prev,
                                   const float* __restrict__ embed, const float* __restrict__ ctxadd,
                                   const float* __restrict__ etab, const float* __restrict__ egate,
                                   const float* __restrict__ ln1,
                                   float* __restrict__ X, __half* __restrict__ H) {
    int row = blockIdx.x;
    int b = row >> 9, t = row & 511;
    __shared__ unsigned int sidx[EH];
    int tid = threadIdx.x;
    if (tid < EH) {
        unsigned int xseed = 131u + (unsigned)tid * 1009u;
        unsigned int hs = 0u;
        #pragma unroll
        for (int i = 0; i < 4; i++) {
            unsigned int p = xseed; xseed = xseed * 31u + 1u;
            int pos = t - i;
            unsigned int tok = (pos >= 0) ? (unsigned)tokens[b*TT + pos]
                                          : (unsigned)prev[b*OVL + OVL + pos];
            hs += tok * p;
        }
        sidx[tid] = hs % MM;
    }
    __syncthreads();
    int d0 = tid * 4;
    int eh = tid >> 5;
    int jj = d0 & 127;
    int tok = tokens[b*TT + t];
    float4 ev = *(const float4*)(embed + (size_t)tok*DD + d0);
    float4 cv = *(const float4*)(ctxadd + b*DD + d0);
    float4 rv = *(const float4*)(etab + ((size_t)sidx[eh]*EH + eh)*EHD + jj);
    float4 gv = *(const float4*)(egate + eh*EHD + jj);
    float4 o;
    o.x = ev.x + cv.x + rv.x * (1.f/(1.f+__expf(-gv.x)));
    o.y = ev.y + cv.y + rv.y * (1.f/(1.f+__expf(-gv.y)));
    o.z = ev.z + cv.z + rv.z * (1.f/(1.f+__expf(-gv.z)));
    o.w = ev.w + cv.w + rv.w * (1.f/(1.f+__expf(-gv.w)));
    *(float4*)(X + (size_t)row*DD + d0) = o;
    float ss = blockReduceSum128(o.x*o.x + o.y*o.y + o.z*o.z + o.w*o.w);
    float inv = rsqrtf(ss * (1.f/DD) + 1e-6f);
    float4 sc = ((const float4*)ln1)[tid];
    size_t off = (size_t)row*DD + d0;
    *(__half2*)(H + off)     = __floats2half2_rn(o.x*inv*sc.x, o.y*inv*sc.y);
    *(__half2*)(H + off + 2) = __floats2half2_rn(o.z*inv*sc.z, o.w*inv*sc.w);
}

// ---------------- RMSNorm -> fp16 plane (4 rows per 512-thread block) ----------------
__global__ void __launch_bounds__(512) rmsnorm_half_kernel(
        const float* __restrict__ X, const float* __restrict__ scale,
        __half* __restrict__ H) {
    int row = blockIdx.x*4 + (threadIdx.x >> 7);
    int t128 = threadIdx.x & 127;
    float4 v = ((const float4*)(X + (size_t)row*DD))[t128];
    float ss = groupReduceSum128of512(v.x*v.x + v.y*v.y + v.z*v.z + v.w*v.w);
    float inv = rsqrtf(ss * (1.f/DD) + 1e-6f);
    float4 sc = ((const float4*)scale)[t128];
    size_t off = (size_t)row*DD + t128*4;
    *(__half2*)(H + off)     = __floats2half2_rn(v.x*inv*sc.x, v.y*inv*sc.y);
    *(__half2*)(H + off + 2) = __floats2half2_rn(v.z*inv*sc.z, v.w*inv*sc.w);
}

// ---------------- final RMSNorm (fp32 out) + fused salience logits ----------------
__global__ void rmsnorm_logits_kernel(const float* __restrict__ X, const float* __restrict__ scale,
                                      const float* __restrict__ sal_W, const float* __restrict__ sal_b,
                                      const float* __restrict__ temp,
                                      float* __restrict__ Out, float* __restrict__ logits) {
    int row = blockIdx.x;
    float4 v = ((const float4*)(X + (size_t)row*DD))[threadIdx.x];
    float ss = blockReduceSum128(v.x*v.x + v.y*v.y + v.z*v.z + v.w*v.w);
    float inv = rsqrtf(ss * (1.f/DD) + 1e-6f);
    float4 sc = ((const float4*)scale)[threadIdx.x];
    float4 o;
    o.x = v.x*inv*sc.x; o.y = v.y*inv*sc.y; o.z = v.z*inv*sc.z; o.w = v.w*inv*sc.w;
    ((float4*)(Out + (size_t)row*DD))[threadIdx.x] = o;
    // fused logits: each thread contributes its 4 d's to all 4 heads
    int d0 = threadIdx.x * 4;
    float4 w0 = *(const float4*)(sal_W + (d0+0)*EH);
    float4 w1 = *(const float4*)(sal_W + (d0+1)*EH);
    float4 w2 = *(const float4*)(sal_W + (d0+2)*EH);
    float4 w3 = *(const float4*)(sal_W + (d0+3)*EH);
    float a0 = o.x*w0.x + o.y*w1.x + o.z*w2.x + o.w*w3.x;
    float a1 = o.x*w0.y + o.y*w1.y + o.z*w2.y + o.w*w3.y;
    float a2 = o.x*w0.z + o.y*w1.z + o.z*w2.z + o.w*w3.z;
    float a3 = o.x*w0.w + o.y*w1.w + o.z*w2.w + o.w*w3.w;
    a0 = blockReduceSum128(a0);
    a1 = blockReduceSum128(a1);
    a2 = blockReduceSum128(a2);
    a3 = blockReduceSum128(a3);
    if (threadIdx.x < 4) {
        float a = (threadIdx.x == 0) ? a0 : (threadIdx.x == 1) ? a1 : (threadIdx.x == 2) ? a2 : a3;
        float tp = log1pf(expf(temp[threadIdx.x])) + 0.3f;
        logits[(size_t)row*EH + threadIdx.x] = (a + sal_b[threadIdx.x]) / tp;
    }
}

// ---------------- rope helper ----------------
__device__ __forceinline__ float4 rope4(float4 v, int t, int dv) {
    const float c = 9.210340371976184f / 64.f;
    float inv0 = __expf(-(float)dv * c);
    float inv1 = __expf(-(float)(dv+2) * c);
    float s0, c0, s1, c1;
    __sincosf((float)t * inv0, &s0, &c0);
    __sincosf((float)t * inv1, &s1, &c1);
    float4 r;
    r.x = v.x*c0 - v.y*s0;  r.y = v.x*s0 + v.y*c0;
    r.z = v.z*c1 - v.w*s1;  r.w = v.z*s1 + v.w*c1;
    return r;
}
__device__ __forceinline__ float4 h4f(const __half2* p) {
    float2 a = __half22float2(p[0]);
    float2 b = __half22float2(p[1]);
    return make_float4(a.x, a.y, b.x, b.y);
}

// ---------------- HMMA causal flash attention: BQ=128, BK=64, HD=64, fp16 QKV in ----------------
#define FPAD 72
#define FSMEM ((128 + 64 + 64)*FPAD*2)   // 36864

__global__ void __launch_bounds__(256, 2) flash_kernel(const __half* __restrict__ QKV,
        __half* __restrict__ Oh) {
    extern __shared__ char fsm[];
    __half* Qh = (__half*)fsm;
    __half* Kh = Qh + 128*FPAD;
    __half* Vt = Kh + 64*FPAD;
    uint32_t uq = smem_to_u32(Qh);
    uint32_t uk = smem_to_u32(Kh);
    uint32_t uv = smem_to_u32(Vt);

    int bh = blockIdx.y;
    int b = bh >> 3, h = bh & 7;
    int q0 = ((int)gridDim.x - 1 - (int)blockIdx.x) * 128;   // heavy tiles first
    int tid = threadIdx.x, lane = tid & 31, wid = tid >> 5;
    int gid = lane >> 2, ctg = lane & 3;
    const int a_row = lane & 15;
    const int a_k   = (lane >> 4) * 8;
    const int b_row = (lane & 7) + ((lane >> 4) << 3);
    const int b_k   = ((lane >> 3) & 1) * 8;
    size_t base = ((size_t)b*TT)*1536 + h*HD;
    const float scl = 0.125f;

    for (int i = tid; i < 128*16; i += 256) {
        int r = i >> 4, dv = (i & 15) * 4;
        float4 v = h4f((const __half2*)(QKV + base + (size_t)(q0 + r)*1536 + dv));
        v = rope4(v, q0 + r, dv);
        __half2* dst = (__half2*)(Qh + r*FPAD + dv);
        dst[0] = __floats2half2_rn(v.x, v.y);
        dst[1] = __floats2half2_rn(v.z, v.w);
    }

    float m0 = -1e30f, m1 = -1e30f, l0 = 0.f, l1 = 0.f;
    float oacc[8][4];
    #pragma unroll
    for (int i = 0; i < 8; i++)
        #pragma unroll
        for (int j = 0; j < 4; j++) oacc[i][j] = 0.f;

    int row0 = q0 + wid*16 + gid;
    int nkt = (q0 >> 6) + 2;
    for (int kt = 0; kt < nkt; kt++) {
        int k0 = kt * 64;
        __syncthreads();
        for (int i = tid; i < 64*16; i += 256) {
            int r = i >> 4, dv = (i & 15)*4;
            size_t g = base + (size_t)(k0 + r)*1536 + dv;
            float4 kv = h4f((const __half2*)(QKV + g + 512));
            kv = rope4(kv, k0 + r, dv);
            __half2* kd = (__half2*)(Kh + r*FPAD + dv);
            kd[0] = __floats2half2_rn(kv.x, kv.y);
            kd[1] = __floats2half2_rn(kv.z, kv.w);
            __half2 v0 = ((const __half2*)(QKV + g + 1024))[0];
            __half2 v1 = ((const __half2*)(QKV + g + 1024))[1];
            Vt[(dv+0)*FPAD + r] = __low2half(v0);
            Vt[(dv+1)*FPAD + r] = __high2half(v0);
            Vt[(dv+2)*FPAD + r] = __low2half(v1);
            Vt[(dv+3)*FPAD + r] = __high2half(v1);
        }
        __syncthreads();
        float sacc[8][4];
        #pragma unroll
        for (int nt = 0; nt < 8; nt++)
            #pragma unroll
            for (int j = 0; j < 4; j++) sacc[nt][j] = 0.f;
        #pragma unroll
        for (int kk = 0; kk < 64; kk += 16) {
            uint32_t af[4], bf[4][4];
            LDSM4(af, uq + (uint32_t)((wid*16 + a_row)*FPAD + kk + a_k)*2);
            #pragma unroll
            for (int np = 0; np < 4; np++)
                LDSM4(bf[np], uk + (uint32_t)((np*16 + b_row)*FPAD + kk + b_k)*2);
            #pragma unroll
            for (int np = 0; np < 4; np++) {
                HMMA(sacc[2*np],   af, bf[np][0], bf[np][1]);
                HMMA(sacc[2*np+1], af, bf[np][2], bf[np][3]);
            }
        }
        if (kt >= nkt - 2) {
            #pragma unroll
            for (int nt = 0; nt < 8; nt++) {
                int col = k0 + nt*8 + ctg*2;
                #pragma unroll
                for (int j = 0; j < 4; j++) {
                    int cc = col + (j & 1);
                    int rr = row0 + ((j >> 1) << 3);
                    sacc[nt][j] = (cc <= rr) ? sacc[nt][j]*scl : -1e9f;
                }
            }
        } else {
            #pragma unroll
            for (int nt = 0; nt < 8; nt++)
                #pragma unroll
                for (int j = 0; j < 4; j++) sacc[nt][j] *= scl;
        }
        float rm0 = -1e30f, rm1 = -1e30f;
        #pragma unroll
        for (int nt = 0; nt < 8; nt++) {
            rm0 = fmaxf(rm0, fmaxf(sacc[nt][0], sacc[nt][1]));
            rm1 = fmaxf(rm1, fmaxf(sacc[nt][2], sacc[nt][3]));
        }
        rm0 = fmaxf(rm0, __shfl_xor_sync(0xffffffffu, rm0, 1));
        rm0 = fmaxf(rm0, __shfl_xor_sync(0xffffffffu, rm0, 2));
        rm1 = fmaxf(rm1, __shfl_xor_sync(0xffffffffu, rm1, 1));
        rm1 = fmaxf(rm1, __shfl_xor_sync(0xffffffffu, rm1, 2));
        float mn0 = fmaxf(m0, rm0), mn1 = fmaxf(m1, rm1);
        float c0 = __expf(m0 - mn0), c1 = __expf(m1 - mn1);
        m0 = mn0; m1 = mn1;
        float rs0 = 0.f, rs1 = 0.f;
        #pragma unroll
        for (int nt = 0; nt < 8; nt++) {
            sacc[nt][0] = __expf(sacc[nt][0] - mn0); rs0 += sacc[nt][0];
            sacc[nt][1] = __expf(sacc[nt][1] - mn0); rs0 += sacc[nt][1];
            sacc[nt][2] = __expf(sacc[nt][2] - mn1); rs1 += sacc[nt][2];
            sacc[nt][3] = __expf(sacc[nt][3] - mn1); rs1 += sacc[nt][3];
        }
        rs0 += __shfl_xor_sync(0xffffffffu, rs0, 1);
        rs0 += __shfl_xor_sync(0xffffffffu, rs0, 2);
        rs1 += __shfl_xor_sync(0xffffffffu, rs1, 1);
        rs1 += __shfl_xor_sync(0xffffffffu, rs1, 2);
        l0 = l0*c0 + rs0;
        l1 = l1*c1 + rs1;
        #pragma unroll
        for (int nh = 0; nh < 8; nh++) {
            oacc[nh][0] *= c0; oacc[nh][1] *= c0;
            oacc[nh][2] *= c1; oacc[nh][3] *= c1;
        }
        #pragma unroll
        for (int g = 0; g < 4; g++) {
            uint32_t pf[4];
            pf[0] = f22u(sacc[2*g][0],   sacc[2*g][1]);
            pf[1] = f22u(sacc[2*g][2],   sacc[2*g][3]);
            pf[2] = f22u(sacc[2*g+1][0], sacc[2*g+1][1]);
            pf[3] = f22u(sacc[2*g+1][2], sacc[2*g+1][3]);
            int kof = g*16;
            #pragma unroll
            for (int nh = 0; nh < 4; nh++) {
                uint32_t bf2[4];
                LDSM4(bf2, uv + (uint32_t)((nh*16 + b_row)*FPAD + kof + b_k)*2);
                HMMA(oacc[2*nh],   pf, bf2[0], bf2[1]);
                HMMA(oacc[2*nh+1], pf, bf2[2], bf2[3]);
            }
        }
    }
    float inv0 = 1.f / l0, inv1 = 1.f / l1;
    #pragma unroll
    for (int nh = 0; nh < 8; nh++) {
        int c = nh*8 + ctg*2;
        size_t r0 = (size_t)(b*TT + row0)*DD + h*HD + c;
        size_t r1 = (size_t)(b*TT + row0 + 8)*DD + h*HD + c;
        *(__half2*)(Oh + r0) = __floats2half2_rn(oacc[nh][0]*inv0, oacc[nh][1]*inv0);
        *(__half2*)(Oh + r1) = __floats2half2_rn(oacc[nh][2]*inv1, oacc[nh][3]*inv1);
    }
}

// ---------------- masked softmax pool (512 threads) ----------------
__global__ void __launch_bounds__(512) pool_kernel(
        const int* __restrict__ tokens, const float* __restrict__ logits,
        const float* __restrict__ X, const float* __restrict__ gate_W,
        const float* __restrict__ gate_b,
        float* __restrict__ wv_out, float* __restrict__ u_out) {
    int b = blockIdx.x >> 2, e = blockIdx.x & 3;
    int tid = threadIdx.x;
    __shared__ float ws[TT];
    __shared__ float part[4][EHD];
    int t = tid;
    int mv = (tokens[b*TT + t] != 0);
    float lgv = logits[((size_t)b*TT + t)*EH + e];
    float sf = mv ? lgv : -1e9f;
    float mx = blockReduceMax512(sf);
    float ev = mv ? expf(sf - mx) : 0.f;
    ws[t] = ev;
    float ssum = blockReduceSum512(ev);
    float nvalid = blockReduceSum512((float)mv);
    float wsc = 1.f / (ssum + 1e-6f);
    int tc = tid >> 7, d = tid & 127;
    float acc = 0.f;
    const float* xb = X + ((size_t)b*TT + tc*128)*DD + e*EHD + d;
    #pragma unroll 4
    for (int tt = 0; tt < 128; tt++)
        acc += ws[tc*128 + tt] * xb[(size_t)tt*DD];
    part[tc][d] = acc;
    __syncthreads();
    if (tc == 0) {
        float a = (part[0][d] + part[1][d] + part[2][d] + part[3][d]) * wsc;
        wv_out[b*DD + e*EHD + d] = a;
        part[0][d] = a * gate_W[d];
    }
    __syncthreads();
    if (tid < 32) {
        float g = part[0][tid] + part[0][tid+32] + part[0][tid+64] + part[0][tid+96];
        g = warpReduceSum(g);
        if (tid == 0) {
            float gl = g + gate_b[0];
            u_out[b*EH + e] = (nvalid > 0.f) ? 1.f/(1.f+expf(-gl)) : 0.f;
        }
    }
}

// ---------------- fast/slow state update ----------------
__global__ void update_kernel(const float* __restrict__ wv, const float* __restrict__ u,
                              const float* __restrict__ sal_rms,
                              const float* __restrict__ fast, const float* __restrict__ slow,
                              float* __restrict__ out_fast, float* __restrict__ out_slow) {
    int b = blockIdx.x, tid = threadIdx.x;
    float4 v = ((const float4*)(wv + b*DD))[tid];
    float ss = blockReduceSum128(v.x*v.x + v.y*v.y + v.z*v.z + v.w*v.w);
    float inv = rsqrtf(ss * (1.f/DD) + 1e-6f);
    float4 sr = ((const float4*)sal_rms)[tid];
    int e = tid >> 5;
    float uu = u[b*EH + e];
    float4 f = ((const float4*)(fast + b*DD))[tid];
    float4 s = ((const float4*)(slow + b*DD))[tid];
    float4 wn;
    wn.x = v.x*inv*sr.x; wn.y = v.y*inv*sr.y; wn.z = v.z*inv*sr.z; wn.w = v.w*inv*sr.w;
    float4 nf, ns;
    nf.x = (1.f-uu)*f.x + uu*wn.x;  nf.y = (1.f-uu)*f.y + uu*wn.y;
    nf.z = (1.f-uu)*f.z + uu*wn.z;  nf.w = (1.f-uu)*f.w + uu*wn.w;
    float ud = 0.1f*uu;
    ns.x = (1.f-ud)*s.x + ud*wn.x;  ns.y = (1.f-ud)*s.y + ud*wn.y;
    ns.z = (1.f-ud)*s.z + ud*wn.z;  ns.w = (1.f-ud)*s.w + ud*wn.w;
    ((float4*)(out_fast + b*DD))[tid] = nf;
    ((float4*)(out_slow + b*DD))[tid] = ns;
}

// ---------------- launch ----------------
extern "C" void kernel_launch(void* const* d_in, const int* in_sizes, int n_in,
                              void* d_out, int out_size) {
    const int*   tokens = (const int*)  d_in[0];
    const int*   prev   = (const int*)  d_in[1];
    const float* fast   = (const float*)d_in[2];
    const float* slow   = (const float*)d_in[3];
    const float* embed  = (const float*)d_in[4];
    const float* ctx_W  = (const float*)d_in[5];
    const float* ctx_b  = (const float*)d_in[6];
    const float* etab   = (const float*)d_in[7];
    const float* egate  = (const float*)d_in[8];
    const float* ln1    = (const float*)d_in[9];
    const float* Wq     = (const float*)d_in[10];
    const float* bq     = (const float*)d_in[11];
    const float* Wk     = (const float*)d_in[12];
    const float* bk     = (const float*)d_in[13];
    const float* Wv     = (const float*)d_in[14];
    const float* bv     = (const float*)d_in[15];
    const float* Wo     = (const float*)d_in[16];
    const float* bo     = (const float*)d_in[17];
    const float* ln2    = (const float*)d_in[18];
    const float* W1     = (const float*)d_in[19];
    const float* W2     = (const float*)d_in[20];
    const float* ln_f   = (const float*)d_in[21];
    const float* sal_W  = (const float*)d_in[22];
    const float* sal_b  = (const float*)d_in[23];
    const float* temp   = (const float*)d_in[24];
    const float* gate_W = (const float*)d_in[25];
    const float* gate_b = (const float*)d_in[26];
    const float* sal_rms= (const float*)d_in[27];
    float* out = (float*)d_out;

    float *gx, *gctx, *glog, *gwv, *gu;
    __half *gqkv, *nx, *at, *ff;
    __half *wA, *w1, *w2;
    cudaGetSymbolAddress((void**)&gx,   g_x);
    cudaGetSymbolAddress((void**)&gqkv, g_qkv);
    cudaGetSymbolAddress((void**)&gctx, g_ctx);
    cudaGetSymbolAddress((void**)&glog, g_logits);
    cudaGetSymbolAddress((void**)&gwv,  g_wv);
    cudaGetSymbolAddress((void**)&gu,   g_u);
    cudaGetSymbolAddress((void**)&nx,   g_nx);
    cudaGetSymbolAddress((void**)&at,   g_at);
    cudaGetSymbolAddress((void**)&ff,   g_ff);
    cudaGetSymbolAddress((void**)&wA,   g_wqkvo);
    cudaGetSymbolAddress((void**)&w1,   g_w1);
    cudaGetSymbolAddress((void**)&w2,   g_w2);

    cudaFuncSetAttribute(hgemm<0>, cudaFuncAttributeMaxDynamicSharedMemorySize, HSMEM);
    cudaFuncSetAttribute(hgemm<1>, cudaFuncAttributeMaxDynamicSharedMemorySize, HSMEM);
    cudaFuncSetAttribute(hgemm<4>, cudaFuncAttributeMaxDynamicSharedMemorySize, HSMEM);
    cudaFuncSetAttribute(hgemm_ffn, cudaFuncAttributeMaxDynamicSharedMemorySize, HSMEM);
    cudaFuncSetAttribute(flash_kernel, cudaFuncAttributeMaxDynamicSharedMemorySize, FSMEM);

    dim3 tb(32, 8);
    dim3 gD(NTOK/128, DD/128);
    dim3 gQKV(NTOK/128, (3*DD)/128);
    dim3 gFF(NTOK/128, FF/64);

    // ncu captures launch #4 -> fused-QKV hgemm.
    tsplit4_kernel<<<dim3(DD/32, DD/32, 4*LL), tb>>>(Wq, Wk, Wv, Wo, wA);                // 1
    ctx_kernel<<<BB, 512>>>(fast, slow, ctx_W, ctx_b, gctx);                             // 2
    embed_fused_kernel<<<NTOK, 128>>>(tokens, prev, embed, gctx, etab, egate, ln1,
                                      gx, nx);                                           // 3

    for (int l = 0; l < LL; l++) {
        size_t wo  = (size_t)l*4*DD*DD;
        size_t w1o = (size_t)l*2*FF*DD;
        size_t w2o = (size_t)l*DD*FF;
        if (l > 0)
            rmsnorm_half_kernel<<<NTOK/4, 512>>>(gx, ln1 + l*DD, nx);
        hgemm<0><<<gQKV, 256, HSMEM>>>(nx, wA + wo,
                                       bq + l*DD, bk + l*DD, bv + l*DD,
                                       nullptr, nullptr, gqkv, NTOK, 3*DD, DD);
        if (l == 0) {
            tsplitW1_kernel<<<dim3(FF/32, DD/32, 2*LL), tb>>>(W1, w1);
            tsplit_kernel<<<dim3(DD/32, FF/32, LL), tb>>>(W2, DD, (size_t)FF*DD, w2, (size_t)DD*FF, FF);
        }
        flash_kernel<<<dim3(TT/128, BB*HH), 256, FSMEM>>>(gqkv, at);
        hgemm<1><<<gD, 256, HSMEM>>>(at, wA + wo + (size_t)1536*DD,
                                     bo + l*DD, nullptr, nullptr, gx,
                                     gx, nullptr, NTOK, DD, DD);
        rmsnorm_half_kernel<<<NTOK/4, 512>>>(gx, ln2 + l*DD, nx);
        hgemm_ffn<<<gFF, 256, HSMEM>>>(nx, w1 + w1o, w1 + w1o + (size_t)FF*DD,
                                       ff, NTOK, FF, DD);
        hgemm<4><<<gD, 256, HSMEM>>>(ff, w2 + w2o,
                                     nullptr, nullptr, nullptr, gx,
                                     gx, nullptr, NTOK, DD, FF);
    }
    rmsnorm_logits_kernel<<<NTOK, 128>>>(gx, ln_f, sal_W, sal_b, temp, out, glog);
    pool_kernel<<<BB*EH, 512>>>(tokens, glog, out, gate_W, gate_b, gwv, gu);
    update_kernel<<<BB, 128>>>(gwv, gu, sal_rms, fast, slow,
                               out + (size_t)NTOK*DD,
                               out + (size_t)NTOK*DD + BB*DD);
}

// round 16
// speedup vs baseline: 1.3712x; 1.0081x over previous
#include <cuda_runtime.h>
#include <cuda_fp16.h>
#include <math.h>
#include <stdint.h>

// ---------------- problem constants ----------------
#define BB 32
#define TT 512
#define DD 512
#define LL 6
#define HH 8
#define HD 64
#define FF 2048      // 4*D
#define EH 4
#define EHD 128
#define MM 100000u
#define OVL 64
#define NTOK (BB*TT)   // 16384

// ---------------- scratch ----------------
__device__ float g_x[NTOK*DD];
__device__ float g_ctx[BB*DD];
__device__ float g_logits[NTOK*EH];
__device__ float g_wv[BB*DD];
__device__ float g_u[BB*EH];
__device__ float2 g_ropetab[TT*32];
// fp16 activations
__device__ __half g_qkv[(size_t)NTOK*3*DD];
__device__ __half g_nx[NTOK*DD];
__device__ __half g_at[NTOK*DD];
__device__ __half g_ff[(size_t)NTOK*FF];
// transposed fp16 weights: [N][K]
__device__ __half g_wqkvo[(size_t)LL*4*DD*DD];
__device__ __half g_w1[(size_t)LL*2*FF*DD];
__device__ __half g_w2[(size_t)LL*DD*FF];

// ---------------- PTX helpers ----------------
__device__ __forceinline__ uint32_t smem_to_u32(const void* p) {
    uint32_t a;
    asm("{ .reg .u64 t; cvta.to.shared.u64 t, %1; cvt.u32.u64 %0, t; }" : "=r"(a) : "l"(p));
    return a;
}
__device__ __forceinline__ void cp16(uint32_t dst, const void* src) {
    asm volatile("cp.async.cg.shared.global [%0], [%1], 16;" :: "r"(dst), "l"(src));
}
#define CP_COMMIT() asm volatile("cp.async.commit_group;" ::: "memory")
#define CP_WAIT2()  asm volatile("cp.async.wait_group 2;" ::: "memory")

#define LDSM4(r, addr) \
    asm volatile("ldmatrix.sync.aligned.m8n8.x4.shared.b16 {%0,%1,%2,%3}, [%4];" \
        : "=r"((r)[0]), "=r"((r)[1]), "=r"((r)[2]), "=r"((r)[3]) : "r"(addr))

#define HMMA(c, a, b0, b1) \
    asm volatile("mma.sync.aligned.m16n8k16.row.col.f32.f16.f16.f32 " \
        "{%0,%1,%2,%3}, {%4,%5,%6,%7}, {%8,%9}, {%0,%1,%2,%3};" \
        : "+f"((c)[0]), "+f"((c)[1]), "+f"((c)[2]), "+f"((c)[3]) \
        : "r"((a)[0]), "r"((a)[1]), "r"((a)[2]), "r"((a)[3]), "r"(b0), "r"(b1))

__device__ __forceinline__ uint32_t f22u(float a, float b) {
    __half2 h = __floats2half2_rn(a, b);
    return *(uint32_t*)&h;
}

// ---------------- reduction helpers ----------------
__device__ __forceinline__ float warpReduceSum(float v) {
    #pragma unroll
    for (int o = 16; o; o >>= 1) v += __shfl_xor_sync(0xffffffffu, v, o);
    return v;
}
__device__ __forceinline__ float warpReduceMax(float v) {
    #pragma unroll
    for (int o = 16; o; o >>= 1) v = fmaxf(v, __shfl_xor_sync(0xffffffffu, v, o));
    return v;
}
__device__ __forceinline__ float blockReduceSum128(float v) {
    __shared__ float sm[4];
    __syncthreads();
    v = warpReduceSum(v);
    if ((threadIdx.x & 31) == 0) sm[threadIdx.x >> 5] = v;
    __syncthreads();
    return sm[0] + sm[1] + sm[2] + sm[3];
}
__device__ __forceinline__ float blockReduceSum512(float v) {
    __shared__ float sm[16];
    __syncthreads();
    v = warpReduceSum(v);
    if ((threadIdx.x & 31) == 0) sm[threadIdx.x >> 5] = v;
    __syncthreads();
    float r = 0.f;
    #pragma unroll
    for (int i = 0; i < 16; i++) r += sm[i];
    return r;
}
__device__ __forceinline__ float blockReduceMax512(float v) {
    __shared__ float sm[16];
    __syncthreads();
    v = warpReduceMax(v);
    if ((threadIdx.x & 31) == 0) sm[threadIdx.x >> 5] = v;
    __syncthreads();
    float r = -1e30f;
    #pragma unroll
    for (int i = 0; i < 16; i++) r = fmaxf(r, sm[i]);
    return r;
}
__device__ __forceinline__ float groupReduceSum128of512(float v) {
    __shared__ float sm[16];
    __syncthreads();
    v = warpReduceSum(v);
    if ((threadIdx.x & 31) == 0) sm[threadIdx.x >> 5] = v;
    __syncthreads();
    int g4 = (threadIdx.x >> 7) << 2;
    return sm[g4] + sm[g4+1] + sm[g4+2] + sm[g4+3];
}

// ---------------- rope cos/sin table (bit-identical to former inline math) ----------------
__global__ void rope_table_kernel(float2* __restrict__ tab) {
    int t = blockIdx.x, j = threadIdx.x;   // 512 x 32
    const float c = 9.210340371976184f / 64.f;
    float inv = __expf(-(float)(2*j) * c);
    float s, co;
    __sincosf((float)t * inv, &s, &co);
    tab[t*32 + j] = make_float2(co, s);
}

// ---------------- 4-source transpose to fp16 (Wq/Wk/Wv/Wo stacked) ----------------
__global__ void tsplit4_kernel(const float* __restrict__ s0, const float* __restrict__ s1,
                               const float* __restrict__ s2, const float* __restrict__ s3,
                               __half* __restrict__ dst) {
    __shared__ float t[32][33];
    int z = blockIdx.z;
    int l = z >> 2, sel = z & 3;
    const float* S = (sel == 0 ? s0 : sel == 1 ? s1 : sel == 2 ? s2 : s3) + (size_t)l*DD*DD;
    __half* Hd = dst + (size_t)z*DD*DD;
    int n0 = blockIdx.x*32, k0 = blockIdx.y*32;
    int x = threadIdx.x, y = threadIdx.y;
    #pragma unroll
    for (int i = 0; i < 32; i += 8) t[y+i][x] = S[(size_t)(k0+y+i)*DD + n0+x];
    __syncthreads();
    #pragma unroll
    for (int i = 0; i < 32; i += 8)
        Hd[(size_t)(n0+y+i)*DD + k0+x] = __float2half_rn(t[x][y+i]);
}

// ---------------- generic transpose to fp16 ----------------
__global__ void tsplit_kernel(const float* __restrict__ src, int ldsrc, size_t srcStride,
                              __half* __restrict__ dst, size_t dstStride, int K) {
    __shared__ float t[32][33];
    int l = blockIdx.z;
    const float* S = src + (size_t)l*srcStride;
    __half* Hd = dst + (size_t)l*dstStride;
    int n0 = blockIdx.x*32, k0 = blockIdx.y*32;
    int x = threadIdx.x, y = threadIdx.y;
    #pragma unroll
    for (int i = 0; i < 32; i += 8) t[y+i][x] = S[(size_t)(k0+y+i)*ldsrc + n0+x];
    __syncthreads();
    #pragma unroll
    for (int i = 0; i < 32; i += 8)
        Hd[(size_t)(n0+y+i)*K + k0+x] = __float2half_rn(t[x][y+i]);
}

// ---------------- W1 transpose to fp16 ----------------
__global__ void tsplitW1_kernel(const float* __restrict__ W1, __half* __restrict__ dst) {
    __shared__ float t[32][33];
    int z = blockIdx.z;
    int l = z >> 1, half = z & 1;
    const float* S = W1 + (size_t)l*DD*2*FF + (size_t)half*FF;
    __half* Hd = dst + (size_t)l*2*FF*DD + (size_t)half*FF*DD;
    int n0 = blockIdx.x*32, k0 = blockIdx.y*32;
    int x = threadIdx.x, y = threadIdx.y;
    #pragma unroll
    for (int i = 0; i < 32; i += 8) t[y+i][x] = S[(size_t)(k0+y+i)*(2*FF) + n0+x];
    __syncthreads();
    #pragma unroll
    for (int i = 0; i < 32; i += 8)
        Hd[(size_t)(n0+y+i)*DD + k0+x] = __float2half_rn(t[x][y+i]);
}

// ---------------- fp16 HMMA GEMM (single pass, 4-stage cp.async) ----------------
// MODE 0: +bias3 (QKV select), fp16 out ; 1: +bias +res, fp32 out ; 4: +res, fp32 out
#define TILE_B 10240
#define STAGE_B 20480
#define HSMEM (4*STAGE_B)

__device__ __forceinline__ void load_stage(uint32_t sb,
        const __half* A, const __half* B, int K, int kof, int tid) {
    #pragma unroll
    for (int i = 0; i < 2; i++) {
        int e = tid + i*256;
        int row = e >> 2, seg = e & 3;
        uint32_t off = (uint32_t)(row*80 + seg*16);
        size_t g = (size_t)row*K + kof + seg*8;
        cp16(sb + off,          A + g);
        cp16(sb + TILE_B + off, B + g);
    }
}

template<int MODE>
__global__ void __launch_bounds__(256, 2)
hgemm(const __half* __restrict__ A, const __half* __restrict__ B,
      const float* __restrict__ bias, const float* __restrict__ bias2,
      const float* __restrict__ bias3,
      const float* __restrict__ Res,
      float* __restrict__ C, __half* __restrict__ OutH,
      int M, int N, int K) {
    extern __shared__ char dsm[];
    uint32_t sb = smem_to_u32(dsm);
    int tid = threadIdx.x, lane = tid & 31, wid = tid >> 5;
    int m0 = blockIdx.x * 128, n0 = blockIdx.y * 128;
    int wm = (wid & 1) * 64, wn = (wid >> 1) * 32;
    const __half* Ab = A + (size_t)m0*K;
    const __half* Bb = B + (size_t)n0*K;
    int NC = K >> 5;

    load_stage(sb,             Ab, Bb, K, 0,  tid); CP_COMMIT();
    load_stage(sb + STAGE_B,   Ab, Bb, K, 32, tid); CP_COMMIT();
    load_stage(sb + 2*STAGE_B, Ab, Bb, K, 64, tid); CP_COMMIT();

    float acc[4][4][4];
    #pragma unroll
    for (int a = 0; a < 4; a++)
        #pragma unroll
        for (int b = 0; b < 4; b++)
            #pragma unroll
            for (int c = 0; c < 4; c++) acc[a][b][c] = 0.f;

    const int a_row = lane & 15;
    const int a_k   = (lane >> 4) * 8;
    const int b_row = (lane & 7) + ((lane >> 4) << 3);
    const int b_k   = ((lane >> 3) & 1) * 8;

    for (int i = 0; i < NC; i++) {
        CP_WAIT2();
        __syncthreads();
        if (i + 3 < NC)
            load_stage(sb + (uint32_t)((i+3) & 3)*STAGE_B, Ab, Bb, K, (i+3)*32, tid);
        CP_COMMIT();
        uint32_t st = sb + (uint32_t)(i & 3)*STAGE_B;
        #pragma unroll
        for (int kk = 0; kk < 32; kk += 16) {
            uint32_t a4[4][4], b2[2][4];
            #pragma unroll
            for (int mt = 0; mt < 4; mt++) {
                uint32_t ad = st + (uint32_t)((wm + mt*16 + a_row)*80 + (kk + a_k)*2);
                LDSM4(a4[mt], ad);
            }
            #pragma unroll
            for (int np = 0; np < 2; np++) {
                uint32_t bd = st + TILE_B + (uint32_t)((wn + np*16 + b_row)*80 + (kk + b_k)*2);
                LDSM4(b2[np], bd);
            }
            #pragma unroll
            for (int mt = 0; mt < 4; mt++)
                #pragma unroll
                for (int nt = 0; nt < 4; nt++)
                    HMMA(acc[mt][nt], a4[mt], b2[nt>>1][(nt&1)*2], b2[nt>>1][(nt&1)*2+1]);
        }
    }

    int gid = lane >> 2, ctg = lane & 3;
    #pragma unroll
    for (int mt = 0; mt < 4; mt++)
        #pragma unroll
        for (int nt = 0; nt < 4; nt++) {
            int r0 = m0 + wm + mt*16 + gid;
            int cc = n0 + wn + nt*8 + ctg*2;
            float2 v0 = make_float2(acc[mt][nt][0], acc[mt][nt][1]);
            float2 v1 = make_float2(acc[mt][nt][2], acc[mt][nt][3]);
            if (MODE == 0) {
                const float* bp = (cc < 512) ? (bias + cc)
                                : (cc < 1024) ? (bias2 + cc - 512) : (bias3 + cc - 1024);
                float2 bb = *(const float2*)bp;
                v0.x += bb.x; v0.y += bb.y; v1.x += bb.x; v1.y += bb.y;
                *(__half2*)(OutH + (size_t)r0*N + cc)     = __floats2half2_rn(v0.x, v0.y);
                *(__half2*)(OutH + (size_t)(r0+8)*N + cc) = __floats2half2_rn(v1.x, v1.y);
            } else {
                if (MODE == 1) {
                    float2 bb = *(const float2*)(bias + cc);
                    v0.x += bb.x; v0.y += bb.y; v1.x += bb.x; v1.y += bb.y;
                }
                float2 ra = *(const float2*)(Res + (size_t)r0*N + cc);
                float2 rb = *(const float2*)(Res + (size_t)(r0+8)*N + cc);
                v0.x += ra.x; v0.y += ra.y; v1.x += rb.x; v1.y += rb.y;
                *(float2*)(C + (size_t)r0*N + cc) = v0;
                *(float2*)(C + (size_t)(r0+8)*N + cc) = v1;
            }
        }
}

// ---------------- fused gate+value FFN GEMM ----------------
#define FT_BG 10240
#define FT_BV 15360

__device__ __forceinline__ void load_stage_ffn(uint32_t sb,
        const __half* A, const __half* Bg, const __half* Bv, int K, int kof, int tid) {
    #pragma unroll
    for (int i = 0; i < 2; i++) {
        int e = tid + i*256;
        int row = e >> 2, seg = e & 3;
        uint32_t off = (uint32_t)(row*80 + seg*16);
        cp16(sb + off, A + (size_t)row*K + kof + seg*8);
    }
    {
        int row = tid >> 2, seg = tid & 3;
        uint32_t off = (uint32_t)(row*80 + seg*16);
        size_t g = (size_t)row*K + kof + seg*8;
        cp16(sb + FT_BG + off, Bg + g);
        cp16(sb + FT_BV + off, Bv + g);
    }
}

__global__ void __launch_bounds__(256, 2)
hgemm_ffn(const __half* __restrict__ A, const __half* __restrict__ Bg,
          const __half* __restrict__ Bv, __half* __restrict__ Out,
          int M, int N, int K) {
    extern __shared__ char dsm[];
    uint32_t sb = smem_to_u32(dsm);
    int tid = threadIdx.x, lane = tid & 31, wid = tid >> 5;
    int m0 = blockIdx.x * 128, n0 = blockIdx.y * 64;
    int wm = (wid & 1) * 64, wn = (wid >> 1) * 16;
    const __half* Ab  = A  + (size_t)m0*K;
    const __half* Bgb = Bg + (size_t)n0*K;
    const __half* Bvb = Bv + (size_t)n0*K;
    int NC = K >> 5;

    load_stage_ffn(sb,             Ab, Bgb, Bvb, K, 0,  tid); CP_COMMIT();
    load_stage_ffn(sb + STAGE_B,   Ab, Bgb, Bvb, K, 32, tid); CP_COMMIT();
    load_stage_ffn(sb + 2*STAGE_B, Ab, Bgb, Bvb, K, 64, tid); CP_COMMIT();

    float ag[4][2][4], av[4][2][4];
    #pragma unroll
    for (int a = 0; a < 4; a++)
        #pragma unroll
        for (int b = 0; b < 2; b++)
            #pragma unroll
            for (int c = 0; c < 4; c++) { ag[a][b][c] = 0.f; av[a][b][c] = 0.f; }

    const int a_row = lane & 15;
    const int a_k   = (lane >> 4) * 8;
    const int b_row = (lane & 7) + ((lane >> 4) << 3);
    const int b_k   = ((lane >> 3) & 1) * 8;

    for (int i = 0; i < NC; i++) {
        CP_WAIT2();
        __syncthreads();
        if (i + 3 < NC)
            load_stage_ffn(sb + (uint32_t)((i+3) & 3)*STAGE_B, Ab, Bgb, Bvb, K, (i+3)*32, tid);
        CP_COMMIT();
        uint32_t st = sb + (uint32_t)(i & 3)*STAGE_B;
        #pragma unroll
        for (int kk = 0; kk < 32; kk += 16) {
            uint32_t a4[4][4], bg[4], bv2[4];
            #pragma unroll
            for (int mt = 0; mt < 4; mt++) {
                uint32_t ad = st + (uint32_t)((wm + mt*16 + a_row)*80 + (kk + a_k)*2);
                LDSM4(a4[mt], ad);
            }
            uint32_t brow = (uint32_t)((wn + b_row)*80 + (kk + b_k)*2);
            LDSM4(bg,  st + FT_BG + brow);
            LDSM4(bv2, st + FT_BV + brow);
            #pragma unroll
            for (int mt = 0; mt < 4; mt++) {
                HMMA(ag[mt][0], a4[mt], bg[0],  bg[1]);
                HMMA(ag[mt][1], a4[mt], bg[2],  bg[3]);
                HMMA(av[mt][0], a4[mt], bv2[0], bv2[1]);
                HMMA(av[mt][1], a4[mt], bv2[2], bv2[3]);
            }
        }
    }

    int gid = lane >> 2, ctg = lane & 3;
    #pragma unroll
    for (int mt = 0; mt < 4; mt++)
        #pragma unroll
        for (int nt = 0; nt < 2; nt++) {
            int r0 = m0 + wm + mt*16 + gid;
            int cc = n0 + wn + nt*8 + ctg*2;
            float g0 = ag[mt][nt][0], g1 = ag[mt][nt][1];
            float g2 = ag[mt][nt][2], g3 = ag[mt][nt][3];
            float s0 = g0/(1.f+__expf(-g0))*av[mt][nt][0];
            float s1 = g1/(1.f+__expf(-g1))*av[mt][nt][1];
            float s2 = g2/(1.f+__expf(-g2))*av[mt][nt][2];
            float s3 = g3/(1.f+__expf(-g3))*av[mt][nt][3];
            *(__half2*)(Out + (size_t)r0*N + cc)     = __floats2half2_rn(s0, s1);
            *(__half2*)(Out + (size_t)(r0+8)*N + cc) = __floats2half2_rn(s2, s3);
        }
}

// ---------------- context projection (256 blocks, 8-way k-slice) ----------------
__global__ void __launch_bounds__(512) ctx_kernel(
        const float* __restrict__ fast, const float* __restrict__ slow,
        const float* __restrict__ W, const float* __restrict__ bias,
        float* __restrict__ out) {
    int b = blockIdx.x;
    int dl = threadIdx.x & 63;
    int d = blockIdx.y*64 + dl;
    int ks = threadIdx.x >> 6;           // 0..7
    __shared__ float sm[8][64];
    const float* fb = fast + b*DD;
    const float* sb = slow + b*DD;
    float acc = 0.f;
    #pragma unroll 4
    for (int k = ks*128; k < ks*128 + 128; k++) {
        float a = (k < DD) ? fb[k] : sb[k - DD];
        acc += a * W[(size_t)k*DD + d];
    }
    sm[ks][dl] = acc;
    __syncthreads();
    if (ks == 0) {
        float r = bias[d];
        #pragma unroll
        for (int i = 0; i < 8; i++) r += sm[i][dl];
        out[b*DD + d] = r;
    }
}

// ---------------- embedding + context + engram + fused layer-0 rmsnorm ----------------
__global__ void embed_fused_kernel(const int* __restrict__ tokens, const int* __restrict__ prev,
                                   const float* __restrict__ embed, const float* __restrict__ ctxadd,
                                   const float* __restrict__ etab, const float* __restrict__ egate,
                                   const float* __restrict__ ln1,
                                   float* __restrict__ X, __half* __restrict__ H) {
    int row = blockIdx.x;
    int b = row >> 9, t = row & 511;
    __shared__ unsigned int sidx[EH];
    int tid = threadIdx.x;
    if (tid < EH) {
        unsigned int xseed = 131u + (unsigned)tid * 1009u;
        unsigned int hs = 0u;
        #pragma unroll
        for (int i = 0; i < 4; i++) {
            unsigned int p = xseed; xseed = xseed * 31u + 1u;
            int pos = t - i;
            unsigned int tok = (pos >= 0) ? (unsigned)tokens[b*TT + pos]
                                          : (unsigned)prev[b*OVL + OVL + pos];
            hs += tok * p;
        }
        sidx[tid] = hs % MM;
    }
    __syncthreads();
    int d0 = tid * 4;
    int eh = tid >> 5;
    int jj = d0 & 127;
    int tok = tokens[b*TT + t];
    float4 ev = *(const float4*)(embed + (size_t)tok*DD + d0);
    float4 cv = *(const float4*)(ctxadd + b*DD + d0);
    float4 rv = *(const float4*)(etab + ((size_t)sidx[eh]*EH + eh)*EHD + jj);
    float4 gv = *(const float4*)(egate + eh*EHD + jj);
    float4 o;
    o.x = ev.x + cv.x + rv.x * (1.f/(1.f+__expf(-gv.x)));
    o.y = ev.y + cv.y + rv.y * (1.f/(1.f+__expf(-gv.y)));
    o.z = ev.z + cv.z + rv.z * (1.f/(1.f+__expf(-gv.z)));
    o.w = ev.w + cv.w + rv.w * (1.f/(1.f+__expf(-gv.w)));
    *(float4*)(X + (size_t)row*DD + d0) = o;
    float ss = blockReduceSum128(o.x*o.x + o.y*o.y + o.z*o.z + o.w*o.w);
    float inv = rsqrtf(ss * (1.f/DD) + 1e-6f);
    float4 sc = ((const float4*)ln1)[tid];
    size_t off = (size_t)row*DD + d0;
    *(__half2*)(H + off)     = __floats2half2_rn(o.x*inv*sc.x, o.y*inv*sc.y);
    *(__half2*)(H + off + 2) = __floats2half2_rn(o.z*inv*sc.z, o.w*inv*sc.w);
}

// ---------------- RMSNorm -> fp16 plane (4 rows per 512-thread block) ----------------
__global__ void __launch_bounds__(512) rmsnorm_half_kernel(
        const float* __restrict__ X, const float* __restrict__ scale,
        __half* __restrict__ H) {
    int row = blockIdx.x*4 + (threadIdx.x >> 7);
    int t128 = threadIdx.x & 127;
    float4 v = ((const float4*)(X + (size_t)row*DD))[t128];
    float ss = groupReduceSum128of512(v.x*v.x + v.y*v.y + v.z*v.z + v.w*v.w);
    float inv = rsqrtf(ss * (1.f/DD) + 1e-6f);
    float4 sc = ((const float4*)scale)[t128];
    size_t off = (size_t)row*DD + t128*4;
    *(__half2*)(H + off)     = __floats2half2_rn(v.x*inv*sc.x, v.y*inv*sc.y);
    *(__half2*)(H + off + 2) = __floats2half2_rn(v.z*inv*sc.z, v.w*inv*sc.w);
}

// ---------------- final RMSNorm (fp32 out) + fused salience logits ----------------
__global__ void rmsnorm_logits_kernel(const float* __restrict__ X, const float* __restrict__ scale,
                                      const float* __restrict__ sal_W, const float* __restrict__ sal_b,
                                      const float* __restrict__ temp,
                                      float* __restrict__ Out, float* __restrict__ logits) {
    int row = blockIdx.x;
    float4 v = ((const float4*)(X + (size_t)row*DD))[threadIdx.x];
    float ss = blockReduceSum128(v.x*v.x + v.y*v.y + v.z*v.z + v.w*v.w);
    float inv = rsqrtf(ss * (1.f/DD) + 1e-6f);
    float4 sc = ((const float4*)scale)[threadIdx.x];
    float4 o;
    o.x = v.x*inv*sc.x; o.y = v.y*inv*sc.y; o.z = v.z*inv*sc.z; o.w = v.w*inv*sc.w;
    ((float4*)(Out + (size_t)row*DD))[threadIdx.x] = o;
    int d0 = threadIdx.x * 4;
    float4 w0 = *(const float4*)(sal_W + (d0+0)*EH);
    float4 w1 = *(const float4*)(sal_W + (d0+1)*EH);
    float4 w2 = *(const float4*)(sal_W + (d0+2)*EH);
    float4 w3 = *(const float4*)(sal_W + (d0+3)*EH);
    float a0 = o.x*w0.x + o.y*w1.x + o.z*w2.x + o.w*w3.x;
    float a1 = o.x*w0.y + o.y*w1.y + o.z*w2.y + o.w*w3.y;
    float a2 = o.x*w0.z + o.y*w1.z + o.z*w2.z + o.w*w3.z;
    float a3 = o.x*w0.w + o.y*w1.w + o.z*w2.w + o.w*w3.w;
    a0 = blockReduceSum128(a0);
    a1 = blockReduceSum128(a1);
    a2 = blockReduceSum128(a2);
    a3 = blockReduceSum128(a3);
    if (threadIdx.x < 4) {
        float a = (threadIdx.x == 0) ? a0 : (threadIdx.x == 1) ? a1 : (threadIdx.x == 2) ? a2 : a3;
        float tp = log1pf(expf(temp[threadIdx.x])) + 0.3f;
        logits[(size_t)row*EH + threadIdx.x] = (a + sal_b[threadIdx.x]) / tp;
    }
}

// ---------------- helpers ----------------
__device__ __forceinline__ float4 h4f(const __half2* p) {
    float2 a = __half22float2(p[0]);
    float2 b = __half22float2(p[1]);
    return make_float4(a.x, a.y, b.x, b.y);
}
__device__ __forceinline__ float4 rope4t(float4 v, float2 cs0, float2 cs1) {
    float4 r;
    r.x = v.x*cs0.x - v.y*cs0.y;  r.y = v.x*cs0.y + v.y*cs0.x;
    r.z = v.z*cs1.x - v.w*cs1.y;  r.w = v.z*cs1.y + v.w*cs1.x;
    return r;
}

// ---------------- HMMA causal flash attention: BQ=128, BK=64, HD=64, fp16 QKV, table rope ----------------
#define FPAD 72
#define FSMEM ((128 + 64 + 64)*FPAD*2)   // 36864

__global__ void __launch_bounds__(256, 2) flash_kernel(const __half* __restrict__ QKV,
        const float2* __restrict__ ropetab, __half* __restrict__ Oh) {
    extern __shared__ char fsm[];
    __half* Qh = (__half*)fsm;
    __half* Kh = Qh + 128*FPAD;
    __half* Vt = Kh + 64*FPAD;
    uint32_t uq = smem_to_u32(Qh);
    uint32_t uk = smem_to_u32(Kh);
    uint32_t uv = smem_to_u32(Vt);

    int bh = blockIdx.y;
    int b = bh >> 3, h = bh & 7;
    int q0 = ((int)gridDim.x - 1 - (int)blockIdx.x) * 128;   // heavy tiles first
    int tid = threadIdx.x, lane = tid & 31, wid = tid >> 5;
    int gid = lane >> 2, ctg = lane & 3;
    const int a_row = lane & 15;
    const int a_k   = (lane >> 4) * 8;
    const int b_row = (lane & 7) + ((lane >> 4) << 3);
    const int b_k   = ((lane >> 3) & 1) * 8;
    size_t base = ((size_t)b*TT)*1536 + h*HD;
    const float scl = 0.125f;

    for (int i = tid; i < 128*16; i += 256) {
        int r = i >> 4, dv = (i & 15) * 4;
        float4 v = h4f((const __half2*)(QKV + base + (size_t)(q0 + r)*1536 + dv));
        float2 cs0 = ropetab[(q0 + r)*32 + (dv >> 1)];
        float2 cs1 = ropetab[(q0 + r)*32 + (dv >> 1) + 1];
        v = rope4t(v, cs0, cs1);
        __half2* dst = (__half2*)(Qh + r*FPAD + dv);
        dst[0] = __floats2half2_rn(v.x, v.y);
        dst[1] = __floats2half2_rn(v.z, v.w);
    }

    float m0 = -1e30f, m1 = -1e30f, l0 = 0.f, l1 = 0.f;
    float oacc[8][4];
    #pragma unroll
    for (int i = 0; i < 8; i++)
        #pragma unroll
        for (int j = 0; j < 4; j++) oacc[i][j] = 0.f;

    int row0 = q0 + wid*16 + gid;
    int nkt = (q0 >> 6) + 2;
    for (int kt = 0; kt < nkt; kt++) {
        int k0 = kt * 64;
        __syncthreads();
        for (int i = tid; i < 64*16; i += 256) {
            int r = i >> 4, dv = (i & 15)*4;
            size_t g = base + (size_t)(k0 + r)*1536 + dv;
            float4 kv = h4f((const __half2*)(QKV + g + 512));
            float2 cs0 = ropetab[(k0 + r)*32 + (dv >> 1)];
            float2 cs1 = ropetab[(k0 + r)*32 + (dv >> 1) + 1];
            kv = rope4t(kv, cs0, cs1);
            __half2* kd = (__half2*)(Kh + r*FPAD + dv);
            kd[0] = __floats2half2_rn(kv.x, kv.y);
            kd[1] = __floats2half2_rn(kv.z, kv.w);
            __half2 v0 = ((const __half2*)(QKV + g + 1024))[0];
            __half2 v1 = ((const __half2*)(QKV + g + 1024))[1];
            Vt[(dv+0)*FPAD + r] = __low2half(v0);
            Vt[(dv+1)*FPAD + r] = __high2half(v0);
            Vt[(dv+2)*FPAD + r] = __low2half(v1);
            Vt[(dv+3)*FPAD + r] = __high2half(v1);
        }
        __syncthreads();
        float sacc[8][4];
        #pragma unroll
        for (int nt = 0; nt < 8; nt++)
            #pragma unroll
            for (int j = 0; j < 4; j++) sacc[nt][j] = 0.f;
        #pragma unroll
        for (int kk = 0; kk < 64; kk += 16) {
            uint32_t af[4], bf[4][4];
            LDSM4(af, uq + (uint32_t)((wid*16 + a_row)*FPAD + kk + a_k)*2);
            #pragma unroll
            for (int np = 0; np < 4; np++)
                LDSM4(bf[np], uk + (uint32_t)((np*16 + b_row)*FPAD + kk + b_k)*2);
            #pragma unroll
            for (int np = 0; np < 4; np++) {
                HMMA(sacc[2*np],   af, bf[np][0], bf[np][1]);
                HMMA(sacc[2*np+1], af, bf[np][2], bf[np][3]);
            }
        }
        if (kt >= nkt - 2) {
            #pragma unroll
            for (int nt = 0; nt < 8; nt++) {
                int col = k0 + nt*8 + ctg*2;
                #pragma unroll
                for (int j = 0; j < 4; j++) {
                    int cc = col + (j & 1);
                    int rr = row0 + ((j >> 1) << 3);
                    sacc[nt][j] = (cc <= rr) ? sacc[nt][j]*scl : -1e9f;
                }
            }
        } else {
            #pragma unroll
            for (int nt = 0; nt < 8; nt++)
                #pragma unroll
                for (int j = 0; j < 4; j++) sacc[nt][j] *= scl;
        }
        float rm0 = -1e30f, rm1 = -1e30f;
        #pragma unroll
        for (int nt = 0; nt < 8; nt++) {
            rm0 = fmaxf(rm0, fmaxf(sacc[nt][0], sacc[nt][1]));
            rm1 = fmaxf(rm1, fmaxf(sacc[nt][2], sacc[nt][3]));
        }
        rm0 = fmaxf(rm0, __shfl_xor_sync(0xffffffffu, rm0, 1));
        rm0 = fmaxf(rm0, __shfl_xor_sync(0xffffffffu, rm0, 2));
        rm1 = fmaxf(rm1, __shfl_xor_sync(0xffffffffu, rm1, 1));
        rm1 = fmaxf(rm1, __shfl_xor_sync(0xffffffffu, rm1, 2));
        float mn0 = fmaxf(m0, rm0), mn1 = fmaxf(m1, rm1);
        float c0 = __expf(m0 - mn0), c1 = __expf(m1 - mn1);
        m0 = mn0; m1 = mn1;
        float rs0 = 0.f, rs1 = 0.f;
        #pragma unroll
        for (int nt = 0; nt < 8; nt++) {
            sacc[nt][0] = __expf(sacc[nt][0] - mn0); rs0 += sacc[nt][0];
            sacc[nt][1] = __expf(sacc[nt][1] - mn0); rs0 += sacc[nt][1];
            sacc[nt][2] = __expf(sacc[nt][2] - mn1); rs1 += sacc[nt][2];
            sacc[nt][3] = __expf(sacc[nt][3] - mn1); rs1 += sacc[nt][3];
        }
        rs0 += __shfl_xor_sync(0xffffffffu, rs0, 1);
        rs0 += __shfl_xor_sync(0xffffffffu, rs0, 2);
        rs1 += __shfl_xor_sync(0xffffffffu, rs1, 1);
        rs1 += __shfl_xor_sync(0xffffffffu, rs1, 2);
        l0 = l0*c0 + rs0;
        l1 = l1*c1 + rs1;
        #pragma unroll
        for (int nh = 0; nh < 8; nh++) {
            oacc[nh][0] *= c0; oacc[nh][1] *= c0;
            oacc[nh][2] *= c1; oacc[nh][3] *= c1;
        }
        #pragma unroll
        for (int g = 0; g < 4; g++) {
            uint32_t pf[4];
            pf[0] = f22u(sacc[2*g][0],   sacc[2*g][1]);
            pf[1] = f22u(sacc[2*g][2],   sacc[2*g][3]);
            pf[2] = f22u(sacc[2*g+1][0], sacc[2*g+1][1]);
            pf[3] = f22u(sacc[2*g+1][2], sacc[2*g+1][3]);
            int kof = g*16;
            #pragma unroll
            for (int nh = 0; nh < 4; nh++) {
                uint32_t bf2[4];
                LDSM4(bf2, uv + (uint32_t)((nh*16 + b_row)*FPAD + kof + b_k)*2);
                HMMA(oacc[2*nh],   pf, bf2[0], bf2[1]);
                HMMA(oacc[2*nh+1], pf, bf2[2], bf2[3]);
            }
        }
    }
    float inv0 = 1.f / l0, inv1 = 1.f / l1;
    #pragma unroll
    for (int nh = 0; nh < 8; nh++) {
        int c = nh*8 + ctg*2;
        size_t r0 = (size_t)(b*TT + row0)*DD + h*HD + c;
        size_t r1 = (size_t)(b*TT + row0 + 8)*DD + h*HD + c;
        *(__half2*)(Oh + r0) = __floats2half2_rn(oacc[nh][0]*inv0, oacc[nh][1]*inv0);
        *(__half2*)(Oh + r1) = __floats2half2_rn(oacc[nh][2]*inv1, oacc[nh][3]*inv1);
    }
}

// ---------------- masked softmax pool (512 threads) ----------------
__global__ void __launch_bounds__(512) pool_kernel(
        const int* __restrict__ tokens, const float* __restrict__ logits,
        const float* __restrict__ X, const float* __restrict__ gate_W,
        const float* __restrict__ gate_b,
        float* __restrict__ wv_out, float* __restrict__ u_out) {
    int b = blockIdx.x >> 2, e = blockIdx.x & 3;
    int tid = threadIdx.x;
    __shared__ float ws[TT];
    __shared__ float part[4][EHD];
    int t = tid;
    int mv = (tokens[b*TT + t] != 0);
    float lgv = logits[((size_t)b*TT + t)*EH + e];
    float sf = mv ? lgv : -1e9f;
    float mx = blockReduceMax512(sf);
    float ev = mv ? expf(sf - mx) : 0.f;
    ws[t] = ev;
    float ssum = blockReduceSum512(ev);
    float nvalid = blockReduceSum512((float)mv);
    float wsc = 1.f / (ssum + 1e-6f);
    int tc = tid >> 7, d = tid & 127;
    float acc = 0.f;
    const float* xb = X + ((size_t)b*TT + tc*128)*DD + e*EHD + d;
    #pragma unroll 4
    for (int tt = 0; tt < 128; tt++)
        acc += ws[tc*128 + tt] * xb[(size_t)tt*DD];
    part[tc][d] = acc;
    __syncthreads();
    if (tc == 0) {
        float a = (part[0][d] + part[1][d] + part[2][d] + part[3][d]) * wsc;
        wv_out[b*DD + e*EHD + d] = a;
        part[0][d] = a * gate_W[d];
    }
    __syncthreads();
    if (tid < 32) {
        float g = part[0][tid] + part[0][tid+32] + part[0][tid+64] + part[0][tid+96];
        g = warpReduceSum(g);
        if (tid == 0) {
            float gl = g + gate_b[0];
            u_out[b*EH + e] = (nvalid > 0.f) ? 1.f/(1.f+expf(-gl)) : 0.f;
        }
    }
}

// ---------------- fast/slow state update ----------------
__global__ void update_kernel(const float* __restrict__ wv, const float* __restrict__ u,
                              const float* __restrict__ sal_rms,
                              const float* __restrict__ fast, const float* __restrict__ slow,
                              float* __restrict__ out_fast, float* __restrict__ out_slow) {
    int b = blockIdx.x, tid = threadIdx.x;
    float4 v = ((const float4*)(wv + b*DD))[tid];
    float ss = blockReduceSum128(v.x*v.x + v.y*v.y + v.z*v.z + v.w*v.w);
    float inv = rsqrtf(ss * (1.f/DD) + 1e-6f);
    float4 sr = ((const float4*)sal_rms)[tid];
    int e = tid >> 5;
    float uu = u[b*EH + e];
    float4 f = ((const float4*)(fast + b*DD))[tid];
    float4 s = ((const float4*)(slow + b*DD))[tid];
    float4 wn;
    wn.x = v.x*inv*sr.x; wn.y = v.y*inv*sr.y; wn.z = v.z*inv*sr.z; wn.w = v.w*inv*sr.w;
    float4 nf, ns;
    nf.x = (1.f-uu)*f.x + uu*wn.x;  nf.y = (1.f-uu)*f.y + uu*wn.y;
    nf.z = (1.f-uu)*f.z + uu*wn.z;  nf.w = (1.f-uu)*f.w + uu*wn.w;
    float ud = 0.1f*uu;
    ns.x = (1.f-ud)*s.x + ud*wn.x;  ns.y = (1.f-ud)*s.y + ud*wn.y;
    ns.z = (1.f-ud)*s.z + ud*wn.z;  ns.w = (1.f-ud)*s.w + ud*wn.w;
    ((float4*)(out_fast + b*DD))[tid] = nf;
    ((float4*)(out_slow + b*DD))[tid] = ns;
}

// ---------------- launch ----------------
extern "C" void kernel_launch(void* const* d_in, const int* in_sizes, int n_in,
                              void* d_out, int out_size) {
    const int*   tokens = (const int*)  d_in[0];
    const int*   prev   = (const int*)  d_in[1];
    const float* fast   = (const float*)d_in[2];
    const float* slow   = (const float*)d_in[3];
    const float* embed  = (const float*)d_in[4];
    const float* ctx_W  = (const float*)d_in[5];
    const float* ctx_b  = (const float*)d_in[6];
    const float* etab   = (const float*)d_in[7];
    const float* egate  = (const float*)d_in[8];
    const float* ln1    = (const float*)d_in[9];
    const float* Wq     = (const float*)d_in[10];
    const float* bq     = (const float*)d_in[11];
    const float* Wk     = (const float*)d_in[12];
    const float* bk     = (const float*)d_in[13];
    const float* Wv     = (const float*)d_in[14];
    const float* bv     = (const float*)d_in[15];
    const float* Wo     = (const float*)d_in[16];
    const float* bo     = (const float*)d_in[17];
    const float* ln2    = (const float*)d_in[18];
    const float* W1     = (const float*)d_in[19];
    const float* W2     = (const float*)d_in[20];
    const float* ln_f   = (const float*)d_in[21];
    const float* sal_W  = (const float*)d_in[22];
    const float* sal_b  = (const float*)d_in[23];
    const float* temp   = (const float*)d_in[24];
    const float* gate_W = (const float*)d_in[25];
    const float* gate_b = (const float*)d_in[26];
    const float* sal_rms= (const float*)d_in[27];
    float* out = (float*)d_out;

    float *gx, *gctx, *glog, *gwv, *gu;
    float2 *grope;
    __half *gqkv, *nx, *at, *ff;
    __half *wA, *w1, *w2;
    cudaGetSymbolAddress((void**)&gx,    g_x);
    cudaGetSymbolAddress((void**)&gqkv,  g_qkv);
    cudaGetSymbolAddress((void**)&gctx,  g_ctx);
    cudaGetSymbolAddress((void**)&glog,  g_logits);
    cudaGetSymbolAddress((void**)&gwv,   g_wv);
    cudaGetSymbolAddress((void**)&gu,    g_u);
    cudaGetSymbolAddress((void**)&grope, g_ropetab);
    cudaGetSymbolAddress((void**)&nx,    g_nx);
    cudaGetSymbolAddress((void**)&at,    g_at);
    cudaGetSymbolAddress((void**)&ff,    g_ff);
    cudaGetSymbolAddress((void**)&wA,    g_wqkvo);
    cudaGetSymbolAddress((void**)&w1,    g_w1);
    cudaGetSymbolAddress((void**)&w2,    g_w2);

    cudaFuncSetAttribute(hgemm<0>, cudaFuncAttributeMaxDynamicSharedMemorySize, HSMEM);
    cudaFuncSetAttribute(hgemm<1>, cudaFuncAttributeMaxDynamicSharedMemorySize, HSMEM);
    cudaFuncSetAttribute(hgemm<4>, cudaFuncAttributeMaxDynamicSharedMemorySize, HSMEM);
    cudaFuncSetAttribute(hgemm_ffn, cudaFuncAttributeMaxDynamicSharedMemorySize, HSMEM);
    cudaFuncSetAttribute(flash_kernel, cudaFuncAttributeMaxDynamicSharedMemorySize, FSMEM);

    dim3 tb(32, 8);
    dim3 gD(NTOK/128, DD/128);
    dim3 gQKV(NTOK/128, (3*DD)/128);
    dim3 gFF(NTOK/128, FF/64);

    // ncu captures launch #4 -> fused-QKV hgemm.
    tsplit4_kernel<<<dim3(DD/32, DD/32, 4*LL), tb>>>(Wq, Wk, Wv, Wo, wA);                // 1
    ctx_kernel<<<dim3(BB, DD/64), 512>>>(fast, slow, ctx_W, ctx_b, gctx);                // 2
    embed_fused_kernel<<<NTOK, 128>>>(tokens, prev, embed, gctx, etab, egate, ln1,
                                      gx, nx);                                           // 3

    for (int l = 0; l < LL; l++) {
        size_t wo  = (size_t)l*4*DD*DD;
        size_t w1o = (size_t)l*2*FF*DD;
        size_t w2o = (size_t)l*DD*FF;
        if (l > 0)
            rmsnorm_half_kernel<<<NTOK/4, 512>>>(gx, ln1 + l*DD, nx);
        hgemm<0><<<gQKV, 256, HSMEM>>>(nx, wA + wo,
                                       bq + l*DD, bk + l*DD, bv + l*DD,
                                       nullptr, nullptr, gqkv, NTOK, 3*DD, DD);
        if (l == 0) {
            rope_table_kernel<<<TT, 32>>>(grope);
            tsplitW1_kernel<<<dim3(FF/32, DD/32, 2*LL), tb>>>(W1, w1);
            tsplit_kernel<<<dim3(DD/32, FF/32, LL), tb>>>(W2, DD, (size_t)FF*DD, w2, (size_t)DD*FF, FF);
        }
        flash_kernel<<<dim3(TT/128, BB*HH), 256, FSMEM>>>(gqkv, grope, at);
        hgemm<1><<<gD, 256, HSMEM>>>(at, wA + wo + (size_t)1536*DD,
                                     bo + l*DD, nullptr, nullptr, gx,
                                     gx, nullptr, NTOK, DD, DD);
        rmsnorm_half_kernel<<<NTOK/4, 512>>>(gx, ln2 + l*DD, nx);
        hgemm_ffn<<<gFF, 256, HSMEM>>>(nx, w1 + w1o, w1 + w1o + (size_t)FF*DD,
                                       ff, NTOK, FF, DD);
        hgemm<4><<<gD, 256, HSMEM>>>(ff, w2 + w2o,
                                     nullptr, nullptr, nullptr, gx,
                                     gx, nullptr, NTOK, DD, FF);
    }
    rmsnorm_logits_kernel<<<NTOK, 128>>>(gx, ln_f, sal_W, sal_b, temp, out, glog);
    pool_kernel<<<BB*EH, 512>>>(tokens, glog, out, gate_W, gate_b, gwv, gu);
    update_kernel<<<BB, 128>>>(gwv, gu, sal_rms, fast, slow,
                               out + (size_t)NTOK*DD,
                               out + (size_t)NTOK*DD + BB*DD);
}